// round 7
// baseline (speedup 1.0000x reference)
#include <cuda_runtime.h>
#include <cstdint>

#define BATCH 8
#define NSEQ  4096
#define DIM   384
#define HEADS 6
#define DHEAD 64
#define INNER 384
#define ROWS  (BATCH*NSEQ)   // 32768

// ---- scratch (device globals: no allocation allowed) ----
__device__ float g_q   [ (size_t)ROWS*INNER ];
__device__ float g_k   [ (size_t)ROWS*INNER ];
__device__ float g_v   [ (size_t)ROWS*INNER ];
__device__ float g_attn[ (size_t)ROWS*INNER ];
__device__ float g_kv  [ BATCH*HEADS*DHEAD*DHEAD ];
__device__ float g_ksum[ BATCH*HEADS*DHEAD ];

__device__ __forceinline__ float elu1(float x) {
    return x > 0.f ? x + 1.f : __expf(x);
}

__device__ __forceinline__ uint32_t f2tf32(float x) {
    uint32_t u;
    asm("cvt.rna.tf32.f32 %0, %1;" : "=r"(u) : "f"(x));
    return u;
}

__device__ __forceinline__ void mma_tf32(float c[4], uint32_t a0, uint32_t a1,
                                         uint32_t a2, uint32_t a3,
                                         uint32_t b0, uint32_t b1) {
    asm volatile(
        "mma.sync.aligned.m16n8k8.row.col.f32.tf32.tf32.f32 "
        "{%0,%1,%2,%3}, {%4,%5,%6,%7}, {%8,%9}, {%0,%1,%2,%3};"
        : "+f"(c[0]), "+f"(c[1]), "+f"(c[2]), "+f"(c[3])
        : "r"(a0), "r"(a1), "r"(a2), "r"(a3), "r"(b0), "r"(b1));
}

// ============================================================================
// tf32 mma.sync GEMM (round-5 exact: convert-on-load, single buffer).
// C[M,N] = A[M,K] @ B[K,N], fp32 in/out. CTA tile 128x128, BK=32, 256 thr
// (8 warps, warp tile 64x32). M%128==0, N%128==0, K%32==0.
// EPI 0: +bias; EPI 1: elu1; EPI 2: N-split -> C (elu1) / C2 (raw).
// ============================================================================
#define APITCH 36    // (4*lr+lc)%32 distinct -> conflict-free A frags
#define BPITCH 136   // (8*lc+lr)%32 distinct -> conflict-free B frags

template<int EPI>
__global__ __launch_bounds__(256)
void mma_gemm(const float* __restrict__ A, const float* __restrict__ B,
              float* __restrict__ C, float* __restrict__ C2,
              const float* __restrict__ bias, int N, int K)
{
    __shared__ uint32_t As[128 * APITCH];   // [m][k], tf32 bits
    __shared__ uint32_t Bs[32  * BPITCH];   // [k][n], tf32 bits

    const int tid  = threadIdx.x;
    const int wid  = tid >> 5;
    const int lane = tid & 31;
    const int wm   = (wid & 1) * 64;
    const int wn   = (wid >> 1) * 32;
    const int row0 = blockIdx.y * 128;
    const int col0 = blockIdx.x * 128;
    const int lr = lane >> 2;
    const int lc = lane & 3;

    float acc[4][4][4];
    #pragma unroll
    for (int i = 0; i < 4; i++)
        #pragma unroll
        for (int j = 0; j < 4; j++)
            #pragma unroll
            for (int r = 0; r < 4; r++) acc[i][j][r] = 0.f;

    for (int k0 = 0; k0 < K; k0 += 32) {
        #pragma unroll
        for (int j = 0; j < 4; j++) {
            int idx = tid + 256 * j;
            int r = idx >> 3, c4 = (idx & 7) * 4;
            float4 v = *reinterpret_cast<const float4*>(
                &A[(size_t)(row0 + r) * K + k0 + c4]);
            uint32_t* dst = &As[r * APITCH + c4];
            dst[0] = f2tf32(v.x); dst[1] = f2tf32(v.y);
            dst[2] = f2tf32(v.z); dst[3] = f2tf32(v.w);
        }
        #pragma unroll
        for (int j = 0; j < 4; j++) {
            int idx = tid + 256 * j;
            int r = idx >> 5, c4 = (idx & 31) * 4;
            float4 v = *reinterpret_cast<const float4*>(
                &B[(size_t)(k0 + r) * N + col0 + c4]);
            uint32_t* dst = &Bs[r * BPITCH + c4];
            dst[0] = f2tf32(v.x); dst[1] = f2tf32(v.y);
            dst[2] = f2tf32(v.z); dst[3] = f2tf32(v.w);
        }
        __syncthreads();

        #pragma unroll
        for (int s = 0; s < 4; s++) {
            const int kk = s * 8;
            uint32_t af[4][4];
            #pragma unroll
            for (int mt = 0; mt < 4; mt++) {
                const uint32_t* ap = &As[(wm + mt * 16 + lr) * APITCH + kk + lc];
                af[mt][0] = ap[0];
                af[mt][1] = ap[8 * APITCH];
                af[mt][2] = ap[4];
                af[mt][3] = ap[8 * APITCH + 4];
            }
            uint32_t bf[4][2];
            #pragma unroll
            for (int nt = 0; nt < 4; nt++) {
                const uint32_t* bp = &Bs[(kk + lc) * BPITCH + wn + nt * 8 + lr];
                bf[nt][0] = bp[0];
                bf[nt][1] = bp[4 * BPITCH];
            }
            #pragma unroll
            for (int mt = 0; mt < 4; mt++)
                #pragma unroll
                for (int nt = 0; nt < 4; nt++)
                    mma_tf32(acc[mt][nt], af[mt][0], af[mt][1], af[mt][2],
                             af[mt][3], bf[nt][0], bf[nt][1]);
        }
        __syncthreads();
    }

    // ---- epilogue ----
    const int half = N >> 1;
    #pragma unroll
    for (int mt = 0; mt < 4; mt++) {
        #pragma unroll
        for (int nt = 0; nt < 4; nt++) {
            const int col = col0 + wn + nt * 8 + lc * 2;
            #pragma unroll
            for (int hh = 0; hh < 2; hh++) {
                const int row = row0 + wm + mt * 16 + lr + hh * 8;
                float v0 = acc[mt][nt][hh * 2 + 0];
                float v1 = acc[mt][nt][hh * 2 + 1];
                float2 o;
                if (EPI == 0) {
                    o.x = v0 + bias[col]; o.y = v1 + bias[col + 1];
                    *reinterpret_cast<float2*>(&C[(size_t)row * N + col]) = o;
                } else if (EPI == 1) {
                    o.x = elu1(v0); o.y = elu1(v1);
                    *reinterpret_cast<float2*>(&C[(size_t)row * N + col]) = o;
                } else {
                    if (col < half) {
                        o.x = elu1(v0); o.y = elu1(v1);
                        *reinterpret_cast<float2*>(&C[(size_t)row * half + col]) = o;
                    } else {
                        o.x = v0; o.y = v1;
                        *reinterpret_cast<float2*>(&C2[(size_t)row * half + (col - half)]) = o;
                    }
                }
            }
        }
    }
}

// ---------------------------------------------------------------------------
// Zero kv / ksum accumulators
// ---------------------------------------------------------------------------
__global__ void zero_kernel()
{
    int i = blockIdx.x * 256 + threadIdx.x;
    if (i < BATCH*HEADS*DHEAD*DHEAD) g_kv[i] = 0.f;
    if (i < BATCH*HEADS*DHEAD)       g_ksum[i] = 0.f;
}

// ---------------------------------------------------------------------------
// kv via tf32 mma:  kv[d][m] = sum_n k[n][d] * v[n][m];  ksum[d] = sum_n k[n][d]
// CHUNK 256 -> grid (48, 16) = 768 CTAs (~5.2/SM) to fix parallelism starvation
// (round-5 profile: occ 31%, issue 22% at 384 CTAs).
// ---------------------------------------------------------------------------
#define CHUNK 256
#define KTP 36
#define VSP 72
__global__ __launch_bounds__(256)
void kv_mma_kernel()
{
    __shared__ uint32_t Kt[64 * KTP];   // [d][n] tf32
    __shared__ uint32_t Vs[32 * VSP];   // [n][m] tf32
    __shared__ float red[16][64];

    const int bh = blockIdx.x;
    const int b = bh / HEADS, h = bh % HEADS;
    const int n0 = blockIdx.y * CHUNK;

    const int tid  = threadIdx.x;
    const int wid  = tid >> 5;
    const int lane = tid & 31;
    const int wm   = (wid & 1) * 32;    // d offset
    const int wn   = (wid >> 1) * 16;   // m offset
    const int lr = lane >> 2;
    const int lc = lane & 3;

    const float* kbase = g_k + ((size_t)(b * NSEQ + n0)) * INNER + h * DHEAD;
    const float* vbase = g_v + ((size_t)(b * NSEQ + n0)) * INNER + h * DHEAD;

    float acc[2][2][4];
    #pragma unroll
    for (int i = 0; i < 2; i++)
        #pragma unroll
        for (int j = 0; j < 2; j++)
            #pragma unroll
            for (int r = 0; r < 4; r++) acc[i][j][r] = 0.f;
    float sk[4] = {0.f, 0.f, 0.f, 0.f};

    for (int sub = 0; sub < CHUNK / 32; sub++) {
        const int nn = sub * 32;
        #pragma unroll
        for (int it = 0; it < 2; it++) {
            int idx = tid + it * 256;
            int n = idx >> 4, c4 = (idx & 15) * 4;
            float4 kw = *reinterpret_cast<const float4*>(
                &kbase[(size_t)(nn + n) * INNER + c4]);
            Kt[(c4 + 0) * KTP + n] = f2tf32(kw.x);
            Kt[(c4 + 1) * KTP + n] = f2tf32(kw.y);
            Kt[(c4 + 2) * KTP + n] = f2tf32(kw.z);
            Kt[(c4 + 3) * KTP + n] = f2tf32(kw.w);
            sk[0] += kw.x; sk[1] += kw.y; sk[2] += kw.z; sk[3] += kw.w;
            float4 vw = *reinterpret_cast<const float4*>(
                &vbase[(size_t)(nn + n) * INNER + c4]);
            uint4 o;
            o.x = f2tf32(vw.x); o.y = f2tf32(vw.y);
            o.z = f2tf32(vw.z); o.w = f2tf32(vw.w);
            *reinterpret_cast<uint4*>(&Vs[n * VSP + c4]) = o;
        }
        __syncthreads();

        #pragma unroll
        for (int s = 0; s < 4; s++) {
            const int kk = s * 8;
            uint32_t af[2][4];
            #pragma unroll
            for (int mt = 0; mt < 2; mt++) {
                const uint32_t* ap = &Kt[(wm + mt * 16 + lr) * KTP + kk + lc];
                af[mt][0] = ap[0];
                af[mt][1] = ap[8 * KTP];
                af[mt][2] = ap[4];
                af[mt][3] = ap[8 * KTP + 4];
            }
            uint32_t bf[2][2];
            #pragma unroll
            for (int nt = 0; nt < 2; nt++) {
                const uint32_t* bp = &Vs[(kk + lc) * VSP + wn + nt * 8 + lr];
                bf[nt][0] = bp[0];
                bf[nt][1] = bp[4 * VSP];
            }
            #pragma unroll
            for (int mt = 0; mt < 2; mt++)
                #pragma unroll
                for (int nt = 0; nt < 2; nt++)
                    mma_tf32(acc[mt][nt], af[mt][0], af[mt][1], af[mt][2],
                             af[mt][3], bf[nt][0], bf[nt][1]);
        }
        __syncthreads();
    }

    // ---- ksum reduction ----
    {
        const int c4 = (tid & 15) * 4;
        const int grp = tid >> 4;
        #pragma unroll
        for (int j = 0; j < 4; j++) red[grp][c4 + j] = sk[j];
        __syncthreads();
        if (tid < 64) {
            float s = 0.f;
            #pragma unroll
            for (int r = 0; r < 16; r++) s += red[r][tid];
            atomicAdd(&g_ksum[bh * DHEAD + tid], s);
        }
    }

    // ---- kv accumulation ----
    float* kvp = g_kv + (size_t)bh * DHEAD * DHEAD;
    #pragma unroll
    for (int mt = 0; mt < 2; mt++) {
        #pragma unroll
        for (int nt = 0; nt < 2; nt++) {
            const int col = wn + nt * 8 + lc * 2;
            #pragma unroll
            for (int hh = 0; hh < 2; hh++) {
                const int row = wm + mt * 16 + lr + hh * 8;
                atomicAdd(&kvp[row * DHEAD + col],     acc[mt][nt][hh * 2 + 0]);
                atomicAdd(&kvp[row * DHEAD + col + 1], acc[mt][nt][hh * 2 + 1]);
            }
        }
    }
}

// ---------------------------------------------------------------------------
// attn via tf32 mma: attn[n,m] = (q[n,:] @ kv[:,m]) * 1/(q[n,:].ksum + 1e-6)
// ---------------------------------------------------------------------------
#define AQP 68
#define A_QS  0
#define A_KVS 34816
#define A_KS  52224
#define A_ZR  52480
#define A_SMEM 52992

__global__ __launch_bounds__(256)
void attn_mma_kernel()
{
    extern __shared__ char smem[];
    uint32_t* qs  = reinterpret_cast<uint32_t*>(smem + A_QS);
    uint32_t* kvs = reinterpret_cast<uint32_t*>(smem + A_KVS);
    float*    ks  = reinterpret_cast<float*>(smem + A_KS);
    float*    zr  = reinterpret_cast<float*>(smem + A_ZR);

    const int bh = blockIdx.x;
    const int b = bh / HEADS, h = bh % HEADS;
    const int n0 = blockIdx.y * 128;

    const int tid  = threadIdx.x;
    const int wid  = tid >> 5;
    const int lane = tid & 31;
    const int wm   = (wid & 3) * 32;
    const int wn   = (wid >> 2) * 32;
    const int lr = lane >> 2;
    const int lc = lane & 3;

    const float* qptr = g_q + ((size_t)(b * NSEQ + n0)) * INNER + h * DHEAD;
    #pragma unroll
    for (int j = 0; j < 8; j++) {
        int idx = tid + 256 * j;
        int r = idx >> 4, c4 = (idx & 15) * 4;
        float4 v = *reinterpret_cast<const float4*>(&qptr[(size_t)r * INNER + c4]);
        uint32_t* d = &qs[r * AQP + c4];
        d[0] = f2tf32(v.x); d[1] = f2tf32(v.y);
        d[2] = f2tf32(v.z); d[3] = f2tf32(v.w);
    }
    #pragma unroll
    for (int j = 0; j < 4; j++) {
        int idx = tid + 256 * j;
        int d = idx >> 4, m4 = (idx & 15) * 4;
        float4 v = *reinterpret_cast<const float4*>(&g_kv[(size_t)bh * 4096 + d * 64 + m4]);
        kvs[(m4 + 0) * AQP + d] = f2tf32(v.x);
        kvs[(m4 + 1) * AQP + d] = f2tf32(v.y);
        kvs[(m4 + 2) * AQP + d] = f2tf32(v.z);
        kvs[(m4 + 3) * AQP + d] = f2tf32(v.w);
    }
    if (tid < 64) ks[tid] = g_ksum[bh * 64 + tid];
    __syncthreads();

    if (tid < 128) {
        float s = 0.f;
        #pragma unroll
        for (int dd = 0; dd < 64; dd++)
            s += __uint_as_float(qs[tid * AQP + dd]) * ks[dd];
        zr[tid] = 1.f / (s + 1e-6f);
    }
    __syncthreads();

    float acc[2][4][4];
    #pragma unroll
    for (int i = 0; i < 2; i++)
        #pragma unroll
        for (int j = 0; j < 4; j++)
            #pragma unroll
            for (int r = 0; r < 4; r++) acc[i][j][r] = 0.f;

    #pragma unroll
    for (int s = 0; s < 8; s++) {
        const int kk = s * 8;
        uint32_t af[2][4];
        #pragma unroll
        for (int mt = 0; mt < 2; mt++) {
            const uint32_t* ap = &qs[(wm + mt * 16 + lr) * AQP + kk + lc];
            af[mt][0] = ap[0];
            af[mt][1] = ap[8 * AQP];
            af[mt][2] = ap[4];
            af[mt][3] = ap[8 * AQP + 4];
        }
        uint32_t bf[4][2];
        #pragma unroll
        for (int nt = 0; nt < 4; nt++) {
            const uint32_t* bp = &kvs[(wn + nt * 8 + lr) * AQP + kk + lc];
            bf[nt][0] = bp[0];
            bf[nt][1] = bp[4];
        }
        #pragma unroll
        for (int mt = 0; mt < 2; mt++)
            #pragma unroll
            for (int nt = 0; nt < 4; nt++)
                mma_tf32(acc[mt][nt], af[mt][0], af[mt][1], af[mt][2],
                         af[mt][3], bf[nt][0], bf[nt][1]);
    }

    #pragma unroll
    for (int mt = 0; mt < 2; mt++) {
        #pragma unroll
        for (int nt = 0; nt < 4; nt++) {
            const int col = wn + nt * 8 + lc * 2;
            #pragma unroll
            for (int hh = 0; hh < 2; hh++) {
                const int row = wm + mt * 16 + lr + hh * 8;
                const float z = zr[row];
                float2 o;
                o.x = acc[mt][nt][hh * 2 + 0] * z;
                o.y = acc[mt][nt][hh * 2 + 1] * z;
                *reinterpret_cast<float2*>(
                    &g_attn[((size_t)(b * NSEQ + n0 + row)) * INNER + h * DHEAD + col]) = o;
            }
        }
    }
}

// ---------------------------------------------------------------------------
// Launch order: G2, Z, KV, G1, AT, G5 (dependency-legal; puts mma_gemm<1>
// in the ncu-profiled launch slot so the GEMM finally gets profiled).
// ---------------------------------------------------------------------------
extern "C" void kernel_launch(void* const* d_in, const int* in_sizes, int n_in,
                              void* d_out, int out_size)
{
    const float* x_q  = (const float*)d_in[0];
    const float* x_kv = (const float*)d_in[1];
    const float* Wq   = (const float*)d_in[2];
    const float* Wkv  = (const float*)d_in[3];
    const float* Wout = (const float*)d_in[4];
    const float* bout = (const float*)d_in[5];
    float* out = (float*)d_out;

    float *qp, *kp, *vp, *ap;
    cudaGetSymbolAddress((void**)&qp, g_q);
    cudaGetSymbolAddress((void**)&kp, g_k);
    cudaGetSymbolAddress((void**)&vp, g_v);
    cudaGetSymbolAddress((void**)&ap, g_attn);

    cudaFuncSetAttribute(attn_mma_kernel, cudaFuncAttributeMaxDynamicSharedMemorySize, A_SMEM);

    dim3 blk(256);

    // 1) kv_proj = x_kv @ Wkv -> k (elu1) / v (raw)
    mma_gemm<2><<<dim3(2*INNER/128, ROWS/128), blk>>>(
        x_kv, Wkv, kp, vp, nullptr, 2*INNER, DIM);

    // 2) zero kv/ksum accumulators
    zero_kernel<<<(BATCH*HEADS*DHEAD*DHEAD + 255)/256, blk>>>();

    // 3) kv = k^T v per (b,h); ksum = sum_n k   (tensor-core + atomics)
    kv_mma_kernel<<<dim3(BATCH*HEADS, NSEQ/CHUNK), blk>>>();

    // 4) q = elu1(x_q @ Wq)
    mma_gemm<1><<<dim3(INNER/128, ROWS/128), blk>>>(
        x_q, Wq, qp, nullptr, nullptr, INNER, DIM);

    // 5) attn = (q @ kv) * z   (tensor-core)
    attn_mma_kernel<<<dim3(BATCH*HEADS, NSEQ/128), blk, A_SMEM>>>();

    // 6) out = attn @ Wout + bout
    mma_gemm<0><<<dim3(INNER/128, ROWS/128), blk>>>(
        ap, Wout, out, nullptr, bout, INNER, DIM);
}

// round 8
// speedup vs baseline: 1.4467x; 1.4467x over previous
#include <cuda_runtime.h>
#include <cstdint>

#define BATCH 8
#define NSEQ  4096
#define DIM   384
#define HEADS 6
#define DHEAD 64
#define INNER 384
#define ROWS  (BATCH*NSEQ)   // 32768

// ---- scratch (device globals: no allocation allowed) ----
__device__ float g_xq  [ (size_t)ROWS*DIM ];     // tf32-rounded x_q
__device__ float g_xkv [ (size_t)ROWS*DIM ];     // tf32-rounded x_kv
__device__ float g_wq  [ DIM*INNER ];
__device__ float g_wkv [ DIM*2*INNER ];
__device__ float g_wout[ INNER*DIM ];
__device__ float g_q   [ (size_t)ROWS*INNER ];
__device__ float g_k   [ (size_t)ROWS*INNER ];
__device__ float g_v   [ (size_t)ROWS*INNER ];
__device__ float g_attn[ (size_t)ROWS*INNER ];
__device__ float g_kv  [ BATCH*HEADS*DHEAD*DHEAD ];
__device__ float g_ksum[ BATCH*HEADS*DHEAD ];

__device__ __forceinline__ float elu1(float x) {
    return x > 0.f ? x + 1.f : __expf(x);
}

__device__ __forceinline__ uint32_t f2tf32(float x) {
    uint32_t u;
    asm("cvt.rna.tf32.f32 %0, %1;" : "=r"(u) : "f"(x));
    return u;
}
__device__ __forceinline__ float round_tf32(float x) {
    return __uint_as_float(f2tf32(x));
}

__device__ __forceinline__ uint32_t smem_u32(const void* p) {
    uint32_t a;
    asm("{ .reg .u64 t; cvta.to.shared.u64 t, %1; cvt.u32.u64 %0, t; }"
        : "=r"(a) : "l"(p));
    return a;
}
__device__ __forceinline__ void cp16(uint32_t dst, const void* src) {
    asm volatile("cp.async.cg.shared.global [%0], [%1], 16;"
                 :: "r"(dst), "l"(src));
}
#define CP_COMMIT() asm volatile("cp.async.commit_group;")

__device__ __forceinline__ void mma_tf32(float c[4], uint32_t a0, uint32_t a1,
                                         uint32_t a2, uint32_t a3,
                                         uint32_t b0, uint32_t b1) {
    asm volatile(
        "mma.sync.aligned.m16n8k8.row.col.f32.tf32.tf32.f32 "
        "{%0,%1,%2,%3}, {%4,%5,%6,%7}, {%8,%9}, {%0,%1,%2,%3};"
        : "+f"(c[0]), "+f"(c[1]), "+f"(c[2]), "+f"(c[3])
        : "r"(a0), "r"(a1), "r"(a2), "r"(a3), "r"(b0), "r"(b1));
}

// ---------------------------------------------------------------------------
// cvt kernels: round fp32 -> tf32 bit patterns (rna), stored as float.
// ---------------------------------------------------------------------------
__global__ void cvt_x_kernel(const float* __restrict__ src, float* __restrict__ dst)
{
    const int n4 = ROWS * DIM / 4;
    for (int i = blockIdx.x * blockDim.x + threadIdx.x; i < n4;
         i += gridDim.x * blockDim.x) {
        float4 v = reinterpret_cast<const float4*>(src)[i];
        v.x = round_tf32(v.x); v.y = round_tf32(v.y);
        v.z = round_tf32(v.z); v.w = round_tf32(v.w);
        reinterpret_cast<float4*>(dst)[i] = v;
    }
}

__global__ void cvt_w_kernel(const float* __restrict__ wq,
                             const float* __restrict__ wkv,
                             const float* __restrict__ wout)
{
    const int n1 = DIM*INNER/4, n2 = DIM*2*INNER/4, n3 = INNER*DIM/4;
    for (int i = blockIdx.x * blockDim.x + threadIdx.x; i < n1 + n2 + n3;
         i += gridDim.x * blockDim.x) {
        const float4* s; float4* d; int j;
        if (i < n1)           { s = (const float4*)wq;   d = (float4*)g_wq;   j = i; }
        else if (i < n1 + n2) { s = (const float4*)wkv;  d = (float4*)g_wkv;  j = i - n1; }
        else                  { s = (const float4*)wout; d = (float4*)g_wout; j = i - n1 - n2; }
        float4 v = s[j];
        v.x = round_tf32(v.x); v.y = round_tf32(v.y);
        v.z = round_tf32(v.z); v.w = round_tf32(v.w);
        d[j] = v;
    }
}

// ============================================================================
// tf32 mma.sync GEMM, cp.async 2-stage pipeline, inputs PRE-ROUNDED to tf32.
// C[M,N] = A[M,K] @ B[K,N]. CTA tile 128x128, BK=32, 256 thr (8 warps,
// warp tile 64x32). M%128==0, N%128==0, K%32==0.
// EPI 0: +bias (full fp32 out); EPI 1: elu1, tf32-rounded out;
// EPI 2: N-split at N/2 -> C (elu1, rounded) / C2 (raw, rounded).
// smem: 2 stages x (As 128x36 + Bs 32x136) words = 71680 B dynamic.
// ============================================================================
#define APITCH 36
#define BPITCH 136
#define ST_AW (128*APITCH)
#define ST_BW (32*BPITCH)
#define G_SMEM_BYTES (2*(ST_AW + ST_BW)*4)

template<int EPI>
__global__ __launch_bounds__(256, 2)
void mma_gemm(const float* __restrict__ A, const float* __restrict__ B,
              float* __restrict__ C, float* __restrict__ C2,
              const float* __restrict__ bias, int N, int K)
{
    extern __shared__ uint32_t dsm[];
    uint32_t* As = dsm;                 // 2 stages
    uint32_t* Bs = dsm + 2 * ST_AW;
    const uint32_t sbA = smem_u32(As);
    const uint32_t sbB = smem_u32(Bs);

    const int tid  = threadIdx.x;
    const int wid  = tid >> 5;
    const int lane = tid & 31;
    const int wm   = (wid & 1) * 64;
    const int wn   = (wid >> 1) * 32;
    const int row0 = blockIdx.y * 128;
    const int col0 = blockIdx.x * 128;
    const int lr = lane >> 2;
    const int lc = lane & 3;

    float acc[4][4][4];
    #pragma unroll
    for (int i = 0; i < 4; i++)
        #pragma unroll
        for (int j = 0; j < 4; j++)
            #pragma unroll
            for (int r = 0; r < 4; r++) acc[i][j][r] = 0.f;

    auto issue = [&](int kt, int stage) {
        const int k0 = kt * 32;
        const uint32_t aB = sbA + (uint32_t)stage * ST_AW * 4;
        const uint32_t bB = sbB + (uint32_t)stage * ST_BW * 4;
        #pragma unroll
        for (int j = 0; j < 4; j++) {
            int idx = tid + 256 * j;
            int r = idx >> 3, c4 = (idx & 7) * 4;
            cp16(aB + (uint32_t)(r * APITCH + c4) * 4,
                 &A[(size_t)(row0 + r) * K + k0 + c4]);
        }
        #pragma unroll
        for (int j = 0; j < 4; j++) {
            int idx = tid + 256 * j;
            int r = idx >> 5, c4 = (idx & 31) * 4;
            cp16(bB + (uint32_t)(r * BPITCH + c4) * 4,
                 &B[(size_t)(k0 + r) * N + col0 + c4]);
        }
        CP_COMMIT();
    };

    const int ntiles = K / 32;
    issue(0, 0);

    for (int kt = 0; kt < ntiles; kt++) {
        if (kt + 1 < ntiles) {
            issue(kt + 1, (kt + 1) & 1);
            asm volatile("cp.async.wait_group 1;");
        } else {
            asm volatile("cp.async.wait_group 0;");
        }
        __syncthreads();

        const uint32_t* Asn = As + (kt & 1) * ST_AW;
        const uint32_t* Bsn = Bs + (kt & 1) * ST_BW;

        #pragma unroll
        for (int s = 0; s < 4; s++) {
            const int kk = s * 8;
            uint32_t af[4][4];
            #pragma unroll
            for (int mt = 0; mt < 4; mt++) {
                const uint32_t* ap = &Asn[(wm + mt * 16 + lr) * APITCH + kk + lc];
                af[mt][0] = ap[0];
                af[mt][1] = ap[8 * APITCH];
                af[mt][2] = ap[4];
                af[mt][3] = ap[8 * APITCH + 4];
            }
            uint32_t bf[4][2];
            #pragma unroll
            for (int nt = 0; nt < 4; nt++) {
                const uint32_t* bp = &Bsn[(kk + lc) * BPITCH + wn + nt * 8 + lr];
                bf[nt][0] = bp[0];
                bf[nt][1] = bp[4 * BPITCH];
            }
            #pragma unroll
            for (int mt = 0; mt < 4; mt++)
                #pragma unroll
                for (int nt = 0; nt < 4; nt++)
                    mma_tf32(acc[mt][nt], af[mt][0], af[mt][1], af[mt][2],
                             af[mt][3], bf[nt][0], bf[nt][1]);
        }
        __syncthreads();
    }

    // ---- epilogue ----
    const int half = N >> 1;
    #pragma unroll
    for (int mt = 0; mt < 4; mt++) {
        #pragma unroll
        for (int nt = 0; nt < 4; nt++) {
            const int col = col0 + wn + nt * 8 + lc * 2;
            #pragma unroll
            for (int hh = 0; hh < 2; hh++) {
                const int row = row0 + wm + mt * 16 + lr + hh * 8;
                float v0 = acc[mt][nt][hh * 2 + 0];
                float v1 = acc[mt][nt][hh * 2 + 1];
                float2 o;
                if (EPI == 0) {
                    o.x = v0 + bias[col]; o.y = v1 + bias[col + 1];
                    *reinterpret_cast<float2*>(&C[(size_t)row * N + col]) = o;
                } else if (EPI == 1) {
                    o.x = round_tf32(elu1(v0)); o.y = round_tf32(elu1(v1));
                    *reinterpret_cast<float2*>(&C[(size_t)row * N + col]) = o;
                } else {
                    if (col < half) {
                        o.x = round_tf32(elu1(v0)); o.y = round_tf32(elu1(v1));
                        *reinterpret_cast<float2*>(&C[(size_t)row * half + col]) = o;
                    } else {
                        o.x = round_tf32(v0); o.y = round_tf32(v1);
                        *reinterpret_cast<float2*>(&C2[(size_t)row * half + (col - half)]) = o;
                    }
                }
            }
        }
    }
}

// ---------------------------------------------------------------------------
// Zero kv / ksum accumulators
// ---------------------------------------------------------------------------
__global__ void zero_kernel()
{
    int i = blockIdx.x * 256 + threadIdx.x;
    if (i < BATCH*HEADS*DHEAD*DHEAD) g_kv[i] = 0.f;
    if (i < BATCH*HEADS*DHEAD)       g_ksum[i] = 0.f;
}

// ---------------------------------------------------------------------------
// kv via tf32 mma:  kv[d][m] = sum_n k[n][d] * v[n][m];  ksum[d] = sum_n k[n][d]
// k, v arrive pre-rounded tf32 -> no cvt here.
// ---------------------------------------------------------------------------
#define CHUNK 256
#define KTP 36
#define VSP 72
__global__ __launch_bounds__(256)
void kv_mma_kernel()
{
    __shared__ uint32_t Kt[64 * KTP];   // [d][n] tf32
    __shared__ uint32_t Vs[32 * VSP];   // [n][m] tf32
    __shared__ float red[16][64];

    const int bh = blockIdx.x;
    const int b = bh / HEADS, h = bh % HEADS;
    const int n0 = blockIdx.y * CHUNK;

    const int tid  = threadIdx.x;
    const int wid  = tid >> 5;
    const int lane = tid & 31;
    const int wm   = (wid & 1) * 32;
    const int wn   = (wid >> 1) * 16;
    const int lr = lane >> 2;
    const int lc = lane & 3;

    const float* kbase = g_k + ((size_t)(b * NSEQ + n0)) * INNER + h * DHEAD;
    const float* vbase = g_v + ((size_t)(b * NSEQ + n0)) * INNER + h * DHEAD;

    float acc[2][2][4];
    #pragma unroll
    for (int i = 0; i < 2; i++)
        #pragma unroll
        for (int j = 0; j < 2; j++)
            #pragma unroll
            for (int r = 0; r < 4; r++) acc[i][j][r] = 0.f;
    float sk[4] = {0.f, 0.f, 0.f, 0.f};

    for (int sub = 0; sub < CHUNK / 32; sub++) {
        const int nn = sub * 32;
        #pragma unroll
        for (int it = 0; it < 2; it++) {
            int idx = tid + it * 256;
            int n = idx >> 4, c4 = (idx & 15) * 4;
            float4 kw = *reinterpret_cast<const float4*>(
                &kbase[(size_t)(nn + n) * INNER + c4]);
            Kt[(c4 + 0) * KTP + n] = __float_as_uint(kw.x);
            Kt[(c4 + 1) * KTP + n] = __float_as_uint(kw.y);
            Kt[(c4 + 2) * KTP + n] = __float_as_uint(kw.z);
            Kt[(c4 + 3) * KTP + n] = __float_as_uint(kw.w);
            sk[0] += kw.x; sk[1] += kw.y; sk[2] += kw.z; sk[3] += kw.w;
            float4 vw = *reinterpret_cast<const float4*>(
                &vbase[(size_t)(nn + n) * INNER + c4]);
            uint4 o;
            o.x = __float_as_uint(vw.x); o.y = __float_as_uint(vw.y);
            o.z = __float_as_uint(vw.z); o.w = __float_as_uint(vw.w);
            *reinterpret_cast<uint4*>(&Vs[n * VSP + c4]) = o;
        }
        __syncthreads();

        #pragma unroll
        for (int s = 0; s < 4; s++) {
            const int kk = s * 8;
            uint32_t af[2][4];
            #pragma unroll
            for (int mt = 0; mt < 2; mt++) {
                const uint32_t* ap = &Kt[(wm + mt * 16 + lr) * KTP + kk + lc];
                af[mt][0] = ap[0];
                af[mt][1] = ap[8 * KTP];
                af[mt][2] = ap[4];
                af[mt][3] = ap[8 * KTP + 4];
            }
            uint32_t bf[2][2];
            #pragma unroll
            for (int nt = 0; nt < 2; nt++) {
                const uint32_t* bp = &Vs[(kk + lc) * VSP + wn + nt * 8 + lr];
                bf[nt][0] = bp[0];
                bf[nt][1] = bp[4 * VSP];
            }
            #pragma unroll
            for (int mt = 0; mt < 2; mt++)
                #pragma unroll
                for (int nt = 0; nt < 2; nt++)
                    mma_tf32(acc[mt][nt], af[mt][0], af[mt][1], af[mt][2],
                             af[mt][3], bf[nt][0], bf[nt][1]);
        }
        __syncthreads();
    }

    // ---- ksum reduction ----
    {
        const int c4 = (tid & 15) * 4;
        const int grp = tid >> 4;
        #pragma unroll
        for (int j = 0; j < 4; j++) red[grp][c4 + j] = sk[j];
        __syncthreads();
        if (tid < 64) {
            float s = 0.f;
            #pragma unroll
            for (int r = 0; r < 16; r++) s += red[r][tid];
            atomicAdd(&g_ksum[bh * DHEAD + tid], s);
        }
    }

    // ---- kv accumulation ----
    float* kvp = g_kv + (size_t)bh * DHEAD * DHEAD;
    #pragma unroll
    for (int mt = 0; mt < 2; mt++) {
        #pragma unroll
        for (int nt = 0; nt < 2; nt++) {
            const int col = wn + nt * 8 + lc * 2;
            #pragma unroll
            for (int hh = 0; hh < 2; hh++) {
                const int row = wm + mt * 16 + lr + hh * 8;
                atomicAdd(&kvp[row * DHEAD + col],     acc[mt][nt][hh * 2 + 0]);
                atomicAdd(&kvp[row * DHEAD + col + 1], acc[mt][nt][hh * 2 + 1]);
            }
        }
    }
}

// ---------------------------------------------------------------------------
// attn via tf32 mma: attn[n,m] = (q[n,:] @ kv[:,m]) * 1/(q[n,:].ksum + 1e-6)
// q arrives pre-rounded; kv (fp32 atomics) still converted here.
// Output stored tf32-rounded (feeds GEMM 5).
// ---------------------------------------------------------------------------
#define AQP 68
#define A_QS  0
#define A_KVS 34816
#define A_KS  52224
#define A_ZR  52480
#define A_SMEM 52992

__global__ __launch_bounds__(256)
void attn_mma_kernel()
{
    extern __shared__ char smem[];
    uint32_t* qs  = reinterpret_cast<uint32_t*>(smem + A_QS);
    uint32_t* kvs = reinterpret_cast<uint32_t*>(smem + A_KVS);
    float*    ks  = reinterpret_cast<float*>(smem + A_KS);
    float*    zr  = reinterpret_cast<float*>(smem + A_ZR);

    const int bh = blockIdx.x;
    const int b = bh / HEADS, h = bh % HEADS;
    const int n0 = blockIdx.y * 128;

    const int tid  = threadIdx.x;
    const int wid  = tid >> 5;
    const int lane = tid & 31;
    const int wm   = (wid & 3) * 32;
    const int wn   = (wid >> 2) * 32;
    const int lr = lane >> 2;
    const int lc = lane & 3;

    const float* qptr = g_q + ((size_t)(b * NSEQ + n0)) * INNER + h * DHEAD;
    #pragma unroll
    for (int j = 0; j < 8; j++) {
        int idx = tid + 256 * j;
        int r = idx >> 4, c4 = (idx & 15) * 4;
        float4 v = *reinterpret_cast<const float4*>(&qptr[(size_t)r * INNER + c4]);
        uint32_t* d = &qs[r * AQP + c4];
        d[0] = __float_as_uint(v.x); d[1] = __float_as_uint(v.y);
        d[2] = __float_as_uint(v.z); d[3] = __float_as_uint(v.w);
    }
    #pragma unroll
    for (int j = 0; j < 4; j++) {
        int idx = tid + 256 * j;
        int d = idx >> 4, m4 = (idx & 15) * 4;
        float4 v = *reinterpret_cast<const float4*>(&g_kv[(size_t)bh * 4096 + d * 64 + m4]);
        kvs[(m4 + 0) * AQP + d] = f2tf32(v.x);
        kvs[(m4 + 1) * AQP + d] = f2tf32(v.y);
        kvs[(m4 + 2) * AQP + d] = f2tf32(v.z);
        kvs[(m4 + 3) * AQP + d] = f2tf32(v.w);
    }
    if (tid < 64) ks[tid] = g_ksum[bh * 64 + tid];
    __syncthreads();

    if (tid < 128) {
        float s = 0.f;
        #pragma unroll
        for (int dd = 0; dd < 64; dd++)
            s += __uint_as_float(qs[tid * AQP + dd]) * ks[dd];
        zr[tid] = 1.f / (s + 1e-6f);
    }
    __syncthreads();

    float acc[2][4][4];
    #pragma unroll
    for (int i = 0; i < 2; i++)
        #pragma unroll
        for (int j = 0; j < 4; j++)
            #pragma unroll
            for (int r = 0; r < 4; r++) acc[i][j][r] = 0.f;

    #pragma unroll
    for (int s = 0; s < 8; s++) {
        const int kk = s * 8;
        uint32_t af[2][4];
        #pragma unroll
        for (int mt = 0; mt < 2; mt++) {
            const uint32_t* ap = &qs[(wm + mt * 16 + lr) * AQP + kk + lc];
            af[mt][0] = ap[0];
            af[mt][1] = ap[8 * AQP];
            af[mt][2] = ap[4];
            af[mt][3] = ap[8 * AQP + 4];
        }
        uint32_t bf[4][2];
        #pragma unroll
        for (int nt = 0; nt < 4; nt++) {
            const uint32_t* bp = &kvs[(wn + nt * 8 + lr) * AQP + kk + lc];
            bf[nt][0] = bp[0];
            bf[nt][1] = bp[4];
        }
        #pragma unroll
        for (int mt = 0; mt < 2; mt++)
            #pragma unroll
            for (int nt = 0; nt < 4; nt++)
                mma_tf32(acc[mt][nt], af[mt][0], af[mt][1], af[mt][2],
                         af[mt][3], bf[nt][0], bf[nt][1]);
    }

    #pragma unroll
    for (int mt = 0; mt < 2; mt++) {
        #pragma unroll
        for (int nt = 0; nt < 4; nt++) {
            const int col = wn + nt * 8 + lc * 2;
            #pragma unroll
            for (int hh = 0; hh < 2; hh++) {
                const int row = wm + mt * 16 + lr + hh * 8;
                const float z = zr[row];
                float2 o;
                o.x = round_tf32(acc[mt][nt][hh * 2 + 0] * z);
                o.y = round_tf32(acc[mt][nt][hh * 2 + 1] * z);
                *reinterpret_cast<float2*>(
                    &g_attn[((size_t)(b * NSEQ + n0 + row)) * INNER + h * DHEAD + col]) = o;
            }
        }
    }
}

// ---------------------------------------------------------------------------
// Launch order: cvt_xq, cvt_xkv, cvt_w, G2 (profiled slot #4), Z, KV, G1, AT, G5
// ---------------------------------------------------------------------------
extern "C" void kernel_launch(void* const* d_in, const int* in_sizes, int n_in,
                              void* d_out, int out_size)
{
    const float* x_q  = (const float*)d_in[0];
    const float* x_kv = (const float*)d_in[1];
    const float* Wq   = (const float*)d_in[2];
    const float* Wkv  = (const float*)d_in[3];
    const float* Wout = (const float*)d_in[4];
    const float* bout = (const float*)d_in[5];
    float* out = (float*)d_out;

    float *xqp, *xkvp, *wqp, *wkvp, *woutp, *qp, *kp, *vp, *ap;
    cudaGetSymbolAddress((void**)&xqp,  g_xq);
    cudaGetSymbolAddress((void**)&xkvp, g_xkv);
    cudaGetSymbolAddress((void**)&wqp,  g_wq);
    cudaGetSymbolAddress((void**)&wkvp, g_wkv);
    cudaGetSymbolAddress((void**)&woutp,g_wout);
    cudaGetSymbolAddress((void**)&qp,   g_q);
    cudaGetSymbolAddress((void**)&kp,   g_k);
    cudaGetSymbolAddress((void**)&vp,   g_v);
    cudaGetSymbolAddress((void**)&ap,   g_attn);

    cudaFuncSetAttribute(mma_gemm<0>, cudaFuncAttributeMaxDynamicSharedMemorySize, G_SMEM_BYTES);
    cudaFuncSetAttribute(mma_gemm<1>, cudaFuncAttributeMaxDynamicSharedMemorySize, G_SMEM_BYTES);
    cudaFuncSetAttribute(mma_gemm<2>, cudaFuncAttributeMaxDynamicSharedMemorySize, G_SMEM_BYTES);
    cudaFuncSetAttribute(attn_mma_kernel, cudaFuncAttributeMaxDynamicSharedMemorySize, A_SMEM);

    dim3 blk(256);

    // 1-3) tf32 pre-rounding of inputs and weights
    cvt_x_kernel<<<2048, blk>>>(x_q,  xqp);
    cvt_x_kernel<<<2048, blk>>>(x_kv, xkvp);
    cvt_w_kernel<<<576, blk>>>(Wq, Wkv, Wout);

    // 4) kv_proj = x_kv @ Wkv -> k (elu1, rounded) / v (rounded)   [profiled]
    mma_gemm<2><<<dim3(2*INNER/128, ROWS/128), blk, G_SMEM_BYTES>>>(
        xkvp, wkvp, kp, vp, nullptr, 2*INNER, DIM);

    // 5) zero accumulators
    zero_kernel<<<(BATCH*HEADS*DHEAD*DHEAD + 255)/256, blk>>>();

    // 6) kv = k^T v; ksum = sum_n k
    kv_mma_kernel<<<dim3(BATCH*HEADS, NSEQ/CHUNK), blk>>>();

    // 7) q = elu1(x_q @ Wq), rounded
    mma_gemm<1><<<dim3(INNER/128, ROWS/128), blk, G_SMEM_BYTES>>>(
        xqp, wqp, qp, nullptr, nullptr, INNER, DIM);

    // 8) attn = (q @ kv) * z, rounded
    attn_mma_kernel<<<dim3(BATCH*HEADS, NSEQ/128), blk, A_SMEM>>>();

    // 9) out = attn @ Wout + bout (full fp32)
    mma_gemm<0><<<dim3(INNER/128, ROWS/128), blk, G_SMEM_BYTES>>>(
        ap, woutp, out, nullptr, bout, INNER, DIM);
}

// round 9
// speedup vs baseline: 1.5080x; 1.0424x over previous
#include <cuda_runtime.h>
#include <cstdint>

#define BATCH 8
#define NSEQ  4096
#define DIM   384
#define HEADS 6
#define DHEAD 64
#define INNER 384
#define ROWS  (BATCH*NSEQ)   // 32768

// ---- scratch (device globals: no allocation allowed) ----
__device__ float g_q   [ (size_t)ROWS*INNER ];
__device__ float g_k   [ (size_t)ROWS*INNER ];
__device__ float g_v   [ (size_t)ROWS*INNER ];
__device__ float g_attn[ (size_t)ROWS*INNER ];
__device__ float g_kv  [ BATCH*HEADS*DHEAD*DHEAD ];
__device__ float g_ksum[ BATCH*HEADS*DHEAD ];

__device__ __forceinline__ float elu1(float x) {
    return x > 0.f ? x + 1.f : __expf(x);
}

__device__ __forceinline__ uint32_t f2tf32(float x) {
    uint32_t u;
    asm("cvt.rna.tf32.f32 %0, %1;" : "=r"(u) : "f"(x));
    return u;
}
__device__ __forceinline__ float round_tf32(float x) {
    return __uint_as_float(f2tf32(x));
}
__device__ __forceinline__ uint32_t cvt_bits(uint32_t raw) {
    return f2tf32(__uint_as_float(raw));
}

__device__ __forceinline__ uint32_t smem_u32(const void* p) {
    uint32_t a;
    asm("{ .reg .u64 t; cvta.to.shared.u64 t, %1; cvt.u32.u64 %0, t; }"
        : "=r"(a) : "l"(p));
    return a;
}
__device__ __forceinline__ void cp16(uint32_t dst, const void* src) {
    asm volatile("cp.async.cg.shared.global [%0], [%1], 16;"
                 :: "r"(dst), "l"(src));
}
#define CP_COMMIT() asm volatile("cp.async.commit_group;")

__device__ __forceinline__ void mma_tf32(float c[4], uint32_t a0, uint32_t a1,
                                         uint32_t a2, uint32_t a3,
                                         uint32_t b0, uint32_t b1) {
    asm volatile(
        "mma.sync.aligned.m16n8k8.row.col.f32.tf32.tf32.f32 "
        "{%0,%1,%2,%3}, {%4,%5,%6,%7}, {%8,%9}, {%0,%1,%2,%3};"
        : "+f"(c[0]), "+f"(c[1]), "+f"(c[2]), "+f"(c[3])
        : "r"(a0), "r"(a1), "r"(a2), "r"(a3), "r"(b0), "r"(b1));
}

// ============================================================================
// tf32 mma.sync GEMM: cp.async 3-stage ring, ONE barrier per ktile,
// in-register rna->tf32 conversion after fragment loads (no pre-pass needed).
// C[M,N] = A[M,K] @ B[K,N], raw fp32 inputs. CTA tile 128x128, BK=32,
// 256 thr (8 warps, warp tile 64x32). M%128==0, N%128==0, K%32==0, K>=96.
// EPI 0: +bias (fp32); EPI 1: elu1 rounded; EPI 2: N-split C(elu1)/C2(raw), rounded.
// ============================================================================
#define APITCH 36
#define BPITCH 136
#define NSTAGE 3
#define ST_AW (128*APITCH)
#define ST_BW (32*BPITCH)
#define G_SMEM_BYTES (NSTAGE*(ST_AW + ST_BW)*4)   // 107520

template<int EPI>
__global__ __launch_bounds__(256, 2)
void mma_gemm(const float* __restrict__ A, const float* __restrict__ B,
              float* __restrict__ C, float* __restrict__ C2,
              const float* __restrict__ bias, int N, int K)
{
    extern __shared__ uint32_t dsm[];
    uint32_t* As = dsm;                       // NSTAGE stages of A
    uint32_t* Bs = dsm + NSTAGE * ST_AW;      // NSTAGE stages of B
    const uint32_t sbA = smem_u32(As);
    const uint32_t sbB = smem_u32(Bs);

    const int tid  = threadIdx.x;
    const int wid  = tid >> 5;
    const int lane = tid & 31;
    const int wm   = (wid & 1) * 64;
    const int wn   = (wid >> 1) * 32;
    const int row0 = blockIdx.y * 128;
    const int col0 = blockIdx.x * 128;
    const int lr = lane >> 2;
    const int lc = lane & 3;

    float acc[4][4][4];
    #pragma unroll
    for (int i = 0; i < 4; i++)
        #pragma unroll
        for (int j = 0; j < 4; j++)
            #pragma unroll
            for (int r = 0; r < 4; r++) acc[i][j][r] = 0.f;

    auto issue = [&](int kt, int stage) {
        const int k0 = kt * 32;
        const uint32_t aB = sbA + (uint32_t)stage * ST_AW * 4;
        const uint32_t bB = sbB + (uint32_t)stage * ST_BW * 4;
        #pragma unroll
        for (int j = 0; j < 4; j++) {
            int idx = tid + 256 * j;
            int r = idx >> 3, c4 = (idx & 7) * 4;
            cp16(aB + (uint32_t)(r * APITCH + c4) * 4,
                 &A[(size_t)(row0 + r) * K + k0 + c4]);
        }
        #pragma unroll
        for (int j = 0; j < 4; j++) {
            int idx = tid + 256 * j;
            int r = idx >> 5, c4 = (idx & 31) * 4;
            cp16(bB + (uint32_t)(r * BPITCH + c4) * 4,
                 &B[(size_t)(k0 + r) * N + col0 + c4]);
        }
        CP_COMMIT();
    };

    const int ntiles = K / 32;   // >= 3 at all call sites (K=384)
    issue(0, 0);
    issue(1, 1);

    int stage = 0;
    for (int kt = 0; kt < ntiles; kt++) {
        if (kt + 1 < ntiles) {
            asm volatile("cp.async.wait_group 1;");
        } else {
            asm volatile("cp.async.wait_group 0;");
        }
        // one barrier: publishes tile kt to all warps AND guarantees every
        // warp has finished MMA on tile kt-1 (stage (kt+2)%3) before reuse.
        __syncthreads();

        if (kt + 2 < ntiles) {
            int s2 = stage + 2; if (s2 >= NSTAGE) s2 -= NSTAGE;
            issue(kt + 2, s2);
        }

        const uint32_t* Asn = As + stage * ST_AW;
        const uint32_t* Bsn = Bs + stage * ST_BW;

        #pragma unroll
        for (int s = 0; s < 4; s++) {
            const int kk = s * 8;
            uint32_t af[4][4];
            #pragma unroll
            for (int mt = 0; mt < 4; mt++) {
                const uint32_t* ap = &Asn[(wm + mt * 16 + lr) * APITCH + kk + lc];
                af[mt][0] = cvt_bits(ap[0]);
                af[mt][1] = cvt_bits(ap[8 * APITCH]);
                af[mt][2] = cvt_bits(ap[4]);
                af[mt][3] = cvt_bits(ap[8 * APITCH + 4]);
            }
            uint32_t bf[4][2];
            #pragma unroll
            for (int nt = 0; nt < 4; nt++) {
                const uint32_t* bp = &Bsn[(kk + lc) * BPITCH + wn + nt * 8 + lr];
                bf[nt][0] = cvt_bits(bp[0]);
                bf[nt][1] = cvt_bits(bp[4 * BPITCH]);
            }
            #pragma unroll
            for (int mt = 0; mt < 4; mt++)
                #pragma unroll
                for (int nt = 0; nt < 4; nt++)
                    mma_tf32(acc[mt][nt], af[mt][0], af[mt][1], af[mt][2],
                             af[mt][3], bf[nt][0], bf[nt][1]);
        }

        if (++stage >= NSTAGE) stage = 0;
    }

    // ---- epilogue ----
    const int half = N >> 1;
    #pragma unroll
    for (int mt = 0; mt < 4; mt++) {
        #pragma unroll
        for (int nt = 0; nt < 4; nt++) {
            const int col = col0 + wn + nt * 8 + lc * 2;
            #pragma unroll
            for (int hh = 0; hh < 2; hh++) {
                const int row = row0 + wm + mt * 16 + lr + hh * 8;
                float v0 = acc[mt][nt][hh * 2 + 0];
                float v1 = acc[mt][nt][hh * 2 + 1];
                float2 o;
                if (EPI == 0) {
                    o.x = v0 + bias[col]; o.y = v1 + bias[col + 1];
                    *reinterpret_cast<float2*>(&C[(size_t)row * N + col]) = o;
                } else if (EPI == 1) {
                    o.x = round_tf32(elu1(v0)); o.y = round_tf32(elu1(v1));
                    *reinterpret_cast<float2*>(&C[(size_t)row * N + col]) = o;
                } else {
                    if (col < half) {
                        o.x = round_tf32(elu1(v0)); o.y = round_tf32(elu1(v1));
                        *reinterpret_cast<float2*>(&C[(size_t)row * half + col]) = o;
                    } else {
                        o.x = round_tf32(v0); o.y = round_tf32(v1);
                        *reinterpret_cast<float2*>(&C2[(size_t)row * half + (col - half)]) = o;
                    }
                }
            }
        }
    }
}

// ---------------------------------------------------------------------------
// Zero kv / ksum accumulators
// ---------------------------------------------------------------------------
__global__ void zero_kernel()
{
    int i = blockIdx.x * 256 + threadIdx.x;
    if (i < BATCH*HEADS*DHEAD*DHEAD) g_kv[i] = 0.f;
    if (i < BATCH*HEADS*DHEAD)       g_ksum[i] = 0.f;
}

// ---------------------------------------------------------------------------
// kv via tf32 mma:  kv[d][m] = sum_n k[n][d] * v[n][m];  ksum[d] = sum_n k[n][d]
// k, v arrive pre-rounded tf32 (GEMM epilogue) -> raw bit copies into smem.
// ---------------------------------------------------------------------------
#define CHUNK 256
#define KTP 36
#define VSP 72
__global__ __launch_bounds__(256)
void kv_mma_kernel()
{
    __shared__ uint32_t Kt[64 * KTP];   // [d][n] tf32
    __shared__ uint32_t Vs[32 * VSP];   // [n][m] tf32
    __shared__ float red[16][64];

    const int bh = blockIdx.x;
    const int b = bh / HEADS, h = bh % HEADS;
    const int n0 = blockIdx.y * CHUNK;

    const int tid  = threadIdx.x;
    const int wid  = tid >> 5;
    const int lane = tid & 31;
    const int wm   = (wid & 1) * 32;
    const int wn   = (wid >> 1) * 16;
    const int lr = lane >> 2;
    const int lc = lane & 3;

    const float* kbase = g_k + ((size_t)(b * NSEQ + n0)) * INNER + h * DHEAD;
    const float* vbase = g_v + ((size_t)(b * NSEQ + n0)) * INNER + h * DHEAD;

    float acc[2][2][4];
    #pragma unroll
    for (int i = 0; i < 2; i++)
        #pragma unroll
        for (int j = 0; j < 2; j++)
            #pragma unroll
            for (int r = 0; r < 4; r++) acc[i][j][r] = 0.f;
    float sk[4] = {0.f, 0.f, 0.f, 0.f};

    for (int sub = 0; sub < CHUNK / 32; sub++) {
        const int nn = sub * 32;
        #pragma unroll
        for (int it = 0; it < 2; it++) {
            int idx = tid + it * 256;
            int n = idx >> 4, c4 = (idx & 15) * 4;
            float4 kw = *reinterpret_cast<const float4*>(
                &kbase[(size_t)(nn + n) * INNER + c4]);
            Kt[(c4 + 0) * KTP + n] = __float_as_uint(kw.x);
            Kt[(c4 + 1) * KTP + n] = __float_as_uint(kw.y);
            Kt[(c4 + 2) * KTP + n] = __float_as_uint(kw.z);
            Kt[(c4 + 3) * KTP + n] = __float_as_uint(kw.w);
            sk[0] += kw.x; sk[1] += kw.y; sk[2] += kw.z; sk[3] += kw.w;
            float4 vw = *reinterpret_cast<const float4*>(
                &vbase[(size_t)(nn + n) * INNER + c4]);
            uint4 o;
            o.x = __float_as_uint(vw.x); o.y = __float_as_uint(vw.y);
            o.z = __float_as_uint(vw.z); o.w = __float_as_uint(vw.w);
            *reinterpret_cast<uint4*>(&Vs[n * VSP + c4]) = o;
        }
        __syncthreads();

        #pragma unroll
        for (int s = 0; s < 4; s++) {
            const int kk = s * 8;
            uint32_t af[2][4];
            #pragma unroll
            for (int mt = 0; mt < 2; mt++) {
                const uint32_t* ap = &Kt[(wm + mt * 16 + lr) * KTP + kk + lc];
                af[mt][0] = ap[0];
                af[mt][1] = ap[8 * KTP];
                af[mt][2] = ap[4];
                af[mt][3] = ap[8 * KTP + 4];
            }
            uint32_t bf[2][2];
            #pragma unroll
            for (int nt = 0; nt < 2; nt++) {
                const uint32_t* bp = &Vs[(kk + lc) * VSP + wn + nt * 8 + lr];
                bf[nt][0] = bp[0];
                bf[nt][1] = bp[4 * VSP];
            }
            #pragma unroll
            for (int mt = 0; mt < 2; mt++)
                #pragma unroll
                for (int nt = 0; nt < 2; nt++)
                    mma_tf32(acc[mt][nt], af[mt][0], af[mt][1], af[mt][2],
                             af[mt][3], bf[nt][0], bf[nt][1]);
        }
        __syncthreads();
    }

    // ---- ksum reduction ----
    {
        const int c4 = (tid & 15) * 4;
        const int grp = tid >> 4;
        #pragma unroll
        for (int j = 0; j < 4; j++) red[grp][c4 + j] = sk[j];
        __syncthreads();
        if (tid < 64) {
            float s = 0.f;
            #pragma unroll
            for (int r = 0; r < 16; r++) s += red[r][tid];
            atomicAdd(&g_ksum[bh * DHEAD + tid], s);
        }
    }

    // ---- kv accumulation ----
    float* kvp = g_kv + (size_t)bh * DHEAD * DHEAD;
    #pragma unroll
    for (int mt = 0; mt < 2; mt++) {
        #pragma unroll
        for (int nt = 0; nt < 2; nt++) {
            const int col = wn + nt * 8 + lc * 2;
            #pragma unroll
            for (int hh = 0; hh < 2; hh++) {
                const int row = wm + mt * 16 + lr + hh * 8;
                atomicAdd(&kvp[row * DHEAD + col],     acc[mt][nt][hh * 2 + 0]);
                atomicAdd(&kvp[row * DHEAD + col + 1], acc[mt][nt][hh * 2 + 1]);
            }
        }
    }
}

// ---------------------------------------------------------------------------
// attn via tf32 mma: attn[n,m] = (q[n,:] @ kv[:,m]) * 1/(q[n,:].ksum + 1e-6)
// q pre-rounded; kv (fp32 atomic sums) converted here. Output rounded.
// ---------------------------------------------------------------------------
#define AQP 68
#define A_QS  0
#define A_KVS 34816
#define A_KS  52224
#define A_ZR  52480
#define A_SMEM 52992

__global__ __launch_bounds__(256)
void attn_mma_kernel()
{
    extern __shared__ char smem[];
    uint32_t* qs  = reinterpret_cast<uint32_t*>(smem + A_QS);
    uint32_t* kvs = reinterpret_cast<uint32_t*>(smem + A_KVS);
    float*    ks  = reinterpret_cast<float*>(smem + A_KS);
    float*    zr  = reinterpret_cast<float*>(smem + A_ZR);

    const int bh = blockIdx.x;
    const int b = bh / HEADS, h = bh % HEADS;
    const int n0 = blockIdx.y * 128;

    const int tid  = threadIdx.x;
    const int wid  = tid >> 5;
    const int lane = tid & 31;
    const int wm   = (wid & 3) * 32;
    const int wn   = (wid >> 2) * 32;
    const int lr = lane >> 2;
    const int lc = lane & 3;

    const float* qptr = g_q + ((size_t)(b * NSEQ + n0)) * INNER + h * DHEAD;
    #pragma unroll
    for (int j = 0; j < 8; j++) {
        int idx = tid + 256 * j;
        int r = idx >> 4, c4 = (idx & 15) * 4;
        float4 v = *reinterpret_cast<const float4*>(&qptr[(size_t)r * INNER + c4]);
        uint32_t* d = &qs[r * AQP + c4];
        d[0] = __float_as_uint(v.x); d[1] = __float_as_uint(v.y);
        d[2] = __float_as_uint(v.z); d[3] = __float_as_uint(v.w);
    }
    #pragma unroll
    for (int j = 0; j < 4; j++) {
        int idx = tid + 256 * j;
        int d = idx >> 4, m4 = (idx & 15) * 4;
        float4 v = *reinterpret_cast<const float4*>(&g_kv[(size_t)bh * 4096 + d * 64 + m4]);
        kvs[(m4 + 0) * AQP + d] = f2tf32(v.x);
        kvs[(m4 + 1) * AQP + d] = f2tf32(v.y);
        kvs[(m4 + 2) * AQP + d] = f2tf32(v.z);
        kvs[(m4 + 3) * AQP + d] = f2tf32(v.w);
    }
    if (tid < 64) ks[tid] = g_ksum[bh * 64 + tid];
    __syncthreads();

    if (tid < 128) {
        float s = 0.f;
        #pragma unroll
        for (int dd = 0; dd < 64; dd++)
            s += __uint_as_float(qs[tid * AQP + dd]) * ks[dd];
        zr[tid] = 1.f / (s + 1e-6f);
    }
    __syncthreads();

    float acc[2][4][4];
    #pragma unroll
    for (int i = 0; i < 2; i++)
        #pragma unroll
        for (int j = 0; j < 4; j++)
            #pragma unroll
            for (int r = 0; r < 4; r++) acc[i][j][r] = 0.f;

    #pragma unroll
    for (int s = 0; s < 8; s++) {
        const int kk = s * 8;
        uint32_t af[2][4];
        #pragma unroll
        for (int mt = 0; mt < 2; mt++) {
            const uint32_t* ap = &qs[(wm + mt * 16 + lr) * AQP + kk + lc];
            af[mt][0] = ap[0];
            af[mt][1] = ap[8 * AQP];
            af[mt][2] = ap[4];
            af[mt][3] = ap[8 * AQP + 4];
        }
        uint32_t bf[4][2];
        #pragma unroll
        for (int nt = 0; nt < 4; nt++) {
            const uint32_t* bp = &kvs[(wn + nt * 8 + lr) * AQP + kk + lc];
            bf[nt][0] = bp[0];
            bf[nt][1] = bp[4];
        }
        #pragma unroll
        for (int mt = 0; mt < 2; mt++)
            #pragma unroll
            for (int nt = 0; nt < 4; nt++)
                mma_tf32(acc[mt][nt], af[mt][0], af[mt][1], af[mt][2],
                         af[mt][3], bf[nt][0], bf[nt][1]);
    }

    #pragma unroll
    for (int mt = 0; mt < 2; mt++) {
        #pragma unroll
        for (int nt = 0; nt < 4; nt++) {
            const int col = wn + nt * 8 + lc * 2;
            #pragma unroll
            for (int hh = 0; hh < 2; hh++) {
                const int row = wm + mt * 16 + lr + hh * 8;
                const float z = zr[row];
                float2 o;
                o.x = round_tf32(acc[mt][nt][hh * 2 + 0] * z);
                o.y = round_tf32(acc[mt][nt][hh * 2 + 1] * z);
                *reinterpret_cast<float2*>(
                    &g_attn[((size_t)(b * NSEQ + n0 + row)) * INNER + h * DHEAD + col]) = o;
            }
        }
    }
}

// ---------------------------------------------------------------------------
// Launch order: G2, Z, KV, G1 (profiled 4th slot), AT, G5
// ---------------------------------------------------------------------------
extern "C" void kernel_launch(void* const* d_in, const int* in_sizes, int n_in,
                              void* d_out, int out_size)
{
    const float* x_q  = (const float*)d_in[0];
    const float* x_kv = (const float*)d_in[1];
    const float* Wq   = (const float*)d_in[2];
    const float* Wkv  = (const float*)d_in[3];
    const float* Wout = (const float*)d_in[4];
    const float* bout = (const float*)d_in[5];
    float* out = (float*)d_out;

    float *qp, *kp, *vp, *ap;
    cudaGetSymbolAddress((void**)&qp, g_q);
    cudaGetSymbolAddress((void**)&kp, g_k);
    cudaGetSymbolAddress((void**)&vp, g_v);
    cudaGetSymbolAddress((void**)&ap, g_attn);

    cudaFuncSetAttribute(mma_gemm<0>, cudaFuncAttributeMaxDynamicSharedMemorySize, G_SMEM_BYTES);
    cudaFuncSetAttribute(mma_gemm<1>, cudaFuncAttributeMaxDynamicSharedMemorySize, G_SMEM_BYTES);
    cudaFuncSetAttribute(mma_gemm<2>, cudaFuncAttributeMaxDynamicSharedMemorySize, G_SMEM_BYTES);
    cudaFuncSetAttribute(attn_mma_kernel, cudaFuncAttributeMaxDynamicSharedMemorySize, A_SMEM);

    dim3 blk(256);

    // 1) kv_proj = x_kv @ Wkv -> k (elu1, rounded) / v (rounded)
    mma_gemm<2><<<dim3(2*INNER/128, ROWS/128), blk, G_SMEM_BYTES>>>(
        x_kv, Wkv, kp, vp, nullptr, 2*INNER, DIM);

    // 2) zero accumulators
    zero_kernel<<<(BATCH*HEADS*DHEAD*DHEAD + 255)/256, blk>>>();

    // 3) kv = k^T v; ksum = sum_n k
    kv_mma_kernel<<<dim3(BATCH*HEADS, NSEQ/CHUNK), blk>>>();

    // 4) q = elu1(x_q @ Wq), rounded      [profiled slot]
    mma_gemm<1><<<dim3(INNER/128, ROWS/128), blk, G_SMEM_BYTES>>>(
        x_q, Wq, qp, nullptr, nullptr, INNER, DIM);

    // 5) attn = (q @ kv) * z, rounded
    attn_mma_kernel<<<dim3(BATCH*HEADS, NSEQ/128), blk, A_SMEM>>>();

    // 6) out = attn @ Wout + bout (fp32)
    mma_gemm<0><<<dim3(INNER/128, ROWS/128), blk, G_SMEM_BYTES>>>(
        ap, Wout, out, nullptr, bout, INNER, DIM);
}

// round 10
// speedup vs baseline: 1.5229x; 1.0098x over previous
#include <cuda_runtime.h>
#include <cstdint>

#define BATCH 8
#define NSEQ  4096
#define DIM   384
#define HEADS 6
#define DHEAD 64
#define INNER 384
#define ROWS  (BATCH*NSEQ)   // 32768

// ---- scratch (device globals: no allocation allowed) ----
__device__ float g_wq  [ DIM*INNER ];          // tf32-rounded weights
__device__ float g_wkv [ DIM*2*INNER ];
__device__ float g_wout[ INNER*DIM ];
__device__ float g_q   [ (size_t)ROWS*INNER ];
__device__ float g_k   [ (size_t)ROWS*INNER ];
__device__ float g_v   [ (size_t)ROWS*INNER ];
__device__ float g_attn[ (size_t)ROWS*INNER ];
__device__ float g_kv  [ BATCH*HEADS*DHEAD*DHEAD ];
__device__ float g_ksum[ BATCH*HEADS*DHEAD ];

__device__ __forceinline__ float elu1(float x) {
    return x > 0.f ? x + 1.f : __expf(x);
}

__device__ __forceinline__ uint32_t f2tf32(float x) {
    uint32_t u;
    asm("cvt.rna.tf32.f32 %0, %1;" : "=r"(u) : "f"(x));
    return u;
}
__device__ __forceinline__ float round_tf32(float x) {
    return __uint_as_float(f2tf32(x));
}
__device__ __forceinline__ uint32_t cvt_bits(uint32_t raw) {
    return f2tf32(__uint_as_float(raw));
}

__device__ __forceinline__ uint32_t smem_u32(const void* p) {
    uint32_t a;
    asm("{ .reg .u64 t; cvta.to.shared.u64 t, %1; cvt.u32.u64 %0, t; }"
        : "=r"(a) : "l"(p));
    return a;
}
__device__ __forceinline__ void cp16(uint32_t dst, const void* src) {
    asm volatile("cp.async.cg.shared.global [%0], [%1], 16;"
                 :: "r"(dst), "l"(src));
}
#define CP_COMMIT() asm volatile("cp.async.commit_group;")

__device__ __forceinline__ void mma_tf32(float c[4], uint32_t a0, uint32_t a1,
                                         uint32_t a2, uint32_t a3,
                                         uint32_t b0, uint32_t b1) {
    asm volatile(
        "mma.sync.aligned.m16n8k8.row.col.f32.tf32.tf32.f32 "
        "{%0,%1,%2,%3}, {%4,%5,%6,%7}, {%8,%9}, {%0,%1,%2,%3};"
        : "+f"(c[0]), "+f"(c[1]), "+f"(c[2]), "+f"(c[3])
        : "r"(a0), "r"(a1), "r"(a2), "r"(a3), "r"(b0), "r"(b1));
}

// ---------------------------------------------------------------------------
// One-time weight rounding: fp32 -> tf32 bits (rna), ~2.3 MB total.
// ---------------------------------------------------------------------------
__global__ void cvt_w_kernel(const float* __restrict__ wq,
                             const float* __restrict__ wkv,
                             const float* __restrict__ wout)
{
    const int n1 = DIM*INNER/4, n2 = DIM*2*INNER/4, n3 = INNER*DIM/4;
    for (int i = blockIdx.x * blockDim.x + threadIdx.x; i < n1 + n2 + n3;
         i += gridDim.x * blockDim.x) {
        const float4* s; float4* d; int j;
        if (i < n1)           { s = (const float4*)wq;   d = (float4*)g_wq;   j = i; }
        else if (i < n1 + n2) { s = (const float4*)wkv;  d = (float4*)g_wkv;  j = i - n1; }
        else                  { s = (const float4*)wout; d = (float4*)g_wout; j = i - n1 - n2; }
        float4 v = s[j];
        v.x = round_tf32(v.x); v.y = round_tf32(v.y);
        v.z = round_tf32(v.z); v.w = round_tf32(v.w);
        d[j] = v;
    }
}

// ============================================================================
// tf32 mma.sync GEMM: cp.async 3-stage ring, ONE barrier per ktile.
// B operand must be PRE-ROUNDED tf32 (weights). A converted in-register iff
// CVTA (x inputs); pre-rounded A (g_attn) skips conversion entirely.
// C[M,N] = A[M,K] @ B[K,N]. CTA tile 128x128, BK=32, 256 thr (8 warps,
// warp tile 64x32). M%128==0, N%128==0, K%32==0, K>=96.
// EPI 0: +bias (fp32); EPI 1: elu1 rounded; EPI 2: N-split C(elu1)/C2(raw), rounded.
// ============================================================================
#define APITCH 36
#define BPITCH 136
#define NSTAGE 3
#define ST_AW (128*APITCH)
#define ST_BW (32*BPITCH)
#define G_SMEM_BYTES (NSTAGE*(ST_AW + ST_BW)*4)   // 107520

template<int EPI, bool CVTA>
__global__ __launch_bounds__(256, 2)
void mma_gemm(const float* __restrict__ A, const float* __restrict__ B,
              float* __restrict__ C, float* __restrict__ C2,
              const float* __restrict__ bias, int N, int K)
{
    extern __shared__ uint32_t dsm[];
    uint32_t* As = dsm;
    uint32_t* Bs = dsm + NSTAGE * ST_AW;
    const uint32_t sbA = smem_u32(As);
    const uint32_t sbB = smem_u32(Bs);

    const int tid  = threadIdx.x;
    const int wid  = tid >> 5;
    const int lane = tid & 31;
    const int wm   = (wid & 1) * 64;
    const int wn   = (wid >> 1) * 32;
    const int row0 = blockIdx.y * 128;
    const int col0 = blockIdx.x * 128;
    const int lr = lane >> 2;
    const int lc = lane & 3;

    float acc[4][4][4];
    #pragma unroll
    for (int i = 0; i < 4; i++)
        #pragma unroll
        for (int j = 0; j < 4; j++)
            #pragma unroll
            for (int r = 0; r < 4; r++) acc[i][j][r] = 0.f;

    auto issue = [&](int kt, int stage) {
        const int k0 = kt * 32;
        const uint32_t aB = sbA + (uint32_t)stage * ST_AW * 4;
        const uint32_t bB = sbB + (uint32_t)stage * ST_BW * 4;
        #pragma unroll
        for (int j = 0; j < 4; j++) {
            int idx = tid + 256 * j;
            int r = idx >> 3, c4 = (idx & 7) * 4;
            cp16(aB + (uint32_t)(r * APITCH + c4) * 4,
                 &A[(size_t)(row0 + r) * K + k0 + c4]);
        }
        #pragma unroll
        for (int j = 0; j < 4; j++) {
            int idx = tid + 256 * j;
            int r = idx >> 5, c4 = (idx & 31) * 4;
            cp16(bB + (uint32_t)(r * BPITCH + c4) * 4,
                 &B[(size_t)(k0 + r) * N + col0 + c4]);
        }
        CP_COMMIT();
    };

    const int ntiles = K / 32;
    issue(0, 0);
    issue(1, 1);

    int stage = 0;
    for (int kt = 0; kt < ntiles; kt++) {
        if (kt + 1 < ntiles) {
            asm volatile("cp.async.wait_group 1;");
        } else {
            asm volatile("cp.async.wait_group 0;");
        }
        __syncthreads();

        if (kt + 2 < ntiles) {
            int s2 = stage + 2; if (s2 >= NSTAGE) s2 -= NSTAGE;
            issue(kt + 2, s2);
        }

        const uint32_t* Asn = As + stage * ST_AW;
        const uint32_t* Bsn = Bs + stage * ST_BW;

        #pragma unroll
        for (int s = 0; s < 4; s++) {
            const int kk = s * 8;
            uint32_t af[4][4];
            #pragma unroll
            for (int mt = 0; mt < 4; mt++) {
                const uint32_t* ap = &Asn[(wm + mt * 16 + lr) * APITCH + kk + lc];
                if (CVTA) {
                    af[mt][0] = cvt_bits(ap[0]);
                    af[mt][1] = cvt_bits(ap[8 * APITCH]);
                    af[mt][2] = cvt_bits(ap[4]);
                    af[mt][3] = cvt_bits(ap[8 * APITCH + 4]);
                } else {
                    af[mt][0] = ap[0];
                    af[mt][1] = ap[8 * APITCH];
                    af[mt][2] = ap[4];
                    af[mt][3] = ap[8 * APITCH + 4];
                }
            }
            uint32_t bf[4][2];
            #pragma unroll
            for (int nt = 0; nt < 4; nt++) {
                const uint32_t* bp = &Bsn[(kk + lc) * BPITCH + wn + nt * 8 + lr];
                bf[nt][0] = bp[0];
                bf[nt][1] = bp[4 * BPITCH];
            }
            #pragma unroll
            for (int mt = 0; mt < 4; mt++)
                #pragma unroll
                for (int nt = 0; nt < 4; nt++)
                    mma_tf32(acc[mt][nt], af[mt][0], af[mt][1], af[mt][2],
                             af[mt][3], bf[nt][0], bf[nt][1]);
        }

        if (++stage >= NSTAGE) stage = 0;
    }

    // ---- epilogue ----
    const int half = N >> 1;
    #pragma unroll
    for (int mt = 0; mt < 4; mt++) {
        #pragma unroll
        for (int nt = 0; nt < 4; nt++) {
            const int col = col0 + wn + nt * 8 + lc * 2;
            #pragma unroll
            for (int hh = 0; hh < 2; hh++) {
                const int row = row0 + wm + mt * 16 + lr + hh * 8;
                float v0 = acc[mt][nt][hh * 2 + 0];
                float v1 = acc[mt][nt][hh * 2 + 1];
                float2 o;
                if (EPI == 0) {
                    o.x = v0 + bias[col]; o.y = v1 + bias[col + 1];
                    *reinterpret_cast<float2*>(&C[(size_t)row * N + col]) = o;
                } else if (EPI == 1) {
                    o.x = round_tf32(elu1(v0)); o.y = round_tf32(elu1(v1));
                    *reinterpret_cast<float2*>(&C[(size_t)row * N + col]) = o;
                } else {
                    if (col < half) {
                        o.x = round_tf32(elu1(v0)); o.y = round_tf32(elu1(v1));
                        *reinterpret_cast<float2*>(&C[(size_t)row * half + col]) = o;
                    } else {
                        o.x = round_tf32(v0); o.y = round_tf32(v1);
                        *reinterpret_cast<float2*>(&C2[(size_t)row * half + (col - half)]) = o;
                    }
                }
            }
        }
    }
}

// ---------------------------------------------------------------------------
// Zero kv / ksum accumulators
// ---------------------------------------------------------------------------
__global__ void zero_kernel()
{
    int i = blockIdx.x * 256 + threadIdx.x;
    if (i < BATCH*HEADS*DHEAD*DHEAD) g_kv[i] = 0.f;
    if (i < BATCH*HEADS*DHEAD)       g_ksum[i] = 0.f;
}

// ---------------------------------------------------------------------------
// kv via tf32 mma:  kv[d][m] = sum_n k[n][d] * v[n][m];  ksum[d] = sum_n k[n][d]
// k, v arrive pre-rounded tf32 (GEMM epilogue) -> raw bit copies into smem.
// ---------------------------------------------------------------------------
#define CHUNK 256
#define KTP 36
#define VSP 72
__global__ __launch_bounds__(256)
void kv_mma_kernel()
{
    __shared__ uint32_t Kt[64 * KTP];   // [d][n] tf32
    __shared__ uint32_t Vs[32 * VSP];   // [n][m] tf32
    __shared__ float red[16][64];

    const int bh = blockIdx.x;
    const int b = bh / HEADS, h = bh % HEADS;
    const int n0 = blockIdx.y * CHUNK;

    const int tid  = threadIdx.x;
    const int wid  = tid >> 5;
    const int lane = tid & 31;
    const int wm   = (wid & 1) * 32;
    const int wn   = (wid >> 1) * 16;
    const int lr = lane >> 2;
    const int lc = lane & 3;

    const float* kbase = g_k + ((size_t)(b * NSEQ + n0)) * INNER + h * DHEAD;
    const float* vbase = g_v + ((size_t)(b * NSEQ + n0)) * INNER + h * DHEAD;

    float acc[2][2][4];
    #pragma unroll
    for (int i = 0; i < 2; i++)
        #pragma unroll
        for (int j = 0; j < 2; j++)
            #pragma unroll
            for (int r = 0; r < 4; r++) acc[i][j][r] = 0.f;
    float sk[4] = {0.f, 0.f, 0.f, 0.f};

    for (int sub = 0; sub < CHUNK / 32; sub++) {
        const int nn = sub * 32;
        #pragma unroll
        for (int it = 0; it < 2; it++) {
            int idx = tid + it * 256;
            int n = idx >> 4, c4 = (idx & 15) * 4;
            float4 kw = *reinterpret_cast<const float4*>(
                &kbase[(size_t)(nn + n) * INNER + c4]);
            Kt[(c4 + 0) * KTP + n] = __float_as_uint(kw.x);
            Kt[(c4 + 1) * KTP + n] = __float_as_uint(kw.y);
            Kt[(c4 + 2) * KTP + n] = __float_as_uint(kw.z);
            Kt[(c4 + 3) * KTP + n] = __float_as_uint(kw.w);
            sk[0] += kw.x; sk[1] += kw.y; sk[2] += kw.z; sk[3] += kw.w;
            float4 vw = *reinterpret_cast<const float4*>(
                &vbase[(size_t)(nn + n) * INNER + c4]);
            uint4 o;
            o.x = __float_as_uint(vw.x); o.y = __float_as_uint(vw.y);
            o.z = __float_as_uint(vw.z); o.w = __float_as_uint(vw.w);
            *reinterpret_cast<uint4*>(&Vs[n * VSP + c4]) = o;
        }
        __syncthreads();

        #pragma unroll
        for (int s = 0; s < 4; s++) {
            const int kk = s * 8;
            uint32_t af[2][4];
            #pragma unroll
            for (int mt = 0; mt < 2; mt++) {
                const uint32_t* ap = &Kt[(wm + mt * 16 + lr) * KTP + kk + lc];
                af[mt][0] = ap[0];
                af[mt][1] = ap[8 * KTP];
                af[mt][2] = ap[4];
                af[mt][3] = ap[8 * KTP + 4];
            }
            uint32_t bf[2][2];
            #pragma unroll
            for (int nt = 0; nt < 2; nt++) {
                const uint32_t* bp = &Vs[(kk + lc) * VSP + wn + nt * 8 + lr];
                bf[nt][0] = bp[0];
                bf[nt][1] = bp[4 * VSP];
            }
            #pragma unroll
            for (int mt = 0; mt < 2; mt++)
                #pragma unroll
                for (int nt = 0; nt < 2; nt++)
                    mma_tf32(acc[mt][nt], af[mt][0], af[mt][1], af[mt][2],
                             af[mt][3], bf[nt][0], bf[nt][1]);
        }
        __syncthreads();
    }

    // ---- ksum reduction ----
    {
        const int c4 = (tid & 15) * 4;
        const int grp = tid >> 4;
        #pragma unroll
        for (int j = 0; j < 4; j++) red[grp][c4 + j] = sk[j];
        __syncthreads();
        if (tid < 64) {
            float s = 0.f;
            #pragma unroll
            for (int r = 0; r < 16; r++) s += red[r][tid];
            atomicAdd(&g_ksum[bh * DHEAD + tid], s);
        }
    }

    // ---- kv accumulation ----
    float* kvp = g_kv + (size_t)bh * DHEAD * DHEAD;
    #pragma unroll
    for (int mt = 0; mt < 2; mt++) {
        #pragma unroll
        for (int nt = 0; nt < 2; nt++) {
            const int col = wn + nt * 8 + lc * 2;
            #pragma unroll
            for (int hh = 0; hh < 2; hh++) {
                const int row = wm + mt * 16 + lr + hh * 8;
                atomicAdd(&kvp[row * DHEAD + col],     acc[mt][nt][hh * 2 + 0]);
                atomicAdd(&kvp[row * DHEAD + col + 1], acc[mt][nt][hh * 2 + 1]);
            }
        }
    }
}

// ---------------------------------------------------------------------------
// attn via tf32 mma: attn[n,m] = (q[n,:] @ kv[:,m]) * 1/(q[n,:].ksum + 1e-6)
// q pre-rounded; kv (fp32 atomic sums) converted here. Output rounded.
// ---------------------------------------------------------------------------
#define AQP 68
#define A_QS  0
#define A_KVS 34816
#define A_KS  52224
#define A_ZR  52480
#define A_SMEM 52992

__global__ __launch_bounds__(256)
void attn_mma_kernel()
{
    extern __shared__ char smem[];
    uint32_t* qs  = reinterpret_cast<uint32_t*>(smem + A_QS);
    uint32_t* kvs = reinterpret_cast<uint32_t*>(smem + A_KVS);
    float*    ks  = reinterpret_cast<float*>(smem + A_KS);
    float*    zr  = reinterpret_cast<float*>(smem + A_ZR);

    const int bh = blockIdx.x;
    const int b = bh / HEADS, h = bh % HEADS;
    const int n0 = blockIdx.y * 128;

    const int tid  = threadIdx.x;
    const int wid  = tid >> 5;
    const int lane = tid & 31;
    const int wm   = (wid & 3) * 32;
    const int wn   = (wid >> 2) * 32;
    const int lr = lane >> 2;
    const int lc = lane & 3;

    const float* qptr = g_q + ((size_t)(b * NSEQ + n0)) * INNER + h * DHEAD;
    #pragma unroll
    for (int j = 0; j < 8; j++) {
        int idx = tid + 256 * j;
        int r = idx >> 4, c4 = (idx & 15) * 4;
        float4 v = *reinterpret_cast<const float4*>(&qptr[(size_t)r * INNER + c4]);
        uint32_t* d = &qs[r * AQP + c4];
        d[0] = __float_as_uint(v.x); d[1] = __float_as_uint(v.y);
        d[2] = __float_as_uint(v.z); d[3] = __float_as_uint(v.w);
    }
    #pragma unroll
    for (int j = 0; j < 4; j++) {
        int idx = tid + 256 * j;
        int d = idx >> 4, m4 = (idx & 15) * 4;
        float4 v = *reinterpret_cast<const float4*>(&g_kv[(size_t)bh * 4096 + d * 64 + m4]);
        kvs[(m4 + 0) * AQP + d] = f2tf32(v.x);
        kvs[(m4 + 1) * AQP + d] = f2tf32(v.y);
        kvs[(m4 + 2) * AQP + d] = f2tf32(v.z);
        kvs[(m4 + 3) * AQP + d] = f2tf32(v.w);
    }
    if (tid < 64) ks[tid] = g_ksum[bh * 64 + tid];
    __syncthreads();

    if (tid < 128) {
        float s = 0.f;
        #pragma unroll
        for (int dd = 0; dd < 64; dd++)
            s += __uint_as_float(qs[tid * AQP + dd]) * ks[dd];
        zr[tid] = 1.f / (s + 1e-6f);
    }
    __syncthreads();

    float acc[2][4][4];
    #pragma unroll
    for (int i = 0; i < 2; i++)
        #pragma unroll
        for (int j = 0; j < 4; j++)
            #pragma unroll
            for (int r = 0; r < 4; r++) acc[i][j][r] = 0.f;

    #pragma unroll
    for (int s = 0; s < 8; s++) {
        const int kk = s * 8;
        uint32_t af[2][4];
        #pragma unroll
        for (int mt = 0; mt < 2; mt++) {
            const uint32_t* ap = &qs[(wm + mt * 16 + lr) * AQP + kk + lc];
            af[mt][0] = ap[0];
            af[mt][1] = ap[8 * AQP];
            af[mt][2] = ap[4];
            af[mt][3] = ap[8 * AQP + 4];
        }
        uint32_t bf[4][2];
        #pragma unroll
        for (int nt = 0; nt < 4; nt++) {
            const uint32_t* bp = &kvs[(wn + nt * 8 + lr) * AQP + kk + lc];
            bf[nt][0] = bp[0];
            bf[nt][1] = bp[4];
        }
        #pragma unroll
        for (int mt = 0; mt < 2; mt++)
            #pragma unroll
            for (int nt = 0; nt < 4; nt++)
                mma_tf32(acc[mt][nt], af[mt][0], af[mt][1], af[mt][2],
                         af[mt][3], bf[nt][0], bf[nt][1]);
    }

    #pragma unroll
    for (int mt = 0; mt < 2; mt++) {
        #pragma unroll
        for (int nt = 0; nt < 4; nt++) {
            const int col = wn + nt * 8 + lc * 2;
            #pragma unroll
            for (int hh = 0; hh < 2; hh++) {
                const int row = wm + mt * 16 + lr + hh * 8;
                const float z = zr[row];
                float2 o;
                o.x = round_tf32(acc[mt][nt][hh * 2 + 0] * z);
                o.y = round_tf32(acc[mt][nt][hh * 2 + 1] * z);
                *reinterpret_cast<float2*>(
                    &g_attn[((size_t)(b * NSEQ + n0 + row)) * INNER + h * DHEAD + col]) = o;
            }
        }
    }
}

// ---------------------------------------------------------------------------
// Launch order: CVTW, G2, Z, G1 (profiled 4th slot), KV, AT, G5
// ---------------------------------------------------------------------------
extern "C" void kernel_launch(void* const* d_in, const int* in_sizes, int n_in,
                              void* d_out, int out_size)
{
    const float* x_q  = (const float*)d_in[0];
    const float* x_kv = (const float*)d_in[1];
    const float* Wq   = (const float*)d_in[2];
    const float* Wkv  = (const float*)d_in[3];
    const float* Wout = (const float*)d_in[4];
    const float* bout = (const float*)d_in[5];
    float* out = (float*)d_out;

    float *wqp, *wkvp, *woutp, *qp, *kp, *vp, *ap;
    cudaGetSymbolAddress((void**)&wqp,  g_wq);
    cudaGetSymbolAddress((void**)&wkvp, g_wkv);
    cudaGetSymbolAddress((void**)&woutp,g_wout);
    cudaGetSymbolAddress((void**)&qp,   g_q);
    cudaGetSymbolAddress((void**)&kp,   g_k);
    cudaGetSymbolAddress((void**)&vp,   g_v);
    cudaGetSymbolAddress((void**)&ap,   g_attn);

    cudaFuncSetAttribute((const void*)mma_gemm<0,false>, cudaFuncAttributeMaxDynamicSharedMemorySize, G_SMEM_BYTES);
    cudaFuncSetAttribute((const void*)mma_gemm<1,true >, cudaFuncAttributeMaxDynamicSharedMemorySize, G_SMEM_BYTES);
    cudaFuncSetAttribute((const void*)mma_gemm<2,true >, cudaFuncAttributeMaxDynamicSharedMemorySize, G_SMEM_BYTES);
    cudaFuncSetAttribute((const void*)attn_mma_kernel,   cudaFuncAttributeMaxDynamicSharedMemorySize, A_SMEM);

    dim3 blk(256);

    // 1) pre-round weights to tf32 (one-time, ~2.3 MB)
    cvt_w_kernel<<<576, blk>>>(Wq, Wkv, Wout);

    // 2) kv_proj = x_kv @ Wkv -> k (elu1, rounded) / v (rounded)
    mma_gemm<2,true><<<dim3(2*INNER/128, ROWS/128), blk, G_SMEM_BYTES>>>(
        x_kv, wkvp, kp, vp, nullptr, 2*INNER, DIM);

    // 3) zero accumulators
    zero_kernel<<<(BATCH*HEADS*DHEAD*DHEAD + 255)/256, blk>>>();

    // 4) q = elu1(x_q @ Wq), rounded      [profiled slot]
    mma_gemm<1,true><<<dim3(INNER/128, ROWS/128), blk, G_SMEM_BYTES>>>(
        x_q, wqp, qp, nullptr, nullptr, INNER, DIM);

    // 5) kv = k^T v; ksum = sum_n k
    kv_mma_kernel<<<dim3(BATCH*HEADS, NSEQ/CHUNK), blk>>>();

    // 6) attn = (q @ kv) * z, rounded
    attn_mma_kernel<<<dim3(BATCH*HEADS, NSEQ/128), blk, A_SMEM>>>();

    // 7) out = attn @ Wout + bout (fp32); attn already tf32 -> no CVT at all
    mma_gemm<0,false><<<dim3(INNER/128, ROWS/128), blk, G_SMEM_BYTES>>>(
        ap, woutp, out, nullptr, bout, INNER, DIM);
}

// round 11
// speedup vs baseline: 1.6765x; 1.1009x over previous
#include <cuda_runtime.h>
#include <cstdint>

#define BATCH 8
#define NSEQ  4096
#define DIM   384
#define HEADS 6
#define DHEAD 64
#define INNER 384
#define ROWS  (BATCH*NSEQ)   // 32768

// ---- scratch (device globals: no allocation allowed) ----
__device__ float g_wq  [ DIM*INNER ];          // tf32-rounded weights
__device__ float g_wkv [ DIM*2*INNER ];
__device__ float g_wout[ INNER*DIM ];
__device__ float g_q   [ (size_t)ROWS*INNER ];
__device__ float g_k   [ (size_t)ROWS*INNER ];
__device__ float g_v   [ (size_t)ROWS*INNER ];
__device__ float g_attn[ (size_t)ROWS*INNER ];
__device__ float g_kv  [ BATCH*HEADS*DHEAD*DHEAD ];
__device__ float g_ksum[ BATCH*HEADS*DHEAD ];

__device__ __forceinline__ float elu1(float x) {
    return x > 0.f ? x + 1.f : __expf(x);
}

__device__ __forceinline__ uint32_t f2tf32(float x) {
    uint32_t u;
    asm("cvt.rna.tf32.f32 %0, %1;" : "=r"(u) : "f"(x));
    return u;
}
__device__ __forceinline__ float round_tf32(float x) {
    return __uint_as_float(f2tf32(x));
}
__device__ __forceinline__ uint32_t cvt_bits(uint32_t raw) {
    return f2tf32(__uint_as_float(raw));
}

__device__ __forceinline__ uint32_t smem_u32(const void* p) {
    uint32_t a;
    asm("{ .reg .u64 t; cvta.to.shared.u64 t, %1; cvt.u32.u64 %0, t; }"
        : "=r"(a) : "l"(p));
    return a;
}
__device__ __forceinline__ void cp16(uint32_t dst, const void* src) {
    asm volatile("cp.async.cg.shared.global [%0], [%1], 16;"
                 :: "r"(dst), "l"(src));
}
#define CP_COMMIT() asm volatile("cp.async.commit_group;")

__device__ __forceinline__ void mma_tf32(float c[4], uint32_t a0, uint32_t a1,
                                         uint32_t a2, uint32_t a3,
                                         uint32_t b0, uint32_t b1) {
    asm volatile(
        "mma.sync.aligned.m16n8k8.row.col.f32.tf32.tf32.f32 "
        "{%0,%1,%2,%3}, {%4,%5,%6,%7}, {%8,%9}, {%0,%1,%2,%3};"
        : "+f"(c[0]), "+f"(c[1]), "+f"(c[2]), "+f"(c[3])
        : "r"(a0), "r"(a1), "r"(a2), "r"(a3), "r"(b0), "r"(b1));
}

// ---------------------------------------------------------------------------
// One-time: round weights to tf32 AND zero kv/ksum accumulators (merged).
// ---------------------------------------------------------------------------
__global__ void cvt_w_zero_kernel(const float* __restrict__ wq,
                                  const float* __restrict__ wkv,
                                  const float* __restrict__ wout)
{
    const int n1 = DIM*INNER/4, n2 = DIM*2*INNER/4, n3 = INNER*DIM/4;
    const int nw = n1 + n2 + n3;
    const int nz = BATCH*HEADS*DHEAD*DHEAD/4;   // g_kv float4 count
    const int nz2 = BATCH*HEADS*DHEAD/4;        // g_ksum float4 count
    const float4 z4 = make_float4(0.f, 0.f, 0.f, 0.f);
    for (int i = blockIdx.x * blockDim.x + threadIdx.x; i < nw + nz + nz2;
         i += gridDim.x * blockDim.x) {
        if (i < nw) {
            const float4* s; float4* d; int j;
            if (i < n1)           { s = (const float4*)wq;   d = (float4*)g_wq;   j = i; }
            else if (i < n1 + n2) { s = (const float4*)wkv;  d = (float4*)g_wkv;  j = i - n1; }
            else                  { s = (const float4*)wout; d = (float4*)g_wout; j = i - n1 - n2; }
            float4 v = s[j];
            v.x = round_tf32(v.x); v.y = round_tf32(v.y);
            v.z = round_tf32(v.z); v.w = round_tf32(v.w);
            d[j] = v;
        } else if (i < nw + nz) {
            reinterpret_cast<float4*>(g_kv)[i - nw] = z4;
        } else {
            reinterpret_cast<float4*>(g_ksum)[i - nw - nz] = z4;
        }
    }
}

// ============================================================================
// tf32 mma.sync GEMM core: cp.async 3-stage ring, ONE barrier per ktile.
// B pre-rounded tf32 (weights). A converted in-register iff CVTA.
// CTA tile 128x128, BK=32, 256 thr (8 warps, warp tile 64x32).
// epi 0: +bias (fp32); epi 1: elu1 rounded; epi 2: N-split C(elu1)/C2(raw).
// ============================================================================
#define APITCH 36
#define BPITCH 136
#define NSTAGE 3
#define ST_AW (128*APITCH)
#define ST_BW (32*BPITCH)
#define G_SMEM_BYTES (NSTAGE*(ST_AW + ST_BW)*4)   // 107520

template<bool CVTA>
__device__ __forceinline__ void gemm_core(
    const float* __restrict__ A, const float* __restrict__ B,
    float* __restrict__ C, float* __restrict__ C2,
    const float* __restrict__ bias, int N, int K, int epi,
    int row0, int col0)
{
    extern __shared__ uint32_t dsm[];
    uint32_t* As = dsm;
    uint32_t* Bs = dsm + NSTAGE * ST_AW;
    const uint32_t sbA = smem_u32(As);
    const uint32_t sbB = smem_u32(Bs);

    const int tid  = threadIdx.x;
    const int wid  = tid >> 5;
    const int lane = tid & 31;
    const int wm   = (wid & 1) * 64;
    const int wn   = (wid >> 1) * 32;
    const int lr = lane >> 2;
    const int lc = lane & 3;

    float acc[4][4][4];
    #pragma unroll
    for (int i = 0; i < 4; i++)
        #pragma unroll
        for (int j = 0; j < 4; j++)
            #pragma unroll
            for (int r = 0; r < 4; r++) acc[i][j][r] = 0.f;

    auto issue = [&](int kt, int stage) {
        const int k0 = kt * 32;
        const uint32_t aB = sbA + (uint32_t)stage * ST_AW * 4;
        const uint32_t bB = sbB + (uint32_t)stage * ST_BW * 4;
        #pragma unroll
        for (int j = 0; j < 4; j++) {
            int idx = tid + 256 * j;
            int r = idx >> 3, c4 = (idx & 7) * 4;
            cp16(aB + (uint32_t)(r * APITCH + c4) * 4,
                 &A[(size_t)(row0 + r) * K + k0 + c4]);
        }
        #pragma unroll
        for (int j = 0; j < 4; j++) {
            int idx = tid + 256 * j;
            int r = idx >> 5, c4 = (idx & 31) * 4;
            cp16(bB + (uint32_t)(r * BPITCH + c4) * 4,
                 &B[(size_t)(k0 + r) * N + col0 + c4]);
        }
        CP_COMMIT();
    };

    const int ntiles = K / 32;
    issue(0, 0);
    issue(1, 1);

    int stage = 0;
    for (int kt = 0; kt < ntiles; kt++) {
        if (kt + 1 < ntiles) {
            asm volatile("cp.async.wait_group 1;");
        } else {
            asm volatile("cp.async.wait_group 0;");
        }
        __syncthreads();

        if (kt + 2 < ntiles) {
            int s2 = stage + 2; if (s2 >= NSTAGE) s2 -= NSTAGE;
            issue(kt + 2, s2);
        }

        const uint32_t* Asn = As + stage * ST_AW;
        const uint32_t* Bsn = Bs + stage * ST_BW;

        #pragma unroll
        for (int s = 0; s < 4; s++) {
            const int kk = s * 8;
            uint32_t af[4][4];
            #pragma unroll
            for (int mt = 0; mt < 4; mt++) {
                const uint32_t* ap = &Asn[(wm + mt * 16 + lr) * APITCH + kk + lc];
                if (CVTA) {
                    af[mt][0] = cvt_bits(ap[0]);
                    af[mt][1] = cvt_bits(ap[8 * APITCH]);
                    af[mt][2] = cvt_bits(ap[4]);
                    af[mt][3] = cvt_bits(ap[8 * APITCH + 4]);
                } else {
                    af[mt][0] = ap[0];
                    af[mt][1] = ap[8 * APITCH];
                    af[mt][2] = ap[4];
                    af[mt][3] = ap[8 * APITCH + 4];
                }
            }
            uint32_t bf[4][2];
            #pragma unroll
            for (int nt = 0; nt < 4; nt++) {
                const uint32_t* bp = &Bsn[(kk + lc) * BPITCH + wn + nt * 8 + lr];
                bf[nt][0] = bp[0];
                bf[nt][1] = bp[4 * BPITCH];
            }
            #pragma unroll
            for (int mt = 0; mt < 4; mt++)
                #pragma unroll
                for (int nt = 0; nt < 4; nt++)
                    mma_tf32(acc[mt][nt], af[mt][0], af[mt][1], af[mt][2],
                             af[mt][3], bf[nt][0], bf[nt][1]);
        }

        if (++stage >= NSTAGE) stage = 0;
    }

    // ---- epilogue (epi uniform per CTA) ----
    const int half = N >> 1;
    #pragma unroll
    for (int mt = 0; mt < 4; mt++) {
        #pragma unroll
        for (int nt = 0; nt < 4; nt++) {
            const int col = col0 + wn + nt * 8 + lc * 2;
            #pragma unroll
            for (int hh = 0; hh < 2; hh++) {
                const int row = row0 + wm + mt * 16 + lr + hh * 8;
                float v0 = acc[mt][nt][hh * 2 + 0];
                float v1 = acc[mt][nt][hh * 2 + 1];
                float2 o;
                if (epi == 0) {
                    o.x = v0 + bias[col]; o.y = v1 + bias[col + 1];
                    *reinterpret_cast<float2*>(&C[(size_t)row * N + col]) = o;
                } else if (epi == 1) {
                    o.x = round_tf32(elu1(v0)); o.y = round_tf32(elu1(v1));
                    *reinterpret_cast<float2*>(&C[(size_t)row * N + col]) = o;
                } else {
                    if (col < half) {
                        o.x = round_tf32(elu1(v0)); o.y = round_tf32(elu1(v1));
                        *reinterpret_cast<float2*>(&C[(size_t)row * half + col]) = o;
                    } else {
                        o.x = round_tf32(v0); o.y = round_tf32(v1);
                        *reinterpret_cast<float2*>(&C2[(size_t)row * half + (col - half)]) = o;
                    }
                }
            }
        }
    }
}

// ---- merged q-proj + kv-proj launch: grid (9, 256). x<3 -> G1, else G2 ----
__global__ __launch_bounds__(256, 2)
void gemm12_kernel(const float* __restrict__ xq, const float* __restrict__ xkv)
{
    const int bx = blockIdx.x;
    const int row0 = blockIdx.y * 128;
    if (bx < 3) {
        gemm_core<true>(xq, g_wq, g_q, nullptr, nullptr,
                        INNER, DIM, 1, row0, bx * 128);
    } else {
        gemm_core<true>(xkv, g_wkv, g_k, g_v, nullptr,
                        2 * INNER, DIM, 2, row0, (bx - 3) * 128);
    }
}

// ---- output GEMM: attn (pre-rounded) @ Wout + bias ----
__global__ __launch_bounds__(256, 2)
void gemm5_kernel(const float* __restrict__ bias, float* __restrict__ out)
{
    gemm_core<false>(g_attn, g_wout, out, nullptr, bias,
                     INNER, DIM, 0, blockIdx.y * 128, blockIdx.x * 128);
}

// ---------------------------------------------------------------------------
// kv via tf32 mma:  kv[d][m] = sum_n k[n][d] * v[n][m];  ksum[d] = sum_n k[n][d]
// ---------------------------------------------------------------------------
#define CHUNK 256
#define KTP 36
#define VSP 72
__global__ __launch_bounds__(256)
void kv_mma_kernel()
{
    __shared__ uint32_t Kt[64 * KTP];   // [d][n] tf32
    __shared__ uint32_t Vs[32 * VSP];   // [n][m] tf32
    __shared__ float red[16][64];

    const int bh = blockIdx.x;
    const int b = bh / HEADS, h = bh % HEADS;
    const int n0 = blockIdx.y * CHUNK;

    const int tid  = threadIdx.x;
    const int wid  = tid >> 5;
    const int lane = tid & 31;
    const int wm   = (wid & 1) * 32;
    const int wn   = (wid >> 1) * 16;
    const int lr = lane >> 2;
    const int lc = lane & 3;

    const float* kbase = g_k + ((size_t)(b * NSEQ + n0)) * INNER + h * DHEAD;
    const float* vbase = g_v + ((size_t)(b * NSEQ + n0)) * INNER + h * DHEAD;

    float acc[2][2][4];
    #pragma unroll
    for (int i = 0; i < 2; i++)
        #pragma unroll
        for (int j = 0; j < 2; j++)
            #pragma unroll
            for (int r = 0; r < 4; r++) acc[i][j][r] = 0.f;
    float sk[4] = {0.f, 0.f, 0.f, 0.f};

    for (int sub = 0; sub < CHUNK / 32; sub++) {
        const int nn = sub * 32;
        #pragma unroll
        for (int it = 0; it < 2; it++) {
            int idx = tid + it * 256;
            int n = idx >> 4, c4 = (idx & 15) * 4;
            float4 kw = *reinterpret_cast<const float4*>(
                &kbase[(size_t)(nn + n) * INNER + c4]);
            Kt[(c4 + 0) * KTP + n] = __float_as_uint(kw.x);
            Kt[(c4 + 1) * KTP + n] = __float_as_uint(kw.y);
            Kt[(c4 + 2) * KTP + n] = __float_as_uint(kw.z);
            Kt[(c4 + 3) * KTP + n] = __float_as_uint(kw.w);
            sk[0] += kw.x; sk[1] += kw.y; sk[2] += kw.z; sk[3] += kw.w;
            float4 vw = *reinterpret_cast<const float4*>(
                &vbase[(size_t)(nn + n) * INNER + c4]);
            uint4 o;
            o.x = __float_as_uint(vw.x); o.y = __float_as_uint(vw.y);
            o.z = __float_as_uint(vw.z); o.w = __float_as_uint(vw.w);
            *reinterpret_cast<uint4*>(&Vs[n * VSP + c4]) = o;
        }
        __syncthreads();

        #pragma unroll
        for (int s = 0; s < 4; s++) {
            const int kk = s * 8;
            uint32_t af[2][4];
            #pragma unroll
            for (int mt = 0; mt < 2; mt++) {
                const uint32_t* ap = &Kt[(wm + mt * 16 + lr) * KTP + kk + lc];
                af[mt][0] = ap[0];
                af[mt][1] = ap[8 * KTP];
                af[mt][2] = ap[4];
                af[mt][3] = ap[8 * KTP + 4];
            }
            uint32_t bf[2][2];
            #pragma unroll
            for (int nt = 0; nt < 2; nt++) {
                const uint32_t* bp = &Vs[(kk + lc) * VSP + wn + nt * 8 + lr];
                bf[nt][0] = bp[0];
                bf[nt][1] = bp[4 * VSP];
            }
            #pragma unroll
            for (int mt = 0; mt < 2; mt++)
                #pragma unroll
                for (int nt = 0; nt < 2; nt++)
                    mma_tf32(acc[mt][nt], af[mt][0], af[mt][1], af[mt][2],
                             af[mt][3], bf[nt][0], bf[nt][1]);
        }
        __syncthreads();
    }

    // ---- ksum reduction ----
    {
        const int c4 = (tid & 15) * 4;
        const int grp = tid >> 4;
        #pragma unroll
        for (int j = 0; j < 4; j++) red[grp][c4 + j] = sk[j];
        __syncthreads();
        if (tid < 64) {
            float s = 0.f;
            #pragma unroll
            for (int r = 0; r < 16; r++) s += red[r][tid];
            atomicAdd(&g_ksum[bh * DHEAD + tid], s);
        }
    }

    // ---- kv accumulation ----
    float* kvp = g_kv + (size_t)bh * DHEAD * DHEAD;
    #pragma unroll
    for (int mt = 0; mt < 2; mt++) {
        #pragma unroll
        for (int nt = 0; nt < 2; nt++) {
            const int col = wn + nt * 8 + lc * 2;
            #pragma unroll
            for (int hh = 0; hh < 2; hh++) {
                const int row = wm + mt * 16 + lr + hh * 8;
                atomicAdd(&kvp[row * DHEAD + col],     acc[mt][nt][hh * 2 + 0]);
                atomicAdd(&kvp[row * DHEAD + col + 1], acc[mt][nt][hh * 2 + 1]);
            }
        }
    }
}

// ---------------------------------------------------------------------------
// attn via tf32 mma: attn[n,m] = (q[n,:] @ kv[:,m]) * 1/(q[n,:].ksum + 1e-6)
// ---------------------------------------------------------------------------
#define AQP 68
#define A_QS  0
#define A_KVS 34816
#define A_KS  52224
#define A_ZR  52480
#define A_SMEM 52992

__global__ __launch_bounds__(256)
void attn_mma_kernel()
{
    extern __shared__ char smem[];
    uint32_t* qs  = reinterpret_cast<uint32_t*>(smem + A_QS);
    uint32_t* kvs = reinterpret_cast<uint32_t*>(smem + A_KVS);
    float*    ks  = reinterpret_cast<float*>(smem + A_KS);
    float*    zr  = reinterpret_cast<float*>(smem + A_ZR);

    const int bh = blockIdx.x;
    const int b = bh / HEADS, h = bh % HEADS;
    const int n0 = blockIdx.y * 128;

    const int tid  = threadIdx.x;
    const int wid  = tid >> 5;
    const int lane = tid & 31;
    const int wm   = (wid & 3) * 32;
    const int wn   = (wid >> 2) * 32;
    const int lr = lane >> 2;
    const int lc = lane & 3;

    const float* qptr = g_q + ((size_t)(b * NSEQ + n0)) * INNER + h * DHEAD;
    #pragma unroll
    for (int j = 0; j < 8; j++) {
        int idx = tid + 256 * j;
        int r = idx >> 4, c4 = (idx & 15) * 4;
        float4 v = *reinterpret_cast<const float4*>(&qptr[(size_t)r * INNER + c4]);
        uint32_t* d = &qs[r * AQP + c4];
        d[0] = __float_as_uint(v.x); d[1] = __float_as_uint(v.y);
        d[2] = __float_as_uint(v.z); d[3] = __float_as_uint(v.w);
    }
    #pragma unroll
    for (int j = 0; j < 4; j++) {
        int idx = tid + 256 * j;
        int d = idx >> 4, m4 = (idx & 15) * 4;
        float4 v = *reinterpret_cast<const float4*>(&g_kv[(size_t)bh * 4096 + d * 64 + m4]);
        kvs[(m4 + 0) * AQP + d] = f2tf32(v.x);
        kvs[(m4 + 1) * AQP + d] = f2tf32(v.y);
        kvs[(m4 + 2) * AQP + d] = f2tf32(v.z);
        kvs[(m4 + 3) * AQP + d] = f2tf32(v.w);
    }
    if (tid < 64) ks[tid] = g_ksum[bh * 64 + tid];
    __syncthreads();

    if (tid < 128) {
        float s = 0.f;
        #pragma unroll
        for (int dd = 0; dd < 64; dd++)
            s += __uint_as_float(qs[tid * AQP + dd]) * ks[dd];
        zr[tid] = 1.f / (s + 1e-6f);
    }
    __syncthreads();

    float acc[2][4][4];
    #pragma unroll
    for (int i = 0; i < 2; i++)
        #pragma unroll
        for (int j = 0; j < 4; j++)
            #pragma unroll
            for (int r = 0; r < 4; r++) acc[i][j][r] = 0.f;

    #pragma unroll
    for (int s = 0; s < 8; s++) {
        const int kk = s * 8;
        uint32_t af[2][4];
        #pragma unroll
        for (int mt = 0; mt < 2; mt++) {
            const uint32_t* ap = &qs[(wm + mt * 16 + lr) * AQP + kk + lc];
            af[mt][0] = ap[0];
            af[mt][1] = ap[8 * AQP];
            af[mt][2] = ap[4];
            af[mt][3] = ap[8 * AQP + 4];
        }
        uint32_t bf[4][2];
        #pragma unroll
        for (int nt = 0; nt < 4; nt++) {
            const uint32_t* bp = &kvs[(wn + nt * 8 + lr) * AQP + kk + lc];
            bf[nt][0] = bp[0];
            bf[nt][1] = bp[4];
        }
        #pragma unroll
        for (int mt = 0; mt < 2; mt++)
            #pragma unroll
            for (int nt = 0; nt < 4; nt++)
                mma_tf32(acc[mt][nt], af[mt][0], af[mt][1], af[mt][2],
                         af[mt][3], bf[nt][0], bf[nt][1]);
    }

    #pragma unroll
    for (int mt = 0; mt < 2; mt++) {
        #pragma unroll
        for (int nt = 0; nt < 4; nt++) {
            const int col = wn + nt * 8 + lc * 2;
            #pragma unroll
            for (int hh = 0; hh < 2; hh++) {
                const int row = wm + mt * 16 + lr + hh * 8;
                const float z = zr[row];
                float2 o;
                o.x = round_tf32(acc[mt][nt][hh * 2 + 0] * z);
                o.y = round_tf32(acc[mt][nt][hh * 2 + 1] * z);
                *reinterpret_cast<float2*>(
                    &g_attn[((size_t)(b * NSEQ + n0 + row)) * INNER + h * DHEAD + col]) = o;
            }
        }
    }
}

// ---------------------------------------------------------------------------
// Launch order: CVTW+Z, G12 (merged), KV, AT (profiled 4th slot), G5
// ---------------------------------------------------------------------------
extern "C" void kernel_launch(void* const* d_in, const int* in_sizes, int n_in,
                              void* d_out, int out_size)
{
    const float* x_q  = (const float*)d_in[0];
    const float* x_kv = (const float*)d_in[1];
    const float* Wq   = (const float*)d_in[2];
    const float* Wkv  = (const float*)d_in[3];
    const float* Wout = (const float*)d_in[4];
    const float* bout = (const float*)d_in[5];
    float* out = (float*)d_out;

    cudaFuncSetAttribute((const void*)gemm12_kernel, cudaFuncAttributeMaxDynamicSharedMemorySize, G_SMEM_BYTES);
    cudaFuncSetAttribute((const void*)gemm5_kernel,  cudaFuncAttributeMaxDynamicSharedMemorySize, G_SMEM_BYTES);
    cudaFuncSetAttribute((const void*)attn_mma_kernel, cudaFuncAttributeMaxDynamicSharedMemorySize, A_SMEM);

    dim3 blk(256);

    // 1) weights -> tf32 + zero accumulators (merged)
    cvt_w_zero_kernel<<<576, blk>>>(Wq, Wkv, Wout);

    // 2) merged projections: q = elu1(x_q@Wq); k/v = split(x_kv@Wkv)
    gemm12_kernel<<<dim3(9, ROWS/128), blk, G_SMEM_BYTES>>>(x_q, x_kv);

    // 3) kv = k^T v; ksum = sum_n k
    kv_mma_kernel<<<dim3(BATCH*HEADS, NSEQ/CHUNK), blk>>>();

    // 4) attn = (q @ kv) * z      [profiled slot]
    attn_mma_kernel<<<dim3(BATCH*HEADS, NSEQ/128), blk, A_SMEM>>>();

    // 5) out = attn @ Wout + bout
    gemm5_kernel<<<dim3(INNER/128, ROWS/128), blk, G_SMEM_BYTES>>>(bout, out);
}

// round 12
// speedup vs baseline: 1.7263x; 1.0297x over previous
#include <cuda_runtime.h>
#include <cstdint>

#define BATCH 8
#define NSEQ  4096
#define DIM   384
#define HEADS 6
#define DHEAD 64
#define INNER 384
#define ROWS  (BATCH*NSEQ)   // 32768

// ---- scratch (device globals: no allocation allowed) ----
__device__ float g_wq  [ DIM*INNER ];          // tf32-rounded weights
__device__ float g_wkv [ DIM*2*INNER ];
__device__ float g_wout[ INNER*DIM ];
__device__ float g_q   [ (size_t)ROWS*INNER ];
__device__ float g_k   [ (size_t)ROWS*INNER ];
__device__ float g_v   [ (size_t)ROWS*INNER ];
__device__ float g_attn[ (size_t)ROWS*INNER ];
__device__ float g_kv  [ BATCH*HEADS*DHEAD*DHEAD ];
__device__ float g_ksum[ BATCH*HEADS*DHEAD ];

__device__ __forceinline__ float elu1(float x) {
    return x > 0.f ? x + 1.f : __expf(x);
}

__device__ __forceinline__ uint32_t f2tf32(float x) {
    uint32_t u;
    asm("cvt.rna.tf32.f32 %0, %1;" : "=r"(u) : "f"(x));
    return u;
}
__device__ __forceinline__ float round_tf32(float x) {
    return __uint_as_float(f2tf32(x));
}
__device__ __forceinline__ uint32_t cvt_bits(uint32_t raw) {
    return f2tf32(__uint_as_float(raw));
}

__device__ __forceinline__ uint32_t smem_u32(const void* p) {
    uint32_t a;
    asm("{ .reg .u64 t; cvta.to.shared.u64 t, %1; cvt.u32.u64 %0, t; }"
        : "=r"(a) : "l"(p));
    return a;
}
__device__ __forceinline__ void cp16(uint32_t dst, const void* src) {
    asm volatile("cp.async.cg.shared.global [%0], [%1], 16;"
                 :: "r"(dst), "l"(src));
}
#define CP_COMMIT() asm volatile("cp.async.commit_group;")

__device__ __forceinline__ void mma_tf32(float c[4], uint32_t a0, uint32_t a1,
                                         uint32_t a2, uint32_t a3,
                                         uint32_t b0, uint32_t b1) {
    asm volatile(
        "mma.sync.aligned.m16n8k8.row.col.f32.tf32.tf32.f32 "
        "{%0,%1,%2,%3}, {%4,%5,%6,%7}, {%8,%9}, {%0,%1,%2,%3};"
        : "+f"(c[0]), "+f"(c[1]), "+f"(c[2]), "+f"(c[3])
        : "r"(a0), "r"(a1), "r"(a2), "r"(a3), "r"(b0), "r"(b1));
}

// ---------------------------------------------------------------------------
// One-time: round weights to tf32 AND zero kv/ksum accumulators (merged).
// ---------------------------------------------------------------------------
__global__ void cvt_w_zero_kernel(const float* __restrict__ wq,
                                  const float* __restrict__ wkv,
                                  const float* __restrict__ wout)
{
    const int n1 = DIM*INNER/4, n2 = DIM*2*INNER/4, n3 = INNER*DIM/4;
    const int nw = n1 + n2 + n3;
    const int nz = BATCH*HEADS*DHEAD*DHEAD/4;
    const int nz2 = BATCH*HEADS*DHEAD/4;
    const float4 z4 = make_float4(0.f, 0.f, 0.f, 0.f);
    for (int i = blockIdx.x * blockDim.x + threadIdx.x; i < nw + nz + nz2;
         i += gridDim.x * blockDim.x) {
        if (i < nw) {
            const float4* s; float4* d; int j;
            if (i < n1)           { s = (const float4*)wq;   d = (float4*)g_wq;   j = i; }
            else if (i < n1 + n2) { s = (const float4*)wkv;  d = (float4*)g_wkv;  j = i - n1; }
            else                  { s = (const float4*)wout; d = (float4*)g_wout; j = i - n1 - n2; }
            float4 v = s[j];
            v.x = round_tf32(v.x); v.y = round_tf32(v.y);
            v.z = round_tf32(v.z); v.w = round_tf32(v.w);
            d[j] = v;
        } else if (i < nw + nz) {
            reinterpret_cast<float4*>(g_kv)[i - nw] = z4;
        } else {
            reinterpret_cast<float4*>(g_ksum)[i - nw - nz] = z4;
        }
    }
}

// ============================================================================
// tf32 mma.sync GEMM core (UNCHANGED from 348us baseline).
// ============================================================================
#define APITCH 36
#define BPITCH 136
#define NSTAGE 3
#define ST_AW (128*APITCH)
#define ST_BW (32*BPITCH)
#define G_SMEM_BYTES (NSTAGE*(ST_AW + ST_BW)*4)   // 107520

template<bool CVTA>
__device__ __forceinline__ void gemm_core(
    const float* __restrict__ A, const float* __restrict__ B,
    float* __restrict__ C, float* __restrict__ C2,
    const float* __restrict__ bias, int N, int K, int epi,
    int row0, int col0)
{
    extern __shared__ uint32_t dsm[];
    uint32_t* As = dsm;
    uint32_t* Bs = dsm + NSTAGE * ST_AW;
    const uint32_t sbA = smem_u32(As);
    const uint32_t sbB = smem_u32(Bs);

    const int tid  = threadIdx.x;
    const int wid  = tid >> 5;
    const int lane = tid & 31;
    const int wm   = (wid & 1) * 64;
    const int wn   = (wid >> 1) * 32;
    const int lr = lane >> 2;
    const int lc = lane & 3;

    float acc[4][4][4];
    #pragma unroll
    for (int i = 0; i < 4; i++)
        #pragma unroll
        for (int j = 0; j < 4; j++)
            #pragma unroll
            for (int r = 0; r < 4; r++) acc[i][j][r] = 0.f;

    auto issue = [&](int kt, int stage) {
        const int k0 = kt * 32;
        const uint32_t aB = sbA + (uint32_t)stage * ST_AW * 4;
        const uint32_t bB = sbB + (uint32_t)stage * ST_BW * 4;
        #pragma unroll
        for (int j = 0; j < 4; j++) {
            int idx = tid + 256 * j;
            int r = idx >> 3, c4 = (idx & 7) * 4;
            cp16(aB + (uint32_t)(r * APITCH + c4) * 4,
                 &A[(size_t)(row0 + r) * K + k0 + c4]);
        }
        #pragma unroll
        for (int j = 0; j < 4; j++) {
            int idx = tid + 256 * j;
            int r = idx >> 5, c4 = (idx & 31) * 4;
            cp16(bB + (uint32_t)(r * BPITCH + c4) * 4,
                 &B[(size_t)(k0 + r) * N + col0 + c4]);
        }
        CP_COMMIT();
    };

    const int ntiles = K / 32;
    issue(0, 0);
    issue(1, 1);

    int stage = 0;
    for (int kt = 0; kt < ntiles; kt++) {
        if (kt + 1 < ntiles) {
            asm volatile("cp.async.wait_group 1;");
        } else {
            asm volatile("cp.async.wait_group 0;");
        }
        __syncthreads();

        if (kt + 2 < ntiles) {
            int s2 = stage + 2; if (s2 >= NSTAGE) s2 -= NSTAGE;
            issue(kt + 2, s2);
        }

        const uint32_t* Asn = As + stage * ST_AW;
        const uint32_t* Bsn = Bs + stage * ST_BW;

        #pragma unroll
        for (int s = 0; s < 4; s++) {
            const int kk = s * 8;
            uint32_t af[4][4];
            #pragma unroll
            for (int mt = 0; mt < 4; mt++) {
                const uint32_t* ap = &Asn[(wm + mt * 16 + lr) * APITCH + kk + lc];
                if (CVTA) {
                    af[mt][0] = cvt_bits(ap[0]);
                    af[mt][1] = cvt_bits(ap[8 * APITCH]);
                    af[mt][2] = cvt_bits(ap[4]);
                    af[mt][3] = cvt_bits(ap[8 * APITCH + 4]);
                } else {
                    af[mt][0] = ap[0];
                    af[mt][1] = ap[8 * APITCH];
                    af[mt][2] = ap[4];
                    af[mt][3] = ap[8 * APITCH + 4];
                }
            }
            uint32_t bf[4][2];
            #pragma unroll
            for (int nt = 0; nt < 4; nt++) {
                const uint32_t* bp = &Bsn[(kk + lc) * BPITCH + wn + nt * 8 + lr];
                bf[nt][0] = bp[0];
                bf[nt][1] = bp[4 * BPITCH];
            }
            #pragma unroll
            for (int mt = 0; mt < 4; mt++)
                #pragma unroll
                for (int nt = 0; nt < 4; nt++)
                    mma_tf32(acc[mt][nt], af[mt][0], af[mt][1], af[mt][2],
                             af[mt][3], bf[nt][0], bf[nt][1]);
        }

        if (++stage >= NSTAGE) stage = 0;
    }

    const int half = N >> 1;
    #pragma unroll
    for (int mt = 0; mt < 4; mt++) {
        #pragma unroll
        for (int nt = 0; nt < 4; nt++) {
            const int col = col0 + wn + nt * 8 + lc * 2;
            #pragma unroll
            for (int hh = 0; hh < 2; hh++) {
                const int row = row0 + wm + mt * 16 + lr + hh * 8;
                float v0 = acc[mt][nt][hh * 2 + 0];
                float v1 = acc[mt][nt][hh * 2 + 1];
                float2 o;
                if (epi == 0) {
                    o.x = v0 + bias[col]; o.y = v1 + bias[col + 1];
                    *reinterpret_cast<float2*>(&C[(size_t)row * N + col]) = o;
                } else if (epi == 1) {
                    o.x = round_tf32(elu1(v0)); o.y = round_tf32(elu1(v1));
                    *reinterpret_cast<float2*>(&C[(size_t)row * N + col]) = o;
                } else {
                    if (col < half) {
                        o.x = round_tf32(elu1(v0)); o.y = round_tf32(elu1(v1));
                        *reinterpret_cast<float2*>(&C[(size_t)row * half + col]) = o;
                    } else {
                        o.x = round_tf32(v0); o.y = round_tf32(v1);
                        *reinterpret_cast<float2*>(&C2[(size_t)row * half + (col - half)]) = o;
                    }
                }
            }
        }
    }
}

__global__ __launch_bounds__(256, 2)
void gemm12_kernel(const float* __restrict__ xq, const float* __restrict__ xkv)
{
    const int bx = blockIdx.x;
    const int row0 = blockIdx.y * 128;
    if (bx < 3) {
        gemm_core<true>(xq, g_wq, g_q, nullptr, nullptr,
                        INNER, DIM, 1, row0, bx * 128);
    } else {
        gemm_core<true>(xkv, g_wkv, g_k, g_v, nullptr,
                        2 * INNER, DIM, 2, row0, (bx - 3) * 128);
    }
}

__global__ __launch_bounds__(256, 2)
void gemm5_kernel(const float* __restrict__ bias, float* __restrict__ out)
{
    gemm_core<false>(g_attn, g_wout, out, nullptr, bias,
                     INNER, DIM, 0, blockIdx.y * 128, blockIdx.x * 128);
}

// ---------------------------------------------------------------------------
// kv via tf32 mma:  kv[d][m] = sum_n k[n][d]*v[n][m];  ksum[d] = sum_n k[n][d]
// NEW: k stored NATURALLY [n][d] pitch 72 (STS.128, ~2-way) and read directly
// as the A-fragment (bank-exact: (8*(kk+lc)+lr)%32 all distinct). No transpose.
// ---------------------------------------------------------------------------
#define CHUNK 256
#define KVP 72
__global__ __launch_bounds__(256)
void kv_mma_kernel()
{
    __shared__ uint32_t Kn[32 * KVP];   // k natural [n][d], tf32 bits
    __shared__ uint32_t Vs[32 * KVP];   // v natural [n][m], tf32 bits
    __shared__ float red[16][64];

    const int bh = blockIdx.x;
    const int b = bh / HEADS, h = bh % HEADS;
    const int n0 = blockIdx.y * CHUNK;

    const int tid  = threadIdx.x;
    const int wid  = tid >> 5;
    const int lane = tid & 31;
    const int wm   = (wid & 1) * 32;    // d offset
    const int wn   = (wid >> 1) * 16;   // m offset
    const int lr = lane >> 2;
    const int lc = lane & 3;

    const float* kbase = g_k + ((size_t)(b * NSEQ + n0)) * INNER + h * DHEAD;
    const float* vbase = g_v + ((size_t)(b * NSEQ + n0)) * INNER + h * DHEAD;

    float acc[2][2][4];
    #pragma unroll
    for (int i = 0; i < 2; i++)
        #pragma unroll
        for (int j = 0; j < 2; j++)
            #pragma unroll
            for (int r = 0; r < 4; r++) acc[i][j][r] = 0.f;
    float sk[4] = {0.f, 0.f, 0.f, 0.f};

    for (int sub = 0; sub < CHUNK / 32; sub++) {
        const int nn = sub * 32;
        #pragma unroll
        for (int it = 0; it < 2; it++) {
            int idx = tid + it * 256;
            int n = idx >> 4, c4 = (idx & 15) * 4;
            float4 kw = *reinterpret_cast<const float4*>(
                &kbase[(size_t)(nn + n) * INNER + c4]);
            uint4 ko;
            ko.x = __float_as_uint(kw.x); ko.y = __float_as_uint(kw.y);
            ko.z = __float_as_uint(kw.z); ko.w = __float_as_uint(kw.w);
            *reinterpret_cast<uint4*>(&Kn[n * KVP + c4]) = ko;
            sk[0] += kw.x; sk[1] += kw.y; sk[2] += kw.z; sk[3] += kw.w;
            float4 vw = *reinterpret_cast<const float4*>(
                &vbase[(size_t)(nn + n) * INNER + c4]);
            uint4 vo;
            vo.x = __float_as_uint(vw.x); vo.y = __float_as_uint(vw.y);
            vo.z = __float_as_uint(vw.z); vo.w = __float_as_uint(vw.w);
            *reinterpret_cast<uint4*>(&Vs[n * KVP + c4]) = vo;
        }
        __syncthreads();

        #pragma unroll
        for (int s = 0; s < 4; s++) {
            const int kk = s * 8;   // k-dim = n index within subtile
            uint32_t af[2][4];
            #pragma unroll
            for (int mt = 0; mt < 2; mt++) {
                const int drow = wm + mt * 16 + lr;
                const uint32_t* ap = &Kn[(kk + lc) * KVP + drow];
                af[mt][0] = ap[0];              // (d=drow,   n=kk+lc)
                af[mt][1] = ap[8];              // (d=drow+8, n=kk+lc)
                af[mt][2] = ap[4 * KVP];        // (d=drow,   n=kk+lc+4)
                af[mt][3] = ap[4 * KVP + 8];    // (d=drow+8, n=kk+lc+4)
            }
            uint32_t bf[2][2];
            #pragma unroll
            for (int nt = 0; nt < 2; nt++) {
                const uint32_t* bp = &Vs[(kk + lc) * KVP + wn + nt * 8 + lr];
                bf[nt][0] = bp[0];
                bf[nt][1] = bp[4 * KVP];
            }
            #pragma unroll
            for (int mt = 0; mt < 2; mt++)
                #pragma unroll
                for (int nt = 0; nt < 2; nt++)
                    mma_tf32(acc[mt][nt], af[mt][0], af[mt][1], af[mt][2],
                             af[mt][3], bf[nt][0], bf[nt][1]);
        }
        __syncthreads();
    }

    // ---- ksum reduction ----
    {
        const int c4 = (tid & 15) * 4;
        const int grp = tid >> 4;
        #pragma unroll
        for (int j = 0; j < 4; j++) red[grp][c4 + j] = sk[j];
        __syncthreads();
        if (tid < 64) {
            float s = 0.f;
            #pragma unroll
            for (int r = 0; r < 16; r++) s += red[r][tid];
            atomicAdd(&g_ksum[bh * DHEAD + tid], s);
        }
    }

    // ---- kv accumulation ----
    float* kvp = g_kv + (size_t)bh * DHEAD * DHEAD;
    #pragma unroll
    for (int mt = 0; mt < 2; mt++) {
        #pragma unroll
        for (int nt = 0; nt < 2; nt++) {
            const int col = wn + nt * 8 + lc * 2;
            #pragma unroll
            for (int hh = 0; hh < 2; hh++) {
                const int row = wm + mt * 16 + lr + hh * 8;
                atomicAdd(&kvp[row * DHEAD + col],     acc[mt][nt][hh * 2 + 0]);
                atomicAdd(&kvp[row * DHEAD + col + 1], acc[mt][nt][hh * 2 + 1]);
            }
        }
    }
}

// ---------------------------------------------------------------------------
// attn via tf32 mma: attn[n,m] = (q[n,:] @ kv[:,m]) * 1/(q[n,:].ksum + 1e-6)
// NEW: 64-row blocks (smem 36KB -> 5 CTAs/SM), kv stored natural [d][m]
// pitch 72 (= GEMM B-layout: conflict-free frags, STS.128 stores).
// ---------------------------------------------------------------------------
#define AQP 68
__global__ __launch_bounds__(256, 5)
void attn_mma_kernel()
{
    __shared__ uint32_t qs [64 * AQP];   // q rows [n][d] tf32
    __shared__ uint32_t kvs[64 * KVP];   // kv natural [d][m] tf32
    __shared__ float ks[64];
    __shared__ float zr[64];

    const int bh = blockIdx.x;
    const int b = bh / HEADS, h = bh % HEADS;
    const int n0 = blockIdx.y * 64;

    const int tid  = threadIdx.x;
    const int wid  = tid >> 5;
    const int lane = tid & 31;
    const int wm   = (wid & 1) * 32;    // row offset (q rows)
    const int wn   = (wid >> 1) * 16;   // col offset (m)
    const int lr = lane >> 2;
    const int lc = lane & 3;

    // q tile: 64 x 64 from g_q (pre-rounded tf32)
    const float* qptr = g_q + ((size_t)(b * NSEQ + n0)) * INNER + h * DHEAD;
    #pragma unroll
    for (int j = 0; j < 4; j++) {
        int idx = tid + 256 * j;
        int r = idx >> 4, c4 = (idx & 15) * 4;
        float4 v = *reinterpret_cast<const float4*>(&qptr[(size_t)r * INNER + c4]);
        uint4 o;
        o.x = __float_as_uint(v.x); o.y = __float_as_uint(v.y);
        o.z = __float_as_uint(v.z); o.w = __float_as_uint(v.w);
        *reinterpret_cast<uint4*>(&qs[r * AQP + c4]) = o;
    }
    // kv tile: 64 x 64, natural [d][m], convert (fp32 atomic sums) -> tf32
    #pragma unroll
    for (int j = 0; j < 4; j++) {
        int idx = tid + 256 * j;
        int d = idx >> 4, m4 = (idx & 15) * 4;
        float4 v = *reinterpret_cast<const float4*>(&g_kv[(size_t)bh * 4096 + d * 64 + m4]);
        uint4 o;
        o.x = f2tf32(v.x); o.y = f2tf32(v.y);
        o.z = f2tf32(v.z); o.w = f2tf32(v.w);
        *reinterpret_cast<uint4*>(&kvs[d * KVP + m4]) = o;
    }
    if (tid < 64) ks[tid] = g_ksum[bh * 64 + tid];
    __syncthreads();

    if (tid < 64) {
        float s = 0.f;
        #pragma unroll
        for (int dd = 0; dd < 64; dd++)
            s += __uint_as_float(qs[tid * AQP + dd]) * ks[dd];
        zr[tid] = 1.f / (s + 1e-6f);
    }
    __syncthreads();

    float acc[2][2][4];
    #pragma unroll
    for (int i = 0; i < 2; i++)
        #pragma unroll
        for (int j = 0; j < 2; j++)
            #pragma unroll
            for (int r = 0; r < 4; r++) acc[i][j][r] = 0.f;

    #pragma unroll
    for (int s = 0; s < 8; s++) {
        const int kk = s * 8;
        uint32_t af[2][4];
        #pragma unroll
        for (int mt = 0; mt < 2; mt++) {
            const uint32_t* ap = &qs[(wm + mt * 16 + lr) * AQP + kk + lc];
            af[mt][0] = ap[0];
            af[mt][1] = ap[8 * AQP];
            af[mt][2] = ap[4];
            af[mt][3] = ap[8 * AQP + 4];
        }
        uint32_t bf[2][2];
        #pragma unroll
        for (int nt = 0; nt < 2; nt++) {
            const uint32_t* bp = &kvs[(kk + lc) * KVP + wn + nt * 8 + lr];
            bf[nt][0] = bp[0];
            bf[nt][1] = bp[4 * KVP];
        }
        #pragma unroll
        for (int mt = 0; mt < 2; mt++)
            #pragma unroll
            for (int nt = 0; nt < 2; nt++)
                mma_tf32(acc[mt][nt], af[mt][0], af[mt][1], af[mt][2],
                         af[mt][3], bf[nt][0], bf[nt][1]);
    }

    #pragma unroll
    for (int mt = 0; mt < 2; mt++) {
        #pragma unroll
        for (int nt = 0; nt < 2; nt++) {
            const int col = wn + nt * 8 + lc * 2;
            #pragma unroll
            for (int hh = 0; hh < 2; hh++) {
                const int row = wm + mt * 16 + lr + hh * 8;
                const float z = zr[row];
                float2 o;
                o.x = round_tf32(acc[mt][nt][hh * 2 + 0] * z);
                o.y = round_tf32(acc[mt][nt][hh * 2 + 1] * z);
                *reinterpret_cast<float2*>(
                    &g_attn[((size_t)(b * NSEQ + n0 + row)) * INNER + h * DHEAD + col]) = o;
            }
        }
    }
}

// ---------------------------------------------------------------------------
// Launch order: CVTZ, G12, KV, AT (profiled 4th slot), G5
// ---------------------------------------------------------------------------
extern "C" void kernel_launch(void* const* d_in, const int* in_sizes, int n_in,
                              void* d_out, int out_size)
{
    const float* x_q  = (const float*)d_in[0];
    const float* x_kv = (const float*)d_in[1];
    const float* Wq   = (const float*)d_in[2];
    const float* Wkv  = (const float*)d_in[3];
    const float* Wout = (const float*)d_in[4];
    const float* bout = (const float*)d_in[5];
    float* out = (float*)d_out;

    cudaFuncSetAttribute((const void*)gemm12_kernel, cudaFuncAttributeMaxDynamicSharedMemorySize, G_SMEM_BYTES);
    cudaFuncSetAttribute((const void*)gemm5_kernel,  cudaFuncAttributeMaxDynamicSharedMemorySize, G_SMEM_BYTES);

    dim3 blk(256);

    // 1) weights -> tf32 + zero accumulators
    cvt_w_zero_kernel<<<576, blk>>>(Wq, Wkv, Wout);

    // 2) merged projections: q = elu1(x_q@Wq); k/v = split(x_kv@Wkv)
    gemm12_kernel<<<dim3(9, ROWS/128), blk, G_SMEM_BYTES>>>(x_q, x_kv);

    // 3) kv = k^T v; ksum = sum_n k
    kv_mma_kernel<<<dim3(BATCH*HEADS, NSEQ/CHUNK), blk>>>();

    // 4) attn = (q @ kv) * z      [profiled slot]
    attn_mma_kernel<<<dim3(BATCH*HEADS, NSEQ/64), blk>>>();

    // 5) out = attn @ Wout + bout
    gemm5_kernel<<<dim3(INNER/128, ROWS/128), blk, G_SMEM_BYTES>>>(bout, out);
}

// round 13
// speedup vs baseline: 2.0187x; 1.1694x over previous
#include <cuda_runtime.h>
#include <cuda_fp16.h>
#include <cstdint>

#define BATCH 8
#define NSEQ  4096
#define DIM   384
#define HEADS 6
#define DHEAD 64
#define INNER 384
#define ROWS  (BATCH*NSEQ)   // 32768

// ---- scratch (device globals: no allocation allowed) ----
__device__ __half g_wqt  [ (size_t)INNER*DIM ];     // Wq^T  [n][k] fp16
__device__ __half g_wkvt [ (size_t)2*INNER*DIM ];   // Wkv^T [n][k] fp16
__device__ __half g_woutt[ (size_t)DIM*INNER ];     // Wout^T[n][k] fp16
__device__ __half g_q    [ (size_t)ROWS*INNER ];
__device__ __half g_k    [ (size_t)ROWS*INNER ];
__device__ __half g_v    [ (size_t)ROWS*INNER ];
__device__ __half g_attn [ (size_t)ROWS*INNER ];
__device__ float  g_kv   [ BATCH*HEADS*DHEAD*DHEAD ];
__device__ float  g_ksum [ BATCH*HEADS*DHEAD ];

__device__ __forceinline__ float elu1(float x) {
    return x > 0.f ? x + 1.f : __expf(x);
}

__device__ __forceinline__ uint32_t f2tf32(float x) {
    uint32_t u;
    asm("cvt.rna.tf32.f32 %0, %1;" : "=r"(u) : "f"(x));
    return u;
}

__device__ __forceinline__ uint32_t smem_u32(const void* p) {
    uint32_t a;
    asm("{ .reg .u64 t; cvta.to.shared.u64 t, %1; cvt.u32.u64 %0, t; }"
        : "=r"(a) : "l"(p));
    return a;
}
__device__ __forceinline__ void cp16(uint32_t dst, const void* src) {
    asm volatile("cp.async.cg.shared.global [%0], [%1], 16;"
                 :: "r"(dst), "l"(src));
}
#define CP_COMMIT() asm volatile("cp.async.commit_group;")

__device__ __forceinline__ void mma_tf32(float c[4], uint32_t a0, uint32_t a1,
                                         uint32_t a2, uint32_t a3,
                                         uint32_t b0, uint32_t b1) {
    asm volatile(
        "mma.sync.aligned.m16n8k8.row.col.f32.tf32.tf32.f32 "
        "{%0,%1,%2,%3}, {%4,%5,%6,%7}, {%8,%9}, {%0,%1,%2,%3};"
        : "+f"(c[0]), "+f"(c[1]), "+f"(c[2]), "+f"(c[3])
        : "r"(a0), "r"(a1), "r"(a2), "r"(a3), "r"(b0), "r"(b1));
}

__device__ __forceinline__ void mma_f16(float c[4], uint32_t a0, uint32_t a1,
                                        uint32_t a2, uint32_t a3,
                                        uint32_t b0, uint32_t b1) {
    asm volatile(
        "mma.sync.aligned.m16n8k16.row.col.f32.f16.f16.f32 "
        "{%0,%1,%2,%3}, {%4,%5,%6,%7}, {%8,%9}, {%0,%1,%2,%3};"
        : "+f"(c[0]), "+f"(c[1]), "+f"(c[2]), "+f"(c[3])
        : "r"(a0), "r"(a1), "r"(a2), "r"(a3), "r"(b0), "r"(b1));
}

__device__ __forceinline__ uint32_t pack_h2(float lo, float hi) {
    __half2 h = __floats2half2_rn(lo, hi);
    return *reinterpret_cast<uint32_t*>(&h);
}

// ---------------------------------------------------------------------------
// One-time: transpose+convert weights to fp16 [n][k]; zero kv/ksum.
// ---------------------------------------------------------------------------
__global__ void cvt_w_zero_kernel(const float* __restrict__ wq,
                                  const float* __restrict__ wkv,
                                  const float* __restrict__ wout)
{
    const int n1 = DIM*INNER, n2 = DIM*2*INNER, n3 = INNER*DIM;
    const int nw = n1 + n2 + n3;
    const int nz = BATCH*HEADS*DHEAD*DHEAD/4;
    const int nz2 = BATCH*HEADS*DHEAD/4;
    const float4 z4 = make_float4(0.f, 0.f, 0.f, 0.f);
    for (int i = blockIdx.x * blockDim.x + threadIdx.x; i < nw + nz + nz2;
         i += gridDim.x * blockDim.x) {
        if (i < nw) {
            const float* s; __half* d; int j, Nn;
            if (i < n1)           { s = wq;   d = g_wqt;   j = i;           Nn = INNER; }
            else if (i < n1 + n2) { s = wkv;  d = g_wkvt;  j = i - n1;      Nn = 2*INNER; }
            else                  { s = wout; d = g_woutt; j = i - n1 - n2; Nn = DIM; }
            int k = j / Nn, n = j % Nn;     // coalesced read s[k*Nn+n]
            d[(size_t)n * DIM + k] = __float2half(s[j]);
        } else if (i < nw + nz) {
            reinterpret_cast<float4*>(g_kv)[i - nw] = z4;
        } else {
            reinterpret_cast<float4*>(g_ksum)[i - nw - nz] = z4;
        }
    }
}

// ============================================================================
// fp16 mma.sync GEMM core: cp.async 3-stage ring, ONE barrier per ktile.
// B = fp16 weights pre-transposed [n][k]. CVTA=true: A fp32 (x), converted
// via LDS.64 + cvt.f16x2 at frag load. CVTA=false: A fp16 (attn), direct.
// CTA tile 128x128, BK=32 (2 k16 steps), 256 thr (8 warps, warp tile 64x32).
// epi 0: +bias -> fp32 out; epi 1: elu1 -> fp16; epi 2: N-split -> fp16/fp16.
// ============================================================================
#define NSTAGE 3
#define APW32 36                 // A fp32 pitch (words)
#define APW16 20                 // A fp16 pitch (words; 40 halves)
#define BPW   20                 // B fp16 pitch (words; 40 halves)

template<bool CVTA>
__device__ __forceinline__ void gemm_core(
    const void* __restrict__ Av, const __half* __restrict__ Bt,
    float* __restrict__ Cf, __half* __restrict__ Ch, __half* __restrict__ C2h,
    const float* __restrict__ bias, int N, int K, int epi,
    int row0, int col0)
{
    constexpr int APW  = CVTA ? APW32 : APW16;
    constexpr int ST_AW = 128 * APW;
    constexpr int ST_BW = 128 * BPW;

    extern __shared__ uint32_t dsm[];
    uint32_t* As = dsm;
    uint32_t* Bs = dsm + NSTAGE * ST_AW;
    const uint32_t sbA = smem_u32(As);
    const uint32_t sbB = smem_u32(Bs);

    const int tid  = threadIdx.x;
    const int wid  = tid >> 5;
    const int lane = tid & 31;
    const int wm   = (wid & 1) * 64;
    const int wn   = (wid >> 1) * 32;
    const int lr = lane >> 2;
    const int lc = lane & 3;

    float acc[4][4][4];
    #pragma unroll
    for (int i = 0; i < 4; i++)
        #pragma unroll
        for (int j = 0; j < 4; j++)
            #pragma unroll
            for (int r = 0; r < 4; r++) acc[i][j][r] = 0.f;

    auto issue = [&](int kt, int stage) {
        const int k0 = kt * 32;
        const uint32_t aB = sbA + (uint32_t)stage * ST_AW * 4;
        const uint32_t bB = sbB + (uint32_t)stage * ST_BW * 4;
        if (CVTA) {
            const float* A = (const float*)Av;
            #pragma unroll
            for (int j = 0; j < 4; j++) {
                int idx = tid + 256 * j;
                int r = idx >> 3, c4 = (idx & 7) * 4;
                cp16(aB + (uint32_t)(r * APW + c4) * 4,
                     &A[(size_t)(row0 + r) * K + k0 + c4]);
            }
        } else {
            const __half* A = (const __half*)Av;
            #pragma unroll
            for (int j = 0; j < 2; j++) {
                int idx = tid + 256 * j;
                int r = idx >> 2, c8 = (idx & 3) * 8;   // halves
                cp16(aB + (uint32_t)(r * APW + (idx & 3) * 4) * 4,
                     &A[(size_t)(row0 + r) * K + k0 + c8]);
            }
        }
        #pragma unroll
        for (int j = 0; j < 2; j++) {
            int idx = tid + 256 * j;
            int r = idx >> 2, c8 = (idx & 3) * 8;
            cp16(bB + (uint32_t)(r * BPW + (idx & 3) * 4) * 4,
                 &Bt[(size_t)(col0 + r) * K + k0 + c8]);
        }
        CP_COMMIT();
    };

    const int ntiles = K / 32;
    issue(0, 0);
    issue(1, 1);

    int stage = 0;
    for (int kt = 0; kt < ntiles; kt++) {
        if (kt + 1 < ntiles) {
            asm volatile("cp.async.wait_group 1;");
        } else {
            asm volatile("cp.async.wait_group 0;");
        }
        __syncthreads();

        if (kt + 2 < ntiles) {
            int s2 = stage + 2; if (s2 >= NSTAGE) s2 -= NSTAGE;
            issue(kt + 2, s2);
        }

        const uint32_t* Asn = As + stage * ST_AW;
        const uint32_t* Bsn = Bs + stage * ST_BW;

        #pragma unroll
        for (int s = 0; s < 2; s++) {          // two k16 steps per ktile
            uint32_t af[4][4];
            #pragma unroll
            for (int mt = 0; mt < 4; mt++) {
                const int row = wm + mt * 16 + lr;
                if (CVTA) {
                    const float2* Af2 = reinterpret_cast<const float2*>(Asn);
                    int i0 = row * (APW32/2) + s * 8 + lc;
                    float2 p0 = Af2[i0];
                    float2 p1 = Af2[i0 + 8 * (APW32/2)];
                    float2 p2 = Af2[i0 + 4];
                    float2 p3 = Af2[i0 + 8 * (APW32/2) + 4];
                    af[mt][0] = pack_h2(p0.x, p0.y);
                    af[mt][1] = pack_h2(p1.x, p1.y);
                    af[mt][2] = pack_h2(p2.x, p2.y);
                    af[mt][3] = pack_h2(p3.x, p3.y);
                } else {
                    int i0 = row * APW16 + s * 8 + lc;
                    af[mt][0] = Asn[i0];
                    af[mt][1] = Asn[i0 + 8 * APW16];
                    af[mt][2] = Asn[i0 + 4];
                    af[mt][3] = Asn[i0 + 8 * APW16 + 4];
                }
            }
            uint32_t bf[4][2];
            #pragma unroll
            for (int nt = 0; nt < 4; nt++) {
                int j0 = (wn + nt * 8 + lr) * BPW + s * 8 + lc;
                bf[nt][0] = Bsn[j0];
                bf[nt][1] = Bsn[j0 + 4];
            }
            #pragma unroll
            for (int mt = 0; mt < 4; mt++)
                #pragma unroll
                for (int nt = 0; nt < 4; nt++)
                    mma_f16(acc[mt][nt], af[mt][0], af[mt][1], af[mt][2],
                            af[mt][3], bf[nt][0], bf[nt][1]);
        }

        if (++stage >= NSTAGE) stage = 0;
    }

    // ---- epilogue ----
    const int half = N >> 1;
    #pragma unroll
    for (int mt = 0; mt < 4; mt++) {
        #pragma unroll
        for (int nt = 0; nt < 4; nt++) {
            const int col = col0 + wn + nt * 8 + lc * 2;
            #pragma unroll
            for (int hh = 0; hh < 2; hh++) {
                const int row = row0 + wm + mt * 16 + lr + hh * 8;
                float v0 = acc[mt][nt][hh * 2 + 0];
                float v1 = acc[mt][nt][hh * 2 + 1];
                if (epi == 0) {
                    float2 o;
                    o.x = v0 + bias[col]; o.y = v1 + bias[col + 1];
                    *reinterpret_cast<float2*>(&Cf[(size_t)row * N + col]) = o;
                } else if (epi == 1) {
                    __half2 o = __floats2half2_rn(elu1(v0), elu1(v1));
                    *reinterpret_cast<__half2*>(&Ch[(size_t)row * N + col]) = o;
                } else {
                    if (col < half) {
                        __half2 o = __floats2half2_rn(elu1(v0), elu1(v1));
                        *reinterpret_cast<__half2*>(&Ch[(size_t)row * half + col]) = o;
                    } else {
                        __half2 o = __floats2half2_rn(v0, v1);
                        *reinterpret_cast<__half2*>(&C2h[(size_t)row * half + (col - half)]) = o;
                    }
                }
            }
        }
    }
}

#define G12_SMEM (NSTAGE*(128*APW32 + 128*BPW)*4)   // 86016
#define G5_SMEM  (NSTAGE*(128*APW16 + 128*BPW)*4)   // 61440

__global__ __launch_bounds__(256, 2)
void gemm12_kernel(const float* __restrict__ xq, const float* __restrict__ xkv)
{
    const int bx = blockIdx.x;
    const int row0 = blockIdx.y * 128;
    if (bx < 3) {
        gemm_core<true>(xq, g_wqt, nullptr, g_q, nullptr, nullptr,
                        INNER, DIM, 1, row0, bx * 128);
    } else {
        gemm_core<true>(xkv, g_wkvt, nullptr, g_k, g_v, nullptr,
                        2 * INNER, DIM, 2, row0, (bx - 3) * 128);
    }
}

__global__ __launch_bounds__(256, 2)
void gemm5_kernel(const float* __restrict__ bias, float* __restrict__ out)
{
    gemm_core<false>(g_attn, g_woutt, out, nullptr, nullptr, bias,
                     INNER, DIM, 0, blockIdx.y * 128, blockIdx.x * 128);
}

// ---------------------------------------------------------------------------
// kv via tf32 mma (unchanged math): k,v now fp16 in gmem; fp16->fp32 is EXACT
// (11-bit significand) so results are bit-identical to round 12.
// ---------------------------------------------------------------------------
#define CHUNK 256
#define KVP 72
__global__ __launch_bounds__(256)
void kv_mma_kernel()
{
    __shared__ uint32_t Kn[32 * KVP];   // k natural [n][d], fp32/tf32 bits
    __shared__ uint32_t Vs[32 * KVP];   // v natural [n][m]
    __shared__ float red[16][64];

    const int bh = blockIdx.x;
    const int b = bh / HEADS, h = bh % HEADS;
    const int n0 = blockIdx.y * CHUNK;

    const int tid  = threadIdx.x;
    const int wid  = tid >> 5;
    const int lane = tid & 31;
    const int wm   = (wid & 1) * 32;
    const int wn   = (wid >> 1) * 16;
    const int lr = lane >> 2;
    const int lc = lane & 3;

    const __half* kbase = g_k + ((size_t)(b * NSEQ + n0)) * INNER + h * DHEAD;
    const __half* vbase = g_v + ((size_t)(b * NSEQ + n0)) * INNER + h * DHEAD;

    float acc[2][2][4];
    #pragma unroll
    for (int i = 0; i < 2; i++)
        #pragma unroll
        for (int j = 0; j < 2; j++)
            #pragma unroll
            for (int r = 0; r < 4; r++) acc[i][j][r] = 0.f;
    float sk[4] = {0.f, 0.f, 0.f, 0.f};

    for (int sub = 0; sub < CHUNK / 32; sub++) {
        const int nn = sub * 32;
        #pragma unroll
        for (int it = 0; it < 2; it++) {
            int idx = tid + it * 256;
            int n = idx >> 4, c4 = (idx & 15) * 4;
            __half2 kp0, kp1;
            {
                uint2 raw = *reinterpret_cast<const uint2*>(
                    &kbase[(size_t)(nn + n) * INNER + c4]);
                kp0 = *reinterpret_cast<__half2*>(&raw.x);
                kp1 = *reinterpret_cast<__half2*>(&raw.y);
            }
            float2 f01 = __half22float2(kp0);
            float2 f23 = __half22float2(kp1);
            uint4 ko;
            ko.x = __float_as_uint(f01.x); ko.y = __float_as_uint(f01.y);
            ko.z = __float_as_uint(f23.x); ko.w = __float_as_uint(f23.y);
            *reinterpret_cast<uint4*>(&Kn[n * KVP + c4]) = ko;
            sk[0] += f01.x; sk[1] += f01.y; sk[2] += f23.x; sk[3] += f23.y;
            __half2 vp0, vp1;
            {
                uint2 raw = *reinterpret_cast<const uint2*>(
                    &vbase[(size_t)(nn + n) * INNER + c4]);
                vp0 = *reinterpret_cast<__half2*>(&raw.x);
                vp1 = *reinterpret_cast<__half2*>(&raw.y);
            }
            float2 g01 = __half22float2(vp0);
            float2 g23 = __half22float2(vp1);
            uint4 vo;
            vo.x = __float_as_uint(g01.x); vo.y = __float_as_uint(g01.y);
            vo.z = __float_as_uint(g23.x); vo.w = __float_as_uint(g23.y);
            *reinterpret_cast<uint4*>(&Vs[n * KVP + c4]) = vo;
        }
        __syncthreads();

        #pragma unroll
        for (int s = 0; s < 4; s++) {
            const int kk = s * 8;
            uint32_t af[2][4];
            #pragma unroll
            for (int mt = 0; mt < 2; mt++) {
                const int drow = wm + mt * 16 + lr;
                const uint32_t* ap = &Kn[(kk + lc) * KVP + drow];
                af[mt][0] = ap[0];
                af[mt][1] = ap[8];
                af[mt][2] = ap[4 * KVP];
                af[mt][3] = ap[4 * KVP + 8];
            }
            uint32_t bf[2][2];
            #pragma unroll
            for (int nt = 0; nt < 2; nt++) {
                const uint32_t* bp = &Vs[(kk + lc) * KVP + wn + nt * 8 + lr];
                bf[nt][0] = bp[0];
                bf[nt][1] = bp[4 * KVP];
            }
            #pragma unroll
            for (int mt = 0; mt < 2; mt++)
                #pragma unroll
                for (int nt = 0; nt < 2; nt++)
                    mma_tf32(acc[mt][nt], af[mt][0], af[mt][1], af[mt][2],
                             af[mt][3], bf[nt][0], bf[nt][1]);
        }
        __syncthreads();
    }

    {
        const int c4 = (tid & 15) * 4;
        const int grp = tid >> 4;
        #pragma unroll
        for (int j = 0; j < 4; j++) red[grp][c4 + j] = sk[j];
        __syncthreads();
        if (tid < 64) {
            float s = 0.f;
            #pragma unroll
            for (int r = 0; r < 16; r++) s += red[r][tid];
            atomicAdd(&g_ksum[bh * DHEAD + tid], s);
        }
    }

    float* kvp = g_kv + (size_t)bh * DHEAD * DHEAD;
    #pragma unroll
    for (int mt = 0; mt < 2; mt++) {
        #pragma unroll
        for (int nt = 0; nt < 2; nt++) {
            const int col = wn + nt * 8 + lc * 2;
            #pragma unroll
            for (int hh = 0; hh < 2; hh++) {
                const int row = wm + mt * 16 + lr + hh * 8;
                atomicAdd(&kvp[row * DHEAD + col],     acc[mt][nt][hh * 2 + 0]);
                atomicAdd(&kvp[row * DHEAD + col + 1], acc[mt][nt][hh * 2 + 1]);
            }
        }
    }
}

// ---------------------------------------------------------------------------
// attn via tf32 mma (unchanged math): q fp16 (exact->fp32), kv fp32->tf32,
// output stored fp16 (same 11-bit rounding as before).
// ---------------------------------------------------------------------------
#define AQP 68
__global__ __launch_bounds__(256, 5)
void attn_mma_kernel()
{
    __shared__ uint32_t qs [64 * AQP];
    __shared__ uint32_t kvs[64 * KVP];
    __shared__ float ks[64];
    __shared__ float zr[64];

    const int bh = blockIdx.x;
    const int b = bh / HEADS, h = bh % HEADS;
    const int n0 = blockIdx.y * 64;

    const int tid  = threadIdx.x;
    const int wid  = tid >> 5;
    const int lane = tid & 31;
    const int wm   = (wid & 1) * 32;
    const int wn   = (wid >> 1) * 16;
    const int lr = lane >> 2;
    const int lc = lane & 3;

    const __half* qptr = g_q + ((size_t)(b * NSEQ + n0)) * INNER + h * DHEAD;
    #pragma unroll
    for (int j = 0; j < 4; j++) {
        int idx = tid + 256 * j;
        int r = idx >> 4, c4 = (idx & 15) * 4;
        uint2 raw = *reinterpret_cast<const uint2*>(&qptr[(size_t)r * INNER + c4]);
        float2 f01 = __half22float2(*reinterpret_cast<__half2*>(&raw.x));
        float2 f23 = __half22float2(*reinterpret_cast<__half2*>(&raw.y));
        uint4 o;
        o.x = __float_as_uint(f01.x); o.y = __float_as_uint(f01.y);
        o.z = __float_as_uint(f23.x); o.w = __float_as_uint(f23.y);
        *reinterpret_cast<uint4*>(&qs[r * AQP + c4]) = o;
    }
    #pragma unroll
    for (int j = 0; j < 4; j++) {
        int idx = tid + 256 * j;
        int d = idx >> 4, m4 = (idx & 15) * 4;
        float4 v = *reinterpret_cast<const float4*>(&g_kv[(size_t)bh * 4096 + d * 64 + m4]);
        uint4 o;
        o.x = f2tf32(v.x); o.y = f2tf32(v.y);
        o.z = f2tf32(v.z); o.w = f2tf32(v.w);
        *reinterpret_cast<uint4*>(&kvs[d * KVP + m4]) = o;
    }
    if (tid < 64) ks[tid] = g_ksum[bh * 64 + tid];
    __syncthreads();

    if (tid < 64) {
        float s = 0.f;
        #pragma unroll
        for (int dd = 0; dd < 64; dd++)
            s += __uint_as_float(qs[tid * AQP + dd]) * ks[dd];
        zr[tid] = 1.f / (s + 1e-6f);
    }
    __syncthreads();

    float acc[2][2][4];
    #pragma unroll
    for (int i = 0; i < 2; i++)
        #pragma unroll
        for (int j = 0; j < 2; j++)
            #pragma unroll
            for (int r = 0; r < 4; r++) acc[i][j][r] = 0.f;

    #pragma unroll
    for (int s = 0; s < 8; s++) {
        const int kk = s * 8;
        uint32_t af[2][4];
        #pragma unroll
        for (int mt = 0; mt < 2; mt++) {
            const uint32_t* ap = &qs[(wm + mt * 16 + lr) * AQP + kk + lc];
            af[mt][0] = ap[0];
            af[mt][1] = ap[8 * AQP];
            af[mt][2] = ap[4];
            af[mt][3] = ap[8 * AQP + 4];
        }
        uint32_t bf[2][2];
        #pragma unroll
        for (int nt = 0; nt < 2; nt++) {
            const uint32_t* bp = &kvs[(kk + lc) * KVP + wn + nt * 8 + lr];
            bf[nt][0] = bp[0];
            bf[nt][1] = bp[4 * KVP];
        }
        #pragma unroll
        for (int mt = 0; mt < 2; mt++)
            #pragma unroll
            for (int nt = 0; nt < 2; nt++)
                mma_tf32(acc[mt][nt], af[mt][0], af[mt][1], af[mt][2],
                         af[mt][3], bf[nt][0], bf[nt][1]);
    }

    #pragma unroll
    for (int mt = 0; mt < 2; mt++) {
        #pragma unroll
        for (int nt = 0; nt < 2; nt++) {
            const int col = wn + nt * 8 + lc * 2;
            #pragma unroll
            for (int hh = 0; hh < 2; hh++) {
                const int row = wm + mt * 16 + lr + hh * 8;
                const float z = zr[row];
                __half2 o = __floats2half2_rn(acc[mt][nt][hh * 2 + 0] * z,
                                              acc[mt][nt][hh * 2 + 1] * z);
                *reinterpret_cast<__half2*>(
                    &g_attn[((size_t)(b * NSEQ + n0 + row)) * INNER + h * DHEAD + col]) = o;
            }
        }
    }
}

// ---------------------------------------------------------------------------
// Launch order: CVTZ, G12, KV, AT, G5
// ---------------------------------------------------------------------------
extern "C" void kernel_launch(void* const* d_in, const int* in_sizes, int n_in,
                              void* d_out, int out_size)
{
    const float* x_q  = (const float*)d_in[0];
    const float* x_kv = (const float*)d_in[1];
    const float* Wq   = (const float*)d_in[2];
    const float* Wkv  = (const float*)d_in[3];
    const float* Wout = (const float*)d_in[4];
    const float* bout = (const float*)d_in[5];
    float* out = (float*)d_out;

    cudaFuncSetAttribute((const void*)gemm12_kernel, cudaFuncAttributeMaxDynamicSharedMemorySize, G12_SMEM);
    cudaFuncSetAttribute((const void*)gemm5_kernel,  cudaFuncAttributeMaxDynamicSharedMemorySize, G5_SMEM);

    dim3 blk(256);

    // 1) weights -> fp16 transposed + zero accumulators
    cvt_w_zero_kernel<<<576, blk>>>(Wq, Wkv, Wout);

    // 2) merged projections (fp16 mma): q = elu1(x_q@Wq); k/v = split(x_kv@Wkv)
    gemm12_kernel<<<dim3(9, ROWS/128), blk, G12_SMEM>>>(x_q, x_kv);

    // 3) kv = k^T v; ksum = sum_n k
    kv_mma_kernel<<<dim3(BATCH*HEADS, NSEQ/CHUNK), blk>>>();

    // 4) attn = (q @ kv) * z
    attn_mma_kernel<<<dim3(BATCH*HEADS, NSEQ/64), blk>>>();

    // 5) out = attn @ Wout + bout (fp16 mma, fp32 out)
    gemm5_kernel<<<dim3(INNER/128, ROWS/128), blk, G5_SMEM>>>(bout, out);
}

// round 14
// speedup vs baseline: 2.2580x; 1.1185x over previous
#include <cuda_runtime.h>
#include <cuda_fp16.h>
#include <cstdint>

#define BATCH 8
#define NSEQ  4096
#define DIM   384
#define HEADS 6
#define DHEAD 64
#define INNER 384
#define ROWS  (BATCH*NSEQ)   // 32768

// ---- scratch (device globals: no allocation allowed) ----
__device__ __half g_xqh  [ (size_t)ROWS*DIM ];      // x_q  fp16
__device__ __half g_xkvh [ (size_t)ROWS*DIM ];      // x_kv fp16
__device__ __half g_wqt  [ (size_t)INNER*DIM ];     // Wq^T  [n][k] fp16
__device__ __half g_wkvt [ (size_t)2*INNER*DIM ];   // Wkv^T [n][k] fp16
__device__ __half g_woutt[ (size_t)DIM*INNER ];     // Wout^T[n][k] fp16
__device__ __half g_q    [ (size_t)ROWS*INNER ];
__device__ __half g_k    [ (size_t)ROWS*INNER ];
__device__ __half g_v    [ (size_t)ROWS*INNER ];
__device__ __half g_attn [ (size_t)ROWS*INNER ];
__device__ float  g_kv   [ BATCH*HEADS*DHEAD*DHEAD ];
__device__ float  g_ksum [ BATCH*HEADS*DHEAD ];

__device__ __forceinline__ float elu1(float x) {
    return x > 0.f ? x + 1.f : __expf(x);
}

__device__ __forceinline__ uint32_t f2tf32(float x) {
    uint32_t u;
    asm("cvt.rna.tf32.f32 %0, %1;" : "=r"(u) : "f"(x));
    return u;
}

__device__ __forceinline__ uint32_t smem_u32(const void* p) {
    uint32_t a;
    asm("{ .reg .u64 t; cvta.to.shared.u64 t, %1; cvt.u32.u64 %0, t; }"
        : "=r"(a) : "l"(p));
    return a;
}
__device__ __forceinline__ void cp16(uint32_t dst, const void* src) {
    asm volatile("cp.async.cg.shared.global [%0], [%1], 16;"
                 :: "r"(dst), "l"(src));
}
#define CP_COMMIT() asm volatile("cp.async.commit_group;")

__device__ __forceinline__ void mma_tf32(float c[4], uint32_t a0, uint32_t a1,
                                         uint32_t a2, uint32_t a3,
                                         uint32_t b0, uint32_t b1) {
    asm volatile(
        "mma.sync.aligned.m16n8k8.row.col.f32.tf32.tf32.f32 "
        "{%0,%1,%2,%3}, {%4,%5,%6,%7}, {%8,%9}, {%0,%1,%2,%3};"
        : "+f"(c[0]), "+f"(c[1]), "+f"(c[2]), "+f"(c[3])
        : "r"(a0), "r"(a1), "r"(a2), "r"(a3), "r"(b0), "r"(b1));
}

__device__ __forceinline__ void mma_f16(float c[4], uint32_t a0, uint32_t a1,
                                        uint32_t a2, uint32_t a3,
                                        uint32_t b0, uint32_t b1) {
    asm volatile(
        "mma.sync.aligned.m16n8k16.row.col.f32.f16.f16.f32 "
        "{%0,%1,%2,%3}, {%4,%5,%6,%7}, {%8,%9}, {%0,%1,%2,%3};"
        : "+f"(c[0]), "+f"(c[1]), "+f"(c[2]), "+f"(c[3])
        : "r"(a0), "r"(a1), "r"(a2), "r"(a3), "r"(b0), "r"(b1));
}

// ---------------------------------------------------------------------------
// Prep kernels.
// cvt_w_zero: weights -> fp16 transposed [n][k]; zero kv/ksum.
// cvt_x: fp32 x -> fp16 (vectorized: 2x float4 in, 1x uint4 out).
// ---------------------------------------------------------------------------
__global__ void cvt_w_zero_kernel(const float* __restrict__ wq,
                                  const float* __restrict__ wkv,
                                  const float* __restrict__ wout)
{
    const int n1 = DIM*INNER, n2 = DIM*2*INNER, n3 = INNER*DIM;
    const int nw = n1 + n2 + n3;
    const int nz = BATCH*HEADS*DHEAD*DHEAD/4;
    const int nz2 = BATCH*HEADS*DHEAD/4;
    const float4 z4 = make_float4(0.f, 0.f, 0.f, 0.f);
    for (int i = blockIdx.x * blockDim.x + threadIdx.x; i < nw + nz + nz2;
         i += gridDim.x * blockDim.x) {
        if (i < nw) {
            const float* s; __half* d; int j, Nn;
            if (i < n1)           { s = wq;   d = g_wqt;   j = i;           Nn = INNER; }
            else if (i < n1 + n2) { s = wkv;  d = g_wkvt;  j = i - n1;      Nn = 2*INNER; }
            else                  { s = wout; d = g_woutt; j = i - n1 - n2; Nn = DIM; }
            int k = j / Nn, n = j % Nn;
            d[(size_t)n * DIM + k] = __float2half(s[j]);
        } else if (i < nw + nz) {
            reinterpret_cast<float4*>(g_kv)[i - nw] = z4;
        } else {
            reinterpret_cast<float4*>(g_ksum)[i - nw - nz] = z4;
        }
    }
}

__global__ void cvt_x_kernel(const float* __restrict__ src, __half* __restrict__ dst)
{
    const int n8 = ROWS * DIM / 8;
    for (int i = blockIdx.x * blockDim.x + threadIdx.x; i < n8;
         i += gridDim.x * blockDim.x) {
        float4 a = reinterpret_cast<const float4*>(src)[2*i];
        float4 b = reinterpret_cast<const float4*>(src)[2*i + 1];
        __half2 h0 = __floats2half2_rn(a.x, a.y);
        __half2 h1 = __floats2half2_rn(a.z, a.w);
        __half2 h2 = __floats2half2_rn(b.x, b.y);
        __half2 h3 = __floats2half2_rn(b.z, b.w);
        uint4 o;
        o.x = *reinterpret_cast<uint32_t*>(&h0);
        o.y = *reinterpret_cast<uint32_t*>(&h1);
        o.z = *reinterpret_cast<uint32_t*>(&h2);
        o.w = *reinterpret_cast<uint32_t*>(&h3);
        reinterpret_cast<uint4*>(dst)[i] = o;
    }
}

// ============================================================================
// fp16 mma.sync GEMM core: cp.async 3-stage ring, ONE barrier per ktile.
// A fp16 [m][k], B fp16 pre-transposed [n][k]. Zero in-loop conversions.
// CTA tile 128x128, BK=32 (2 k16 steps), 256 thr (8 warps, warp tile 64x32).
// epi 0: +bias -> fp32 out; epi 1: elu1 -> fp16; epi 2: N-split -> fp16/fp16.
// ============================================================================
#define NSTAGE 3
#define APW 20                 // pitch (words; 40 halves)
#define BPW 20
#define ST_AW (128*APW)
#define ST_BW (128*BPW)
#define G_SMEM (NSTAGE*(ST_AW + ST_BW)*4)   // 61440

__device__ __forceinline__ void gemm_core(
    const __half* __restrict__ A, const __half* __restrict__ Bt,
    float* __restrict__ Cf, __half* __restrict__ Ch, __half* __restrict__ C2h,
    const float* __restrict__ bias, int N, int K, int epi,
    int row0, int col0)
{
    extern __shared__ uint32_t dsm[];
    uint32_t* As = dsm;
    uint32_t* Bs = dsm + NSTAGE * ST_AW;
    const uint32_t sbA = smem_u32(As);
    const uint32_t sbB = smem_u32(Bs);

    const int tid  = threadIdx.x;
    const int wid  = tid >> 5;
    const int lane = tid & 31;
    const int wm   = (wid & 1) * 64;
    const int wn   = (wid >> 1) * 32;
    const int lr = lane >> 2;
    const int lc = lane & 3;

    float acc[4][4][4];
    #pragma unroll
    for (int i = 0; i < 4; i++)
        #pragma unroll
        for (int j = 0; j < 4; j++)
            #pragma unroll
            for (int r = 0; r < 4; r++) acc[i][j][r] = 0.f;

    auto issue = [&](int kt, int stage) {
        const int k0 = kt * 32;
        const uint32_t aB = sbA + (uint32_t)stage * ST_AW * 4;
        const uint32_t bB = sbB + (uint32_t)stage * ST_BW * 4;
        #pragma unroll
        for (int j = 0; j < 2; j++) {
            int idx = tid + 256 * j;
            int r = idx >> 2, c8 = (idx & 3) * 8;
            cp16(aB + (uint32_t)(r * APW + (idx & 3) * 4) * 4,
                 &A[(size_t)(row0 + r) * K + k0 + c8]);
        }
        #pragma unroll
        for (int j = 0; j < 2; j++) {
            int idx = tid + 256 * j;
            int r = idx >> 2, c8 = (idx & 3) * 8;
            cp16(bB + (uint32_t)(r * BPW + (idx & 3) * 4) * 4,
                 &Bt[(size_t)(col0 + r) * K + k0 + c8]);
        }
        CP_COMMIT();
    };

    const int ntiles = K / 32;
    issue(0, 0);
    issue(1, 1);

    int stage = 0;
    for (int kt = 0; kt < ntiles; kt++) {
        if (kt + 1 < ntiles) {
            asm volatile("cp.async.wait_group 1;");
        } else {
            asm volatile("cp.async.wait_group 0;");
        }
        __syncthreads();

        if (kt + 2 < ntiles) {
            int s2 = stage + 2; if (s2 >= NSTAGE) s2 -= NSTAGE;
            issue(kt + 2, s2);
        }

        const uint32_t* Asn = As + stage * ST_AW;
        const uint32_t* Bsn = Bs + stage * ST_BW;

        #pragma unroll
        for (int s = 0; s < 2; s++) {
            uint32_t af[4][4];
            #pragma unroll
            for (int mt = 0; mt < 4; mt++) {
                int i0 = (wm + mt * 16 + lr) * APW + s * 8 + lc;
                af[mt][0] = Asn[i0];
                af[mt][1] = Asn[i0 + 8 * APW];
                af[mt][2] = Asn[i0 + 4];
                af[mt][3] = Asn[i0 + 8 * APW + 4];
            }
            uint32_t bf[4][2];
            #pragma unroll
            for (int nt = 0; nt < 4; nt++) {
                int j0 = (wn + nt * 8 + lr) * BPW + s * 8 + lc;
                bf[nt][0] = Bsn[j0];
                bf[nt][1] = Bsn[j0 + 4];
            }
            #pragma unroll
            for (int mt = 0; mt < 4; mt++)
                #pragma unroll
                for (int nt = 0; nt < 4; nt++)
                    mma_f16(acc[mt][nt], af[mt][0], af[mt][1], af[mt][2],
                            af[mt][3], bf[nt][0], bf[nt][1]);
        }

        if (++stage >= NSTAGE) stage = 0;
    }

    // ---- epilogue ----
    const int half = N >> 1;
    #pragma unroll
    for (int mt = 0; mt < 4; mt++) {
        #pragma unroll
        for (int nt = 0; nt < 4; nt++) {
            const int col = col0 + wn + nt * 8 + lc * 2;
            #pragma unroll
            for (int hh = 0; hh < 2; hh++) {
                const int row = row0 + wm + mt * 16 + lr + hh * 8;
                float v0 = acc[mt][nt][hh * 2 + 0];
                float v1 = acc[mt][nt][hh * 2 + 1];
                if (epi == 0) {
                    float2 o;
                    o.x = v0 + bias[col]; o.y = v1 + bias[col + 1];
                    *reinterpret_cast<float2*>(&Cf[(size_t)row * N + col]) = o;
                } else if (epi == 1) {
                    __half2 o = __floats2half2_rn(elu1(v0), elu1(v1));
                    *reinterpret_cast<__half2*>(&Ch[(size_t)row * N + col]) = o;
                } else {
                    if (col < half) {
                        __half2 o = __floats2half2_rn(elu1(v0), elu1(v1));
                        *reinterpret_cast<__half2*>(&Ch[(size_t)row * half + col]) = o;
                    } else {
                        __half2 o = __floats2half2_rn(v0, v1);
                        *reinterpret_cast<__half2*>(&C2h[(size_t)row * half + (col - half)]) = o;
                    }
                }
            }
        }
    }
}

__global__ __launch_bounds__(256, 2)
void gemm12_kernel()
{
    const int bx = blockIdx.x;
    const int row0 = blockIdx.y * 128;
    if (bx < 3) {
        gemm_core(g_xqh, g_wqt, nullptr, g_q, nullptr, nullptr,
                  INNER, DIM, 1, row0, bx * 128);
    } else {
        gemm_core(g_xkvh, g_wkvt, nullptr, g_k, g_v, nullptr,
                  2 * INNER, DIM, 2, row0, (bx - 3) * 128);
    }
}

__global__ __launch_bounds__(256, 2)
void gemm5_kernel(const float* __restrict__ bias, float* __restrict__ out)
{
    gemm_core(g_attn, g_woutt, out, nullptr, nullptr, bias,
              INNER, DIM, 0, blockIdx.y * 128, blockIdx.x * 128);
}

// ---------------------------------------------------------------------------
// kv via tf32 mma (unchanged from 289us baseline).
// ---------------------------------------------------------------------------
#define CHUNK 256
#define KVP 72
__global__ __launch_bounds__(256)
void kv_mma_kernel()
{
    __shared__ uint32_t Kn[32 * KVP];
    __shared__ uint32_t Vs[32 * KVP];
    __shared__ float red[16][64];

    const int bh = blockIdx.x;
    const int b = bh / HEADS, h = bh % HEADS;
    const int n0 = blockIdx.y * CHUNK;

    const int tid  = threadIdx.x;
    const int wid  = tid >> 5;
    const int lane = tid & 31;
    const int wm   = (wid & 1) * 32;
    const int wn   = (wid >> 1) * 16;
    const int lr = lane >> 2;
    const int lc = lane & 3;

    const __half* kbase = g_k + ((size_t)(b * NSEQ + n0)) * INNER + h * DHEAD;
    const __half* vbase = g_v + ((size_t)(b * NSEQ + n0)) * INNER + h * DHEAD;

    float acc[2][2][4];
    #pragma unroll
    for (int i = 0; i < 2; i++)
        #pragma unroll
        for (int j = 0; j < 2; j++)
            #pragma unroll
            for (int r = 0; r < 4; r++) acc[i][j][r] = 0.f;
    float sk[4] = {0.f, 0.f, 0.f, 0.f};

    for (int sub = 0; sub < CHUNK / 32; sub++) {
        const int nn = sub * 32;
        #pragma unroll
        for (int it = 0; it < 2; it++) {
            int idx = tid + it * 256;
            int n = idx >> 4, c4 = (idx & 15) * 4;
            uint2 kraw = *reinterpret_cast<const uint2*>(
                &kbase[(size_t)(nn + n) * INNER + c4]);
            float2 f01 = __half22float2(*reinterpret_cast<__half2*>(&kraw.x));
            float2 f23 = __half22float2(*reinterpret_cast<__half2*>(&kraw.y));
            uint4 ko;
            ko.x = __float_as_uint(f01.x); ko.y = __float_as_uint(f01.y);
            ko.z = __float_as_uint(f23.x); ko.w = __float_as_uint(f23.y);
            *reinterpret_cast<uint4*>(&Kn[n * KVP + c4]) = ko;
            sk[0] += f01.x; sk[1] += f01.y; sk[2] += f23.x; sk[3] += f23.y;
            uint2 vraw = *reinterpret_cast<const uint2*>(
                &vbase[(size_t)(nn + n) * INNER + c4]);
            float2 g01 = __half22float2(*reinterpret_cast<__half2*>(&vraw.x));
            float2 g23 = __half22float2(*reinterpret_cast<__half2*>(&vraw.y));
            uint4 vo;
            vo.x = __float_as_uint(g01.x); vo.y = __float_as_uint(g01.y);
            vo.z = __float_as_uint(g23.x); vo.w = __float_as_uint(g23.y);
            *reinterpret_cast<uint4*>(&Vs[n * KVP + c4]) = vo;
        }
        __syncthreads();

        #pragma unroll
        for (int s = 0; s < 4; s++) {
            const int kk = s * 8;
            uint32_t af[2][4];
            #pragma unroll
            for (int mt = 0; mt < 2; mt++) {
                const int drow = wm + mt * 16 + lr;
                const uint32_t* ap = &Kn[(kk + lc) * KVP + drow];
                af[mt][0] = ap[0];
                af[mt][1] = ap[8];
                af[mt][2] = ap[4 * KVP];
                af[mt][3] = ap[4 * KVP + 8];
            }
            uint32_t bf[2][2];
            #pragma unroll
            for (int nt = 0; nt < 2; nt++) {
                const uint32_t* bp = &Vs[(kk + lc) * KVP + wn + nt * 8 + lr];
                bf[nt][0] = bp[0];
                bf[nt][1] = bp[4 * KVP];
            }
            #pragma unroll
            for (int mt = 0; mt < 2; mt++)
                #pragma unroll
                for (int nt = 0; nt < 2; nt++)
                    mma_tf32(acc[mt][nt], af[mt][0], af[mt][1], af[mt][2],
                             af[mt][3], bf[nt][0], bf[nt][1]);
        }
        __syncthreads();
    }

    {
        const int c4 = (tid & 15) * 4;
        const int grp = tid >> 4;
        #pragma unroll
        for (int j = 0; j < 4; j++) red[grp][c4 + j] = sk[j];
        __syncthreads();
        if (tid < 64) {
            float s = 0.f;
            #pragma unroll
            for (int r = 0; r < 16; r++) s += red[r][tid];
            atomicAdd(&g_ksum[bh * DHEAD + tid], s);
        }
    }

    float* kvp = g_kv + (size_t)bh * DHEAD * DHEAD;
    #pragma unroll
    for (int mt = 0; mt < 2; mt++) {
        #pragma unroll
        for (int nt = 0; nt < 2; nt++) {
            const int col = wn + nt * 8 + lc * 2;
            #pragma unroll
            for (int hh = 0; hh < 2; hh++) {
                const int row = wm + mt * 16 + lr + hh * 8;
                atomicAdd(&kvp[row * DHEAD + col],     acc[mt][nt][hh * 2 + 0]);
                atomicAdd(&kvp[row * DHEAD + col + 1], acc[mt][nt][hh * 2 + 1]);
            }
        }
    }
}

// ---------------------------------------------------------------------------
// attn via tf32 mma (unchanged from 289us baseline).
// ---------------------------------------------------------------------------
#define AQP 68
__global__ __launch_bounds__(256, 5)
void attn_mma_kernel()
{
    __shared__ uint32_t qs [64 * AQP];
    __shared__ uint32_t kvs[64 * KVP];
    __shared__ float ks[64];
    __shared__ float zr[64];

    const int bh = blockIdx.x;
    const int b = bh / HEADS, h = bh % HEADS;
    const int n0 = blockIdx.y * 64;

    const int tid  = threadIdx.x;
    const int wid  = tid >> 5;
    const int lane = tid & 31;
    const int wm   = (wid & 1) * 32;
    const int wn   = (wid >> 1) * 16;
    const int lr = lane >> 2;
    const int lc = lane & 3;

    const __half* qptr = g_q + ((size_t)(b * NSEQ + n0)) * INNER + h * DHEAD;
    #pragma unroll
    for (int j = 0; j < 4; j++) {
        int idx = tid + 256 * j;
        int r = idx >> 4, c4 = (idx & 15) * 4;
        uint2 raw = *reinterpret_cast<const uint2*>(&qptr[(size_t)r * INNER + c4]);
        float2 f01 = __half22float2(*reinterpret_cast<__half2*>(&raw.x));
        float2 f23 = __half22float2(*reinterpret_cast<__half2*>(&raw.y));
        uint4 o;
        o.x = __float_as_uint(f01.x); o.y = __float_as_uint(f01.y);
        o.z = __float_as_uint(f23.x); o.w = __float_as_uint(f23.y);
        *reinterpret_cast<uint4*>(&qs[r * AQP + c4]) = o;
    }
    #pragma unroll
    for (int j = 0; j < 4; j++) {
        int idx = tid + 256 * j;
        int d = idx >> 4, m4 = (idx & 15) * 4;
        float4 v = *reinterpret_cast<const float4*>(&g_kv[(size_t)bh * 4096 + d * 64 + m4]);
        uint4 o;
        o.x = f2tf32(v.x); o.y = f2tf32(v.y);
        o.z = f2tf32(v.z); o.w = f2tf32(v.w);
        *reinterpret_cast<uint4*>(&kvs[d * KVP + m4]) = o;
    }
    if (tid < 64) ks[tid] = g_ksum[bh * 64 + tid];
    __syncthreads();

    if (tid < 64) {
        float s = 0.f;
        #pragma unroll
        for (int dd = 0; dd < 64; dd++)
            s += __uint_as_float(qs[tid * AQP + dd]) * ks[dd];
        zr[tid] = 1.f / (s + 1e-6f);
    }
    __syncthreads();

    float acc[2][2][4];
    #pragma unroll
    for (int i = 0; i < 2; i++)
        #pragma unroll
        for (int j = 0; j < 2; j++)
            #pragma unroll
            for (int r = 0; r < 4; r++) acc[i][j][r] = 0.f;

    #pragma unroll
    for (int s = 0; s < 8; s++) {
        const int kk = s * 8;
        uint32_t af[2][4];
        #pragma unroll
        for (int mt = 0; mt < 2; mt++) {
            const uint32_t* ap = &qs[(wm + mt * 16 + lr) * AQP + kk + lc];
            af[mt][0] = ap[0];
            af[mt][1] = ap[8 * AQP];
            af[mt][2] = ap[4];
            af[mt][3] = ap[8 * AQP + 4];
        }
        uint32_t bf[2][2];
        #pragma unroll
        for (int nt = 0; nt < 2; nt++) {
            const uint32_t* bp = &kvs[(kk + lc) * KVP + wn + nt * 8 + lr];
            bf[nt][0] = bp[0];
            bf[nt][1] = bp[4 * KVP];
        }
        #pragma unroll
        for (int mt = 0; mt < 2; mt++)
            #pragma unroll
            for (int nt = 0; nt < 2; nt++)
                mma_tf32(acc[mt][nt], af[mt][0], af[mt][1], af[mt][2],
                         af[mt][3], bf[nt][0], bf[nt][1]);
    }

    #pragma unroll
    for (int mt = 0; mt < 2; mt++) {
        #pragma unroll
        for (int nt = 0; nt < 2; nt++) {
            const int col = wn + nt * 8 + lc * 2;
            #pragma unroll
            for (int hh = 0; hh < 2; hh++) {
                const int row = wm + mt * 16 + lr + hh * 8;
                const float z = zr[row];
                __half2 o = __floats2half2_rn(acc[mt][nt][hh * 2 + 0] * z,
                                              acc[mt][nt][hh * 2 + 1] * z);
                *reinterpret_cast<__half2*>(
                    &g_attn[((size_t)(b * NSEQ + n0 + row)) * INNER + h * DHEAD + col]) = o;
            }
        }
    }
}

// ---------------------------------------------------------------------------
// Launch order: CVTZ, CVTXQ, CVTXKV, G12 (profiled 4th slot), KV, AT, G5
// ---------------------------------------------------------------------------
extern "C" void kernel_launch(void* const* d_in, const int* in_sizes, int n_in,
                              void* d_out, int out_size)
{
    const float* x_q  = (const float*)d_in[0];
    const float* x_kv = (const float*)d_in[1];
    const float* Wq   = (const float*)d_in[2];
    const float* Wkv  = (const float*)d_in[3];
    const float* Wout = (const float*)d_in[4];
    const float* bout = (const float*)d_in[5];
    float* out = (float*)d_out;

    __half *xqh, *xkvh;
    cudaGetSymbolAddress((void**)&xqh,  g_xqh);
    cudaGetSymbolAddress((void**)&xkvh, g_xkvh);

    cudaFuncSetAttribute((const void*)gemm12_kernel, cudaFuncAttributeMaxDynamicSharedMemorySize, G_SMEM);
    cudaFuncSetAttribute((const void*)gemm5_kernel,  cudaFuncAttributeMaxDynamicSharedMemorySize, G_SMEM);

    dim3 blk(256);

    // 1) weights -> fp16 transposed + zero accumulators
    cvt_w_zero_kernel<<<576, blk>>>(Wq, Wkv, Wout);
    // 2-3) x -> fp16
    cvt_x_kernel<<<1024, blk>>>(x_q,  xqh);
    cvt_x_kernel<<<1024, blk>>>(x_kv, xkvh);

    // 4) merged projections (fp16 mma, no in-loop cvt)   [profiled slot]
    gemm12_kernel<<<dim3(9, ROWS/128), blk, G_SMEM>>>();

    // 5) kv = k^T v; ksum = sum_n k
    kv_mma_kernel<<<dim3(BATCH*HEADS, NSEQ/CHUNK), blk>>>();

    // 6) attn = (q @ kv) * z
    attn_mma_kernel<<<dim3(BATCH*HEADS, NSEQ/64), blk>>>();

    // 7) out = attn @ Wout + bout (fp32 out)
    gemm5_kernel<<<dim3(INNER/128, ROWS/128), blk, G_SMEM>>>(bout, out);
}

// round 15
// speedup vs baseline: 2.5776x; 1.1415x over previous
#include <cuda_runtime.h>
#include <cuda_fp16.h>
#include <cstdint>

#define BATCH 8
#define NSEQ  4096
#define DIM   384
#define HEADS 6
#define DHEAD 64
#define INNER 384
#define ROWS  (BATCH*NSEQ)   // 32768

// ---- scratch (device globals: no allocation allowed) ----
__device__ __half g_xqh  [ (size_t)ROWS*DIM ];      // x_q  fp16
__device__ __half g_xkvh [ (size_t)ROWS*DIM ];      // x_kv fp16
__device__ __half g_wqt  [ (size_t)INNER*DIM ];     // Wq^T  [n][k] fp16
__device__ __half g_wkvt [ (size_t)2*INNER*DIM ];   // Wkv^T [n][k] fp16
__device__ __half g_woutt[ (size_t)DIM*INNER ];     // Wout^T[n][k] fp16
__device__ __half g_q    [ (size_t)ROWS*INNER ];
__device__ __half g_k    [ (size_t)ROWS*INNER ];
__device__ __half g_v    [ (size_t)ROWS*INNER ];
__device__ __half g_attn [ (size_t)ROWS*INNER ];
__device__ float  g_kv   [ BATCH*HEADS*DHEAD*DHEAD ];
__device__ float  g_ksum [ BATCH*HEADS*DHEAD ];

__device__ __forceinline__ float elu1(float x) {
    return x > 0.f ? x + 1.f : __expf(x);
}

__device__ __forceinline__ uint32_t f2tf32(float x) {
    uint32_t u;
    asm("cvt.rna.tf32.f32 %0, %1;" : "=r"(u) : "f"(x));
    return u;
}

__device__ __forceinline__ uint32_t smem_u32(const void* p) {
    uint32_t a;
    asm("{ .reg .u64 t; cvta.to.shared.u64 t, %1; cvt.u32.u64 %0, t; }"
        : "=r"(a) : "l"(p));
    return a;
}
__device__ __forceinline__ void cp16(uint32_t dst, const void* src) {
    asm volatile("cp.async.cg.shared.global [%0], [%1], 16;"
                 :: "r"(dst), "l"(src));
}
#define CP_COMMIT() asm volatile("cp.async.commit_group;")

__device__ __forceinline__ void ldm_x4(uint32_t* r, uint32_t addr) {
    asm volatile("ldmatrix.sync.aligned.m8n8.x4.shared.b16 {%0,%1,%2,%3}, [%4];"
                 : "=r"(r[0]), "=r"(r[1]), "=r"(r[2]), "=r"(r[3])
                 : "r"(addr));
}

__device__ __forceinline__ void mma_tf32(float c[4], uint32_t a0, uint32_t a1,
                                         uint32_t a2, uint32_t a3,
                                         uint32_t b0, uint32_t b1) {
    asm volatile(
        "mma.sync.aligned.m16n8k8.row.col.f32.tf32.tf32.f32 "
        "{%0,%1,%2,%3}, {%4,%5,%6,%7}, {%8,%9}, {%0,%1,%2,%3};"
        : "+f"(c[0]), "+f"(c[1]), "+f"(c[2]), "+f"(c[3])
        : "r"(a0), "r"(a1), "r"(a2), "r"(a3), "r"(b0), "r"(b1));
}

__device__ __forceinline__ void mma_f16(float c[4], uint32_t a0, uint32_t a1,
                                        uint32_t a2, uint32_t a3,
                                        uint32_t b0, uint32_t b1) {
    asm volatile(
        "mma.sync.aligned.m16n8k16.row.col.f32.f16.f16.f32 "
        "{%0,%1,%2,%3}, {%4,%5,%6,%7}, {%8,%9}, {%0,%1,%2,%3};"
        : "+f"(c[0]), "+f"(c[1]), "+f"(c[2]), "+f"(c[3])
        : "r"(a0), "r"(a1), "r"(a2), "r"(a3), "r"(b0), "r"(b1));
}

// ---------------------------------------------------------------------------
// Prep kernels.
// ---------------------------------------------------------------------------
__global__ void cvt_w_zero_kernel(const float* __restrict__ wq,
                                  const float* __restrict__ wkv,
                                  const float* __restrict__ wout)
{
    const int n1 = DIM*INNER, n2 = DIM*2*INNER, n3 = INNER*DIM;
    const int nw = n1 + n2 + n3;
    const int nz = BATCH*HEADS*DHEAD*DHEAD/4;
    const int nz2 = BATCH*HEADS*DHEAD/4;
    const float4 z4 = make_float4(0.f, 0.f, 0.f, 0.f);
    for (int i = blockIdx.x * blockDim.x + threadIdx.x; i < nw + nz + nz2;
         i += gridDim.x * blockDim.x) {
        if (i < nw) {
            const float* s; __half* d; int j, Nn;
            if (i < n1)           { s = wq;   d = g_wqt;   j = i;           Nn = INNER; }
            else if (i < n1 + n2) { s = wkv;  d = g_wkvt;  j = i - n1;      Nn = 2*INNER; }
            else                  { s = wout; d = g_woutt; j = i - n1 - n2; Nn = DIM; }
            int k = j / Nn, n = j % Nn;
            d[(size_t)n * DIM + k] = __float2half(s[j]);
        } else if (i < nw + nz) {
            reinterpret_cast<float4*>(g_kv)[i - nw] = z4;
        } else {
            reinterpret_cast<float4*>(g_ksum)[i - nw - nz] = z4;
        }
    }
}

__global__ void cvt_x_kernel(const float* __restrict__ src, __half* __restrict__ dst)
{
    const int n8 = ROWS * DIM / 8;
    for (int i = blockIdx.x * blockDim.x + threadIdx.x; i < n8;
         i += gridDim.x * blockDim.x) {
        float4 a = reinterpret_cast<const float4*>(src)[2*i];
        float4 b = reinterpret_cast<const float4*>(src)[2*i + 1];
        __half2 h0 = __floats2half2_rn(a.x, a.y);
        __half2 h1 = __floats2half2_rn(a.z, a.w);
        __half2 h2 = __floats2half2_rn(b.x, b.y);
        __half2 h3 = __floats2half2_rn(b.z, b.w);
        uint4 o;
        o.x = *reinterpret_cast<uint32_t*>(&h0);
        o.y = *reinterpret_cast<uint32_t*>(&h1);
        o.z = *reinterpret_cast<uint32_t*>(&h2);
        o.w = *reinterpret_cast<uint32_t*>(&h3);
        reinterpret_cast<uint4*>(dst)[i] = o;
    }
}

// ============================================================================
// fp16 mma.sync GEMM core: cp.async 3-stage ring, ONE barrier per ktile,
// ldmatrix.x4 fragment loads (6 per s-step vs 24 scalar LDS).
// A fp16 [m][k], B fp16 pre-transposed [n][k].
// CTA tile 128x128, BK=32 (2 k16 steps), 256 thr (8 warps, warp tile 64x32).
// epi 0: +bias -> fp32 out; epi 1: elu1 -> fp16; epi 2: N-split -> fp16/fp16.
// ============================================================================
#define NSTAGE 3
#define APW 20                 // pitch (words; 40 halves) -> ldmatrix bank-free
#define BPW 20
#define ST_AW (128*APW)
#define ST_BW (128*BPW)
#define G_SMEM (NSTAGE*(ST_AW + ST_BW)*4)   // 61440

__device__ __forceinline__ void gemm_core(
    const __half* __restrict__ A, const __half* __restrict__ Bt,
    float* __restrict__ Cf, __half* __restrict__ Ch, __half* __restrict__ C2h,
    const float* __restrict__ bias, int N, int K, int epi,
    int row0, int col0)
{
    extern __shared__ uint32_t dsm[];
    uint32_t* As = dsm;
    uint32_t* Bs = dsm + NSTAGE * ST_AW;
    const uint32_t sbA = smem_u32(As);
    const uint32_t sbB = smem_u32(Bs);

    const int tid  = threadIdx.x;
    const int wid  = tid >> 5;
    const int lane = tid & 31;
    const int wm   = (wid & 1) * 64;
    const int wn   = (wid >> 1) * 32;
    const int lr = lane >> 2;
    const int lc = lane & 3;

    // ldmatrix per-lane address components: j = lane>>3 (matrix slot), rr = lane&7
    const int jj = lane >> 3;
    const int rr = lane & 7;
    // A x4: slots map to (row+8*(j&1), k+8*(j>>1)) -> af[0..3] order
    uint32_t aoff[4];
    #pragma unroll
    for (int mt = 0; mt < 4; mt++)
        aoff[mt] = (uint32_t)(((wm + mt * 16 + (jj & 1) * 8 + rr) * APW
                               + (jj >> 1) * 4) * 4);
    // B x4: slots map to (n+8*(j>>1), k+8*(j&1)) -> two nt tiles per ldmatrix
    uint32_t boff[2];
    #pragma unroll
    for (int p = 0; p < 2; p++)
        boff[p] = (uint32_t)(((wn + p * 16 + (jj >> 1) * 8 + rr) * BPW
                              + (jj & 1) * 4) * 4);

    float acc[4][4][4];
    #pragma unroll
    for (int i = 0; i < 4; i++)
        #pragma unroll
        for (int j = 0; j < 4; j++)
            #pragma unroll
            for (int r = 0; r < 4; r++) acc[i][j][r] = 0.f;

    auto issue = [&](int kt, int stage) {
        const int k0 = kt * 32;
        const uint32_t aB = sbA + (uint32_t)stage * ST_AW * 4;
        const uint32_t bB = sbB + (uint32_t)stage * ST_BW * 4;
        #pragma unroll
        for (int j = 0; j < 2; j++) {
            int idx = tid + 256 * j;
            int r = idx >> 2, c8 = (idx & 3) * 8;
            cp16(aB + (uint32_t)(r * APW + (idx & 3) * 4) * 4,
                 &A[(size_t)(row0 + r) * K + k0 + c8]);
        }
        #pragma unroll
        for (int j = 0; j < 2; j++) {
            int idx = tid + 256 * j;
            int r = idx >> 2, c8 = (idx & 3) * 8;
            cp16(bB + (uint32_t)(r * BPW + (idx & 3) * 4) * 4,
                 &Bt[(size_t)(col0 + r) * K + k0 + c8]);
        }
        CP_COMMIT();
    };

    const int ntiles = K / 32;
    issue(0, 0);
    issue(1, 1);

    int stage = 0;
    for (int kt = 0; kt < ntiles; kt++) {
        if (kt + 1 < ntiles) {
            asm volatile("cp.async.wait_group 1;");
        } else {
            asm volatile("cp.async.wait_group 0;");
        }
        __syncthreads();

        if (kt + 2 < ntiles) {
            int s2 = stage + 2; if (s2 >= NSTAGE) s2 -= NSTAGE;
            issue(kt + 2, s2);
        }

        const uint32_t aStage = sbA + (uint32_t)stage * ST_AW * 4;
        const uint32_t bStage = sbB + (uint32_t)stage * ST_BW * 4;

        #pragma unroll
        for (int s = 0; s < 2; s++) {           // two k16 steps; +32B each
            uint32_t af[4][4];
            #pragma unroll
            for (int mt = 0; mt < 4; mt++)
                ldm_x4(af[mt], aStage + aoff[mt] + (uint32_t)s * 32);
            uint32_t bf[4][2];
            #pragma unroll
            for (int p = 0; p < 2; p++) {
                uint32_t t[4];
                ldm_x4(t, bStage + boff[p] + (uint32_t)s * 32);
                bf[2*p][0]   = t[0]; bf[2*p][1]   = t[1];
                bf[2*p+1][0] = t[2]; bf[2*p+1][1] = t[3];
            }
            #pragma unroll
            for (int mt = 0; mt < 4; mt++)
                #pragma unroll
                for (int nt = 0; nt < 4; nt++)
                    mma_f16(acc[mt][nt], af[mt][0], af[mt][1], af[mt][2],
                            af[mt][3], bf[nt][0], bf[nt][1]);
        }

        if (++stage >= NSTAGE) stage = 0;
    }

    // ---- epilogue ----
    const int half = N >> 1;
    #pragma unroll
    for (int mt = 0; mt < 4; mt++) {
        #pragma unroll
        for (int nt = 0; nt < 4; nt++) {
            const int col = col0 + wn + nt * 8 + lc * 2;
            #pragma unroll
            for (int hh = 0; hh < 2; hh++) {
                const int row = row0 + wm + mt * 16 + lr + hh * 8;
                float v0 = acc[mt][nt][hh * 2 + 0];
                float v1 = acc[mt][nt][hh * 2 + 1];
                if (epi == 0) {
                    float2 o;
                    o.x = v0 + bias[col]; o.y = v1 + bias[col + 1];
                    *reinterpret_cast<float2*>(&Cf[(size_t)row * N + col]) = o;
                } else if (epi == 1) {
                    __half2 o = __floats2half2_rn(elu1(v0), elu1(v1));
                    *reinterpret_cast<__half2*>(&Ch[(size_t)row * N + col]) = o;
                } else {
                    if (col < half) {
                        __half2 o = __floats2half2_rn(elu1(v0), elu1(v1));
                        *reinterpret_cast<__half2*>(&Ch[(size_t)row * half + col]) = o;
                    } else {
                        __half2 o = __floats2half2_rn(v0, v1);
                        *reinterpret_cast<__half2*>(&C2h[(size_t)row * half + (col - half)]) = o;
                    }
                }
            }
        }
    }
}

__global__ __launch_bounds__(256, 2)
void gemm12_kernel()
{
    const int bx = blockIdx.x;
    const int row0 = blockIdx.y * 128;
    if (bx < 3) {
        gemm_core(g_xqh, g_wqt, nullptr, g_q, nullptr, nullptr,
                  INNER, DIM, 1, row0, bx * 128);
    } else {
        gemm_core(g_xkvh, g_wkvt, nullptr, g_k, g_v, nullptr,
                  2 * INNER, DIM, 2, row0, (bx - 3) * 128);
    }
}

__global__ __launch_bounds__(256, 2)
void gemm5_kernel(const float* __restrict__ bias, float* __restrict__ out)
{
    gemm_core(g_attn, g_woutt, out, nullptr, nullptr, bias,
              INNER, DIM, 0, blockIdx.y * 128, blockIdx.x * 128);
}

// ---------------------------------------------------------------------------
// kv via tf32 mma (unchanged from 258us baseline).
// ---------------------------------------------------------------------------
#define CHUNK 256
#define KVP 72
__global__ __launch_bounds__(256)
void kv_mma_kernel()
{
    __shared__ uint32_t Kn[32 * KVP];
    __shared__ uint32_t Vs[32 * KVP];
    __shared__ float red[16][64];

    const int bh = blockIdx.x;
    const int b = bh / HEADS, h = bh % HEADS;
    const int n0 = blockIdx.y * CHUNK;

    const int tid  = threadIdx.x;
    const int wid  = tid >> 5;
    const int lane = tid & 31;
    const int wm   = (wid & 1) * 32;
    const int wn   = (wid >> 1) * 16;
    const int lr = lane >> 2;
    const int lc = lane & 3;

    const __half* kbase = g_k + ((size_t)(b * NSEQ + n0)) * INNER + h * DHEAD;
    const __half* vbase = g_v + ((size_t)(b * NSEQ + n0)) * INNER + h * DHEAD;

    float acc[2][2][4];
    #pragma unroll
    for (int i = 0; i < 2; i++)
        #pragma unroll
        for (int j = 0; j < 2; j++)
            #pragma unroll
            for (int r = 0; r < 4; r++) acc[i][j][r] = 0.f;
    float sk[4] = {0.f, 0.f, 0.f, 0.f};

    for (int sub = 0; sub < CHUNK / 32; sub++) {
        const int nn = sub * 32;
        #pragma unroll
        for (int it = 0; it < 2; it++) {
            int idx = tid + it * 256;
            int n = idx >> 4, c4 = (idx & 15) * 4;
            uint2 kraw = *reinterpret_cast<const uint2*>(
                &kbase[(size_t)(nn + n) * INNER + c4]);
            float2 f01 = __half22float2(*reinterpret_cast<__half2*>(&kraw.x));
            float2 f23 = __half22float2(*reinterpret_cast<__half2*>(&kraw.y));
            uint4 ko;
            ko.x = __float_as_uint(f01.x); ko.y = __float_as_uint(f01.y);
            ko.z = __float_as_uint(f23.x); ko.w = __float_as_uint(f23.y);
            *reinterpret_cast<uint4*>(&Kn[n * KVP + c4]) = ko;
            sk[0] += f01.x; sk[1] += f01.y; sk[2] += f23.x; sk[3] += f23.y;
            uint2 vraw = *reinterpret_cast<const uint2*>(
                &vbase[(size_t)(nn + n) * INNER + c4]);
            float2 g01 = __half22float2(*reinterpret_cast<__half2*>(&vraw.x));
            float2 g23 = __half22float2(*reinterpret_cast<__half2*>(&vraw.y));
            uint4 vo;
            vo.x = __float_as_uint(g01.x); vo.y = __float_as_uint(g01.y);
            vo.z = __float_as_uint(g23.x); vo.w = __float_as_uint(g23.y);
            *reinterpret_cast<uint4*>(&Vs[n * KVP + c4]) = vo;
        }
        __syncthreads();

        #pragma unroll
        for (int s = 0; s < 4; s++) {
            const int kk = s * 8;
            uint32_t af[2][4];
            #pragma unroll
            for (int mt = 0; mt < 2; mt++) {
                const int drow = wm + mt * 16 + lr;
                const uint32_t* ap = &Kn[(kk + lc) * KVP + drow];
                af[mt][0] = ap[0];
                af[mt][1] = ap[8];
                af[mt][2] = ap[4 * KVP];
                af[mt][3] = ap[4 * KVP + 8];
            }
            uint32_t bf[2][2];
            #pragma unroll
            for (int nt = 0; nt < 2; nt++) {
                const uint32_t* bp = &Vs[(kk + lc) * KVP + wn + nt * 8 + lr];
                bf[nt][0] = bp[0];
                bf[nt][1] = bp[4 * KVP];
            }
            #pragma unroll
            for (int mt = 0; mt < 2; mt++)
                #pragma unroll
                for (int nt = 0; nt < 2; nt++)
                    mma_tf32(acc[mt][nt], af[mt][0], af[mt][1], af[mt][2],
                             af[mt][3], bf[nt][0], bf[nt][1]);
        }
        __syncthreads();
    }

    {
        const int c4 = (tid & 15) * 4;
        const int grp = tid >> 4;
        #pragma unroll
        for (int j = 0; j < 4; j++) red[grp][c4 + j] = sk[j];
        __syncthreads();
        if (tid < 64) {
            float s = 0.f;
            #pragma unroll
            for (int r = 0; r < 16; r++) s += red[r][tid];
            atomicAdd(&g_ksum[bh * DHEAD + tid], s);
        }
    }

    float* kvp = g_kv + (size_t)bh * DHEAD * DHEAD;
    #pragma unroll
    for (int mt = 0; mt < 2; mt++) {
        #pragma unroll
        for (int nt = 0; nt < 2; nt++) {
            const int col = wn + nt * 8 + lc * 2;
            #pragma unroll
            for (int hh = 0; hh < 2; hh++) {
                const int row = wm + mt * 16 + lr + hh * 8;
                atomicAdd(&kvp[row * DHEAD + col],     acc[mt][nt][hh * 2 + 0]);
                atomicAdd(&kvp[row * DHEAD + col + 1], acc[mt][nt][hh * 2 + 1]);
            }
        }
    }
}

// ---------------------------------------------------------------------------
// attn via tf32 mma (unchanged from 258us baseline).
// ---------------------------------------------------------------------------
#define AQP 68
__global__ __launch_bounds__(256, 5)
void attn_mma_kernel()
{
    __shared__ uint32_t qs [64 * AQP];
    __shared__ uint32_t kvs[64 * KVP];
    __shared__ float ks[64];
    __shared__ float zr[64];

    const int bh = blockIdx.x;
    const int b = bh / HEADS, h = bh % HEADS;
    const int n0 = blockIdx.y * 64;

    const int tid  = threadIdx.x;
    const int wid  = tid >> 5;
    const int lane = tid & 31;
    const int wm   = (wid & 1) * 32;
    const int wn   = (wid >> 1) * 16;
    const int lr = lane >> 2;
    const int lc = lane & 3;

    const __half* qptr = g_q + ((size_t)(b * NSEQ + n0)) * INNER + h * DHEAD;
    #pragma unroll
    for (int j = 0; j < 4; j++) {
        int idx = tid + 256 * j;
        int r = idx >> 4, c4 = (idx & 15) * 4;
        uint2 raw = *reinterpret_cast<const uint2*>(&qptr[(size_t)r * INNER + c4]);
        float2 f01 = __half22float2(*reinterpret_cast<__half2*>(&raw.x));
        float2 f23 = __half22float2(*reinterpret_cast<__half2*>(&raw.y));
        uint4 o;
        o.x = __float_as_uint(f01.x); o.y = __float_as_uint(f01.y);
        o.z = __float_as_uint(f23.x); o.w = __float_as_uint(f23.y);
        *reinterpret_cast<uint4*>(&qs[r * AQP + c4]) = o;
    }
    #pragma unroll
    for (int j = 0; j < 4; j++) {
        int idx = tid + 256 * j;
        int d = idx >> 4, m4 = (idx & 15) * 4;
        float4 v = *reinterpret_cast<const float4*>(&g_kv[(size_t)bh * 4096 + d * 64 + m4]);
        uint4 o;
        o.x = f2tf32(v.x); o.y = f2tf32(v.y);
        o.z = f2tf32(v.z); o.w = f2tf32(v.w);
        *reinterpret_cast<uint4*>(&kvs[d * KVP + m4]) = o;
    }
    if (tid < 64) ks[tid] = g_ksum[bh * 64 + tid];
    __syncthreads();

    if (tid < 64) {
        float s = 0.f;
        #pragma unroll
        for (int dd = 0; dd < 64; dd++)
            s += __uint_as_float(qs[tid * AQP + dd]) * ks[dd];
        zr[tid] = 1.f / (s + 1e-6f);
    }
    __syncthreads();

    float acc[2][2][4];
    #pragma unroll
    for (int i = 0; i < 2; i++)
        #pragma unroll
        for (int j = 0; j < 2; j++)
            #pragma unroll
            for (int r = 0; r < 4; r++) acc[i][j][r] = 0.f;

    #pragma unroll
    for (int s = 0; s < 8; s++) {
        const int kk = s * 8;
        uint32_t af[2][4];
        #pragma unroll
        for (int mt = 0; mt < 2; mt++) {
            const uint32_t* ap = &qs[(wm + mt * 16 + lr) * AQP + kk + lc];
            af[mt][0] = ap[0];
            af[mt][1] = ap[8 * AQP];
            af[mt][2] = ap[4];
            af[mt][3] = ap[8 * AQP + 4];
        }
        uint32_t bf[2][2];
        #pragma unroll
        for (int nt = 0; nt < 2; nt++) {
            const uint32_t* bp = &kvs[(kk + lc) * KVP + wn + nt * 8 + lr];
            bf[nt][0] = bp[0];
            bf[nt][1] = bp[4 * KVP];
        }
        #pragma unroll
        for (int mt = 0; mt < 2; mt++)
            #pragma unroll
            for (int nt = 0; nt < 2; nt++)
                mma_tf32(acc[mt][nt], af[mt][0], af[mt][1], af[mt][2],
                         af[mt][3], bf[nt][0], bf[nt][1]);
    }

    #pragma unroll
    for (int mt = 0; mt < 2; mt++) {
        #pragma unroll
        for (int nt = 0; nt < 2; nt++) {
            const int col = wn + nt * 8 + lc * 2;
            #pragma unroll
            for (int hh = 0; hh < 2; hh++) {
                const int row = wm + mt * 16 + lr + hh * 8;
                const float z = zr[row];
                __half2 o = __floats2half2_rn(acc[mt][nt][hh * 2 + 0] * z,
                                              acc[mt][nt][hh * 2 + 1] * z);
                *reinterpret_cast<__half2*>(
                    &g_attn[((size_t)(b * NSEQ + n0 + row)) * INNER + h * DHEAD + col]) = o;
            }
        }
    }
}

// ---------------------------------------------------------------------------
// Launch order: CVTZ, CVTXQ, CVTXKV, G12 (profiled 4th slot), KV, AT, G5
// ---------------------------------------------------------------------------
extern "C" void kernel_launch(void* const* d_in, const int* in_sizes, int n_in,
                              void* d_out, int out_size)
{
    const float* x_q  = (const float*)d_in[0];
    const float* x_kv = (const float*)d_in[1];
    const float* Wq   = (const float*)d_in[2];
    const float* Wkv  = (const float*)d_in[3];
    const float* Wout = (const float*)d_in[4];
    const float* bout = (const float*)d_in[5];
    float* out = (float*)d_out;

    __half *xqh, *xkvh;
    cudaGetSymbolAddress((void**)&xqh,  g_xqh);
    cudaGetSymbolAddress((void**)&xkvh, g_xkvh);

    cudaFuncSetAttribute((const void*)gemm12_kernel, cudaFuncAttributeMaxDynamicSharedMemorySize, G_SMEM);
    cudaFuncSetAttribute((const void*)gemm5_kernel,  cudaFuncAttributeMaxDynamicSharedMemorySize, G_SMEM);

    dim3 blk(256);

    // 1) weights -> fp16 transposed + zero accumulators
    cvt_w_zero_kernel<<<576, blk>>>(Wq, Wkv, Wout);
    // 2-3) x -> fp16
    cvt_x_kernel<<<1024, blk>>>(x_q,  xqh);
    cvt_x_kernel<<<1024, blk>>>(x_kv, xkvh);

    // 4) merged projections (fp16 mma + ldmatrix)   [profiled slot]
    gemm12_kernel<<<dim3(9, ROWS/128), blk, G_SMEM>>>();

    // 5) kv = k^T v; ksum = sum_n k
    kv_mma_kernel<<<dim3(BATCH*HEADS, NSEQ/CHUNK), blk>>>();

    // 6) attn = (q @ kv) * z
    attn_mma_kernel<<<dim3(BATCH*HEADS, NSEQ/64), blk>>>();

    // 7) out = attn @ Wout + bout (fp32 out)
    gemm5_kernel<<<dim3(INNER/128, ROWS/128), blk, G_SMEM>>>(bout, out);
}

// round 16
// speedup vs baseline: 2.6834x; 1.0410x over previous
#include <cuda_runtime.h>
#include <cuda_fp16.h>
#include <cstdint>

#define BATCH 8
#define NSEQ  4096
#define DIM   384
#define HEADS 6
#define DHEAD 64
#define INNER 384
#define ROWS  (BATCH*NSEQ)   // 32768

// ---- scratch (device globals: no allocation allowed) ----
__device__ __half g_xqh  [ (size_t)ROWS*DIM ];      // x_q  fp16
__device__ __half g_xkvh [ (size_t)ROWS*DIM ];      // x_kv fp16
__device__ __half g_wqt  [ (size_t)INNER*DIM ];     // Wq^T  [n][k] fp16
__device__ __half g_wkvt [ (size_t)2*INNER*DIM ];   // Wkv^T [n][k] fp16
__device__ __half g_woutt[ (size_t)DIM*INNER ];     // Wout^T[n][k] fp16
__device__ __half g_q    [ (size_t)ROWS*INNER ];
__device__ __half g_k    [ (size_t)ROWS*INNER ];
__device__ __half g_v    [ (size_t)ROWS*INNER ];
__device__ __half g_attn [ (size_t)ROWS*INNER ];
__device__ float  g_kv   [ BATCH*HEADS*DHEAD*DHEAD ];
__device__ float  g_ksum [ BATCH*HEADS*DHEAD ];

__device__ __forceinline__ float elu1(float x) {
    return x > 0.f ? x + 1.f : __expf(x);
}

__device__ __forceinline__ uint32_t f2tf32(float x) {
    uint32_t u;
    asm("cvt.rna.tf32.f32 %0, %1;" : "=r"(u) : "f"(x));
    return u;
}

__device__ __forceinline__ uint32_t smem_u32(const void* p) {
    uint32_t a;
    asm("{ .reg .u64 t; cvta.to.shared.u64 t, %1; cvt.u32.u64 %0, t; }"
        : "=r"(a) : "l"(p));
    return a;
}
__device__ __forceinline__ void cp16(uint32_t dst, const void* src) {
    asm volatile("cp.async.cg.shared.global [%0], [%1], 16;"
                 :: "r"(dst), "l"(src));
}
#define CP_COMMIT() asm volatile("cp.async.commit_group;")

__device__ __forceinline__ void ldm_x4(uint32_t* r, uint32_t addr) {
    asm volatile("ldmatrix.sync.aligned.m8n8.x4.shared.b16 {%0,%1,%2,%3}, [%4];"
                 : "=r"(r[0]), "=r"(r[1]), "=r"(r[2]), "=r"(r[3])
                 : "r"(addr));
}

__device__ __forceinline__ void mma_tf32(float c[4], uint32_t a0, uint32_t a1,
                                         uint32_t a2, uint32_t a3,
                                         uint32_t b0, uint32_t b1) {
    asm volatile(
        "mma.sync.aligned.m16n8k8.row.col.f32.tf32.tf32.f32 "
        "{%0,%1,%2,%3}, {%4,%5,%6,%7}, {%8,%9}, {%0,%1,%2,%3};"
        : "+f"(c[0]), "+f"(c[1]), "+f"(c[2]), "+f"(c[3])
        : "r"(a0), "r"(a1), "r"(a2), "r"(a3), "r"(b0), "r"(b1));
}

__device__ __forceinline__ void mma_f16(float c[4], uint32_t a0, uint32_t a1,
                                        uint32_t a2, uint32_t a3,
                                        uint32_t b0, uint32_t b1) {
    asm volatile(
        "mma.sync.aligned.m16n8k16.row.col.f32.f16.f16.f32 "
        "{%0,%1,%2,%3}, {%4,%5,%6,%7}, {%8,%9}, {%0,%1,%2,%3};"
        : "+f"(c[0]), "+f"(c[1]), "+f"(c[2]), "+f"(c[3])
        : "r"(a0), "r"(a1), "r"(a2), "r"(a3), "r"(b0), "r"(b1));
}

// ---------------------------------------------------------------------------
// Single prep kernel: weights -> fp16 transposed; x_q/x_kv -> fp16; zero accs.
// ---------------------------------------------------------------------------
__global__ void prep_kernel(const float* __restrict__ xq,
                            const float* __restrict__ xkv,
                            const float* __restrict__ wq,
                            const float* __restrict__ wkv,
                            const float* __restrict__ wout)
{
    const int nx = ROWS * DIM / 8;            // per x tensor (uint4 granules)
    const int n1 = DIM*INNER, n2 = DIM*2*INNER, n3 = INNER*DIM;
    const int nw = n1 + n2 + n3;
    const int nz = BATCH*HEADS*DHEAD*DHEAD/4;
    const int nz2 = BATCH*HEADS*DHEAD/4;
    const int total = 2 * nx + nw + nz + nz2;
    const float4 z4 = make_float4(0.f, 0.f, 0.f, 0.f);

    for (int i = blockIdx.x * blockDim.x + threadIdx.x; i < total;
         i += gridDim.x * blockDim.x) {
        if (i < 2 * nx) {
            const float* s = (i < nx) ? xq : xkv;
            __half* d = (i < nx) ? g_xqh : g_xkvh;
            int j = (i < nx) ? i : i - nx;
            float4 a = reinterpret_cast<const float4*>(s)[2*j];
            float4 b = reinterpret_cast<const float4*>(s)[2*j + 1];
            __half2 h0 = __floats2half2_rn(a.x, a.y);
            __half2 h1 = __floats2half2_rn(a.z, a.w);
            __half2 h2 = __floats2half2_rn(b.x, b.y);
            __half2 h3 = __floats2half2_rn(b.z, b.w);
            uint4 o;
            o.x = *reinterpret_cast<uint32_t*>(&h0);
            o.y = *reinterpret_cast<uint32_t*>(&h1);
            o.z = *reinterpret_cast<uint32_t*>(&h2);
            o.w = *reinterpret_cast<uint32_t*>(&h3);
            reinterpret_cast<uint4*>(d)[j] = o;
        } else if (i < 2 * nx + nw) {
            int t = i - 2 * nx;
            const float* s; __half* d; int j, Nn;
            if (t < n1)           { s = wq;   d = g_wqt;   j = t;           Nn = INNER; }
            else if (t < n1 + n2) { s = wkv;  d = g_wkvt;  j = t - n1;      Nn = 2*INNER; }
            else                  { s = wout; d = g_woutt; j = t - n1 - n2; Nn = DIM; }
            int k = j / Nn, n = j % Nn;
            d[(size_t)n * DIM + k] = __float2half(s[j]);
        } else if (i < 2 * nx + nw + nz) {
            reinterpret_cast<float4*>(g_kv)[i - 2*nx - nw] = z4;
        } else {
            reinterpret_cast<float4*>(g_ksum)[i - 2*nx - nw - nz] = z4;
        }
    }
}

// ============================================================================
// fp16 mma.sync GEMM core: cp.async 3-stage ring, BK=64 (ONE barrier per
// 64-k-tile: half the syncs of BK=32), ldmatrix.x4 fragment loads.
// A fp16 [m][k], B fp16 pre-transposed [n][k].
// CTA tile 128x128, 256 thr (8 warps, warp tile 64x32).
// epi 0: +bias -> fp32 out; epi 1: elu1 -> fp16; epi 2: N-split -> fp16/fp16.
// ============================================================================
#define NSTAGE 3
#define APW 36                 // pitch words (72 halves: 64 data + 8 pad)
#define BPW 36
#define ST_AW (128*APW)
#define ST_BW (128*BPW)
#define G_SMEM (NSTAGE*(ST_AW + ST_BW)*4)   // 110592

__device__ __forceinline__ void gemm_core(
    const __half* __restrict__ A, const __half* __restrict__ Bt,
    float* __restrict__ Cf, __half* __restrict__ Ch, __half* __restrict__ C2h,
    const float* __restrict__ bias, int N, int K, int epi,
    int row0, int col0)
{
    extern __shared__ uint32_t dsm[];
    uint32_t* As = dsm;
    uint32_t* Bs = dsm + NSTAGE * ST_AW;
    const uint32_t sbA = smem_u32(As);
    const uint32_t sbB = smem_u32(Bs);

    const int tid  = threadIdx.x;
    const int wid  = tid >> 5;
    const int lane = tid & 31;
    const int wm   = (wid & 1) * 64;
    const int wn   = (wid >> 1) * 32;
    const int lr = lane >> 2;
    const int lc = lane & 3;

    const int jj = lane >> 3;
    const int rr = lane & 7;
    uint32_t aoff[4];
    #pragma unroll
    for (int mt = 0; mt < 4; mt++)
        aoff[mt] = (uint32_t)(((wm + mt * 16 + (jj & 1) * 8 + rr) * APW
                               + (jj >> 1) * 4) * 4);
    uint32_t boff[2];
    #pragma unroll
    for (int p = 0; p < 2; p++)
        boff[p] = (uint32_t)(((wn + p * 16 + (jj >> 1) * 8 + rr) * BPW
                              + (jj & 1) * 4) * 4);

    float acc[4][4][4];
    #pragma unroll
    for (int i = 0; i < 4; i++)
        #pragma unroll
        for (int j = 0; j < 4; j++)
            #pragma unroll
            for (int r = 0; r < 4; r++) acc[i][j][r] = 0.f;

    // one 64-k tile: 128 rows x 64 halves = 1024 cp16 per operand
    auto issue = [&](int kt, int stage) {
        const int k0 = kt * 64;
        const uint32_t aB = sbA + (uint32_t)stage * ST_AW * 4;
        const uint32_t bB = sbB + (uint32_t)stage * ST_BW * 4;
        #pragma unroll
        for (int j = 0; j < 4; j++) {
            int idx = tid + 256 * j;
            int r = idx >> 3, c8 = (idx & 7) * 8;
            cp16(aB + (uint32_t)(r * APW + (idx & 7) * 4) * 4,
                 &A[(size_t)(row0 + r) * K + k0 + c8]);
        }
        #pragma unroll
        for (int j = 0; j < 4; j++) {
            int idx = tid + 256 * j;
            int r = idx >> 3, c8 = (idx & 7) * 8;
            cp16(bB + (uint32_t)(r * BPW + (idx & 7) * 4) * 4,
                 &Bt[(size_t)(col0 + r) * K + k0 + c8]);
        }
        CP_COMMIT();
    };

    const int ntiles = K / 64;   // K=384 -> 6
    issue(0, 0);
    issue(1, 1);

    int stage = 0;
    for (int kt = 0; kt < ntiles; kt++) {
        if (kt + 1 < ntiles) {
            asm volatile("cp.async.wait_group 1;");
        } else {
            asm volatile("cp.async.wait_group 0;");
        }
        __syncthreads();

        if (kt + 2 < ntiles) {
            int s2 = stage + 2; if (s2 >= NSTAGE) s2 -= NSTAGE;
            issue(kt + 2, s2);
        }

        const uint32_t aStage = sbA + (uint32_t)stage * ST_AW * 4;
        const uint32_t bStage = sbB + (uint32_t)stage * ST_BW * 4;

        #pragma unroll
        for (int s = 0; s < 4; s++) {           // four k16 steps; +32B each
            uint32_t af[4][4];
            #pragma unroll
            for (int mt = 0; mt < 4; mt++)
                ldm_x4(af[mt], aStage + aoff[mt] + (uint32_t)s * 32);
            uint32_t bf[4][2];
            #pragma unroll
            for (int p = 0; p < 2; p++) {
                uint32_t t[4];
                ldm_x4(t, bStage + boff[p] + (uint32_t)s * 32);
                bf[2*p][0]   = t[0]; bf[2*p][1]   = t[1];
                bf[2*p+1][0] = t[2]; bf[2*p+1][1] = t[3];
            }
            #pragma unroll
            for (int mt = 0; mt < 4; mt++)
                #pragma unroll
                for (int nt = 0; nt < 4; nt++)
                    mma_f16(acc[mt][nt], af[mt][0], af[mt][1], af[mt][2],
                            af[mt][3], bf[nt][0], bf[nt][1]);
        }

        if (++stage >= NSTAGE) stage = 0;
    }

    // ---- epilogue ----
    const int half = N >> 1;
    #pragma unroll
    for (int mt = 0; mt < 4; mt++) {
        #pragma unroll
        for (int nt = 0; nt < 4; nt++) {
            const int col = col0 + wn + nt * 8 + lc * 2;
            #pragma unroll
            for (int hh = 0; hh < 2; hh++) {
                const int row = row0 + wm + mt * 16 + lr + hh * 8;
                float v0 = acc[mt][nt][hh * 2 + 0];
                float v1 = acc[mt][nt][hh * 2 + 1];
                if (epi == 0) {
                    float2 o;
                    o.x = v0 + bias[col]; o.y = v1 + bias[col + 1];
                    *reinterpret_cast<float2*>(&Cf[(size_t)row * N + col]) = o;
                } else if (epi == 1) {
                    __half2 o = __floats2half2_rn(elu1(v0), elu1(v1));
                    *reinterpret_cast<__half2*>(&Ch[(size_t)row * N + col]) = o;
                } else {
                    if (col < half) {
                        __half2 o = __floats2half2_rn(elu1(v0), elu1(v1));
                        *reinterpret_cast<__half2*>(&Ch[(size_t)row * half + col]) = o;
                    } else {
                        __half2 o = __floats2half2_rn(v0, v1);
                        *reinterpret_cast<__half2*>(&C2h[(size_t)row * half + (col - half)]) = o;
                    }
                }
            }
        }
    }
}

__global__ __launch_bounds__(256, 2)
void gemm12_kernel()
{
    const int bx = blockIdx.x;
    const int row0 = blockIdx.y * 128;
    if (bx < 3) {
        gemm_core(g_xqh, g_wqt, nullptr, g_q, nullptr, nullptr,
                  INNER, DIM, 1, row0, bx * 128);
    } else {
        gemm_core(g_xkvh, g_wkvt, nullptr, g_k, g_v, nullptr,
                  2 * INNER, DIM, 2, row0, (bx - 3) * 128);
    }
}

__global__ __launch_bounds__(256, 2)
void gemm5_kernel(const float* __restrict__ bias, float* __restrict__ out)
{
    gemm_core(g_attn, g_woutt, out, nullptr, nullptr, bias,
              INNER, DIM, 0, blockIdx.y * 128, blockIdx.x * 128);
}

// ---------------------------------------------------------------------------
// kv via tf32 mma (unchanged from 226us baseline).
// ---------------------------------------------------------------------------
#define CHUNK 256
#define KVP 72
__global__ __launch_bounds__(256)
void kv_mma_kernel()
{
    __shared__ uint32_t Kn[32 * KVP];
    __shared__ uint32_t Vs[32 * KVP];
    __shared__ float red[16][64];

    const int bh = blockIdx.x;
    const int b = bh / HEADS, h = bh % HEADS;
    const int n0 = blockIdx.y * CHUNK;

    const int tid  = threadIdx.x;
    const int wid  = tid >> 5;
    const int lane = tid & 31;
    const int wm   = (wid & 1) * 32;
    const int wn   = (wid >> 1) * 16;
    const int lr = lane >> 2;
    const int lc = lane & 3;

    const __half* kbase = g_k + ((size_t)(b * NSEQ + n0)) * INNER + h * DHEAD;
    const __half* vbase = g_v + ((size_t)(b * NSEQ + n0)) * INNER + h * DHEAD;

    float acc[2][2][4];
    #pragma unroll
    for (int i = 0; i < 2; i++)
        #pragma unroll
        for (int j = 0; j < 2; j++)
            #pragma unroll
            for (int r = 0; r < 4; r++) acc[i][j][r] = 0.f;
    float sk[4] = {0.f, 0.f, 0.f, 0.f};

    for (int sub = 0; sub < CHUNK / 32; sub++) {
        const int nn = sub * 32;
        #pragma unroll
        for (int it = 0; it < 2; it++) {
            int idx = tid + it * 256;
            int n = idx >> 4, c4 = (idx & 15) * 4;
            uint2 kraw = *reinterpret_cast<const uint2*>(
                &kbase[(size_t)(nn + n) * INNER + c4]);
            float2 f01 = __half22float2(*reinterpret_cast<__half2*>(&kraw.x));
            float2 f23 = __half22float2(*reinterpret_cast<__half2*>(&kraw.y));
            uint4 ko;
            ko.x = __float_as_uint(f01.x); ko.y = __float_as_uint(f01.y);
            ko.z = __float_as_uint(f23.x); ko.w = __float_as_uint(f23.y);
            *reinterpret_cast<uint4*>(&Kn[n * KVP + c4]) = ko;
            sk[0] += f01.x; sk[1] += f01.y; sk[2] += f23.x; sk[3] += f23.y;
            uint2 vraw = *reinterpret_cast<const uint2*>(
                &vbase[(size_t)(nn + n) * INNER + c4]);
            float2 g01 = __half22float2(*reinterpret_cast<__half2*>(&vraw.x));
            float2 g23 = __half22float2(*reinterpret_cast<__half2*>(&vraw.y));
            uint4 vo;
            vo.x = __float_as_uint(g01.x); vo.y = __float_as_uint(g01.y);
            vo.z = __float_as_uint(g23.x); vo.w = __float_as_uint(g23.y);
            *reinterpret_cast<uint4*>(&Vs[n * KVP + c4]) = vo;
        }
        __syncthreads();

        #pragma unroll
        for (int s = 0; s < 4; s++) {
            const int kk = s * 8;
            uint32_t af[2][4];
            #pragma unroll
            for (int mt = 0; mt < 2; mt++) {
                const int drow = wm + mt * 16 + lr;
                const uint32_t* ap = &Kn[(kk + lc) * KVP + drow];
                af[mt][0] = ap[0];
                af[mt][1] = ap[8];
                af[mt][2] = ap[4 * KVP];
                af[mt][3] = ap[4 * KVP + 8];
            }
            uint32_t bf[2][2];
            #pragma unroll
            for (int nt = 0; nt < 2; nt++) {
                const uint32_t* bp = &Vs[(kk + lc) * KVP + wn + nt * 8 + lr];
                bf[nt][0] = bp[0];
                bf[nt][1] = bp[4 * KVP];
            }
            #pragma unroll
            for (int mt = 0; mt < 2; mt++)
                #pragma unroll
                for (int nt = 0; nt < 2; nt++)
                    mma_tf32(acc[mt][nt], af[mt][0], af[mt][1], af[mt][2],
                             af[mt][3], bf[nt][0], bf[nt][1]);
        }
        __syncthreads();
    }

    {
        const int c4 = (tid & 15) * 4;
        const int grp = tid >> 4;
        #pragma unroll
        for (int j = 0; j < 4; j++) red[grp][c4 + j] = sk[j];
        __syncthreads();
        if (tid < 64) {
            float s = 0.f;
            #pragma unroll
            for (int r = 0; r < 16; r++) s += red[r][tid];
            atomicAdd(&g_ksum[bh * DHEAD + tid], s);
        }
    }

    float* kvp = g_kv + (size_t)bh * DHEAD * DHEAD;
    #pragma unroll
    for (int mt = 0; mt < 2; mt++) {
        #pragma unroll
        for (int nt = 0; nt < 2; nt++) {
            const int col = wn + nt * 8 + lc * 2;
            #pragma unroll
            for (int hh = 0; hh < 2; hh++) {
                const int row = wm + mt * 16 + lr + hh * 8;
                atomicAdd(&kvp[row * DHEAD + col],     acc[mt][nt][hh * 2 + 0]);
                atomicAdd(&kvp[row * DHEAD + col + 1], acc[mt][nt][hh * 2 + 1]);
            }
        }
    }
}

// ---------------------------------------------------------------------------
// attn via tf32 mma (unchanged from 226us baseline).
// ---------------------------------------------------------------------------
#define AQP 68
__global__ __launch_bounds__(256, 5)
void attn_mma_kernel()
{
    __shared__ uint32_t qs [64 * AQP];
    __shared__ uint32_t kvs[64 * KVP];
    __shared__ float ks[64];
    __shared__ float zr[64];

    const int bh = blockIdx.x;
    const int b = bh / HEADS, h = bh % HEADS;
    const int n0 = blockIdx.y * 64;

    const int tid  = threadIdx.x;
    const int wid  = tid >> 5;
    const int lane = tid & 31;
    const int wm   = (wid & 1) * 32;
    const int wn   = (wid >> 1) * 16;
    const int lr = lane >> 2;
    const int lc = lane & 3;

    const __half* qptr = g_q + ((size_t)(b * NSEQ + n0)) * INNER + h * DHEAD;
    #pragma unroll
    for (int j = 0; j < 4; j++) {
        int idx = tid + 256 * j;
        int r = idx >> 4, c4 = (idx & 15) * 4;
        uint2 raw = *reinterpret_cast<const uint2*>(&qptr[(size_t)r * INNER + c4]);
        float2 f01 = __half22float2(*reinterpret_cast<__half2*>(&raw.x));
        float2 f23 = __half22float2(*reinterpret_cast<__half2*>(&raw.y));
        uint4 o;
        o.x = __float_as_uint(f01.x); o.y = __float_as_uint(f01.y);
        o.z = __float_as_uint(f23.x); o.w = __float_as_uint(f23.y);
        *reinterpret_cast<uint4*>(&qs[r * AQP + c4]) = o;
    }
    #pragma unroll
    for (int j = 0; j < 4; j++) {
        int idx = tid + 256 * j;
        int d = idx >> 4, m4 = (idx & 15) * 4;
        float4 v = *reinterpret_cast<const float4*>(&g_kv[(size_t)bh * 4096 + d * 64 + m4]);
        uint4 o;
        o.x = f2tf32(v.x); o.y = f2tf32(v.y);
        o.z = f2tf32(v.z); o.w = f2tf32(v.w);
        *reinterpret_cast<uint4*>(&kvs[d * KVP + m4]) = o;
    }
    if (tid < 64) ks[tid] = g_ksum[bh * 64 + tid];
    __syncthreads();

    if (tid < 64) {
        float s = 0.f;
        #pragma unroll
        for (int dd = 0; dd < 64; dd++)
            s += __uint_as_float(qs[tid * AQP + dd]) * ks[dd];
        zr[tid] = 1.f / (s + 1e-6f);
    }
    __syncthreads();

    float acc[2][2][4];
    #pragma unroll
    for (int i = 0; i < 2; i++)
        #pragma unroll
        for (int j = 0; j < 2; j++)
            #pragma unroll
            for (int r = 0; r < 4; r++) acc[i][j][r] = 0.f;

    #pragma unroll
    for (int s = 0; s < 8; s++) {
        const int kk = s * 8;
        uint32_t af[2][4];
        #pragma unroll
        for (int mt = 0; mt < 2; mt++) {
            const uint32_t* ap = &qs[(wm + mt * 16 + lr) * AQP + kk + lc];
            af[mt][0] = ap[0];
            af[mt][1] = ap[8 * AQP];
            af[mt][2] = ap[4];
            af[mt][3] = ap[8 * AQP + 4];
        }
        uint32_t bf[2][2];
        #pragma unroll
        for (int nt = 0; nt < 2; nt++) {
            const uint32_t* bp = &kvs[(kk + lc) * KVP + wn + nt * 8 + lr];
            bf[nt][0] = bp[0];
            bf[nt][1] = bp[4 * KVP];
        }
        #pragma unroll
        for (int mt = 0; mt < 2; mt++)
            #pragma unroll
            for (int nt = 0; nt < 2; nt++)
                mma_tf32(acc[mt][nt], af[mt][0], af[mt][1], af[mt][2],
                         af[mt][3], bf[nt][0], bf[nt][1]);
    }

    #pragma unroll
    for (int mt = 0; mt < 2; mt++) {
        #pragma unroll
        for (int nt = 0; nt < 2; nt++) {
            const int col = wn + nt * 8 + lc * 2;
            #pragma unroll
            for (int hh = 0; hh < 2; hh++) {
                const int row = wm + mt * 16 + lr + hh * 8;
                const float z = zr[row];
                __half2 o = __floats2half2_rn(acc[mt][nt][hh * 2 + 0] * z,
                                              acc[mt][nt][hh * 2 + 1] * z);
                *reinterpret_cast<__half2*>(
                    &g_attn[((size_t)(b * NSEQ + n0 + row)) * INNER + h * DHEAD + col]) = o;
            }
        }
    }
}

// ---------------------------------------------------------------------------
// Launch order: PREP, G12, KV, AT, G5
// ---------------------------------------------------------------------------
extern "C" void kernel_launch(void* const* d_in, const int* in_sizes, int n_in,
                              void* d_out, int out_size)
{
    const float* x_q  = (const float*)d_in[0];
    const float* x_kv = (const float*)d_in[1];
    const float* Wq   = (const float*)d_in[2];
    const float* Wkv  = (const float*)d_in[3];
    const float* Wout = (const float*)d_in[4];
    const float* bout = (const float*)d_in[5];
    float* out = (float*)d_out;

    cudaFuncSetAttribute((const void*)gemm12_kernel, cudaFuncAttributeMaxDynamicSharedMemorySize, G_SMEM);
    cudaFuncSetAttribute((const void*)gemm5_kernel,  cudaFuncAttributeMaxDynamicSharedMemorySize, G_SMEM);

    dim3 blk(256);

    // 1) prep: x->fp16, weights->fp16^T, zero accumulators (single launch)
    prep_kernel<<<2048, blk>>>(x_q, x_kv, Wq, Wkv, Wout);

    // 2) merged projections (fp16 mma + ldmatrix, BK=64)
    gemm12_kernel<<<dim3(9, ROWS/128), blk, G_SMEM>>>();

    // 3) kv = k^T v; ksum = sum_n k
    kv_mma_kernel<<<dim3(BATCH*HEADS, NSEQ/CHUNK), blk>>>();

    // 4) attn = (q @ kv) * z
    attn_mma_kernel<<<dim3(BATCH*HEADS, NSEQ/64), blk>>>();

    // 5) out = attn @ Wout + bout (fp32 out)
    gemm5_kernel<<<dim3(INNER/128, ROWS/128), blk, G_SMEM>>>(bout, out);
}

// round 17
// speedup vs baseline: 2.8172x; 1.0499x over previous
#include <cuda_runtime.h>
#include <cuda_fp16.h>
#include <cstdint>

#define BATCH 8
#define NSEQ  4096
#define DIM   384
#define HEADS 6
#define DHEAD 64
#define INNER 384
#define ROWS  (BATCH*NSEQ)   // 32768

// ---- scratch (device globals: no allocation allowed) ----
__device__ __half g_xqh  [ (size_t)ROWS*DIM ];
__device__ __half g_xkvh [ (size_t)ROWS*DIM ];
__device__ __half g_wqt  [ (size_t)INNER*DIM ];
__device__ __half g_wkvt [ (size_t)2*INNER*DIM ];
__device__ __half g_woutt[ (size_t)DIM*INNER ];
__device__ __half g_q    [ (size_t)ROWS*INNER ];
__device__ __half g_k    [ (size_t)ROWS*INNER ];
__device__ __half g_v    [ (size_t)ROWS*INNER ];
__device__ __half g_attn [ (size_t)ROWS*INNER ];
__device__ float  g_kv   [ BATCH*HEADS*DHEAD*DHEAD ];
__device__ float  g_ksum [ BATCH*HEADS*DHEAD ];

__device__ __forceinline__ float elu1(float x) {
    return x > 0.f ? x + 1.f : __expf(x);
}

__device__ __forceinline__ uint32_t smem_u32(const void* p) {
    uint32_t a;
    asm("{ .reg .u64 t; cvta.to.shared.u64 t, %1; cvt.u32.u64 %0, t; }"
        : "=r"(a) : "l"(p));
    return a;
}
__device__ __forceinline__ void cp16(uint32_t dst, const void* src) {
    asm volatile("cp.async.cg.shared.global [%0], [%1], 16;"
                 :: "r"(dst), "l"(src));
}
#define CP_COMMIT() asm volatile("cp.async.commit_group;")

__device__ __forceinline__ void ldm_x4(uint32_t* r, uint32_t addr) {
    asm volatile("ldmatrix.sync.aligned.m8n8.x4.shared.b16 {%0,%1,%2,%3}, [%4];"
                 : "=r"(r[0]), "=r"(r[1]), "=r"(r[2]), "=r"(r[3])
                 : "r"(addr));
}
__device__ __forceinline__ void ldm_x4_t(uint32_t* r, uint32_t addr) {
    asm volatile("ldmatrix.sync.aligned.m8n8.x4.trans.shared.b16 {%0,%1,%2,%3}, [%4];"
                 : "=r"(r[0]), "=r"(r[1]), "=r"(r[2]), "=r"(r[3])
                 : "r"(addr));
}

__device__ __forceinline__ void mma_f16(float c[4], uint32_t a0, uint32_t a1,
                                        uint32_t a2, uint32_t a3,
                                        uint32_t b0, uint32_t b1) {
    asm volatile(
        "mma.sync.aligned.m16n8k16.row.col.f32.f16.f16.f32 "
        "{%0,%1,%2,%3}, {%4,%5,%6,%7}, {%8,%9}, {%0,%1,%2,%3};"
        : "+f"(c[0]), "+f"(c[1]), "+f"(c[2]), "+f"(c[3])
        : "r"(a0), "r"(a1), "r"(a2), "r"(a3), "r"(b0), "r"(b1));
}

// ---------------------------------------------------------------------------
// Single prep kernel (unchanged from 217us baseline).
// ---------------------------------------------------------------------------
__global__ void prep_kernel(const float* __restrict__ xq,
                            const float* __restrict__ xkv,
                            const float* __restrict__ wq,
                            const float* __restrict__ wkv,
                            const float* __restrict__ wout)
{
    const int nx = ROWS * DIM / 8;
    const int n1 = DIM*INNER, n2 = DIM*2*INNER, n3 = INNER*DIM;
    const int nw = n1 + n2 + n3;
    const int nz = BATCH*HEADS*DHEAD*DHEAD/4;
    const int nz2 = BATCH*HEADS*DHEAD/4;
    const int total = 2 * nx + nw + nz + nz2;
    const float4 z4 = make_float4(0.f, 0.f, 0.f, 0.f);

    for (int i = blockIdx.x * blockDim.x + threadIdx.x; i < total;
         i += gridDim.x * blockDim.x) {
        if (i < 2 * nx) {
            const float* s = (i < nx) ? xq : xkv;
            __half* d = (i < nx) ? g_xqh : g_xkvh;
            int j = (i < nx) ? i : i - nx;
            float4 a = reinterpret_cast<const float4*>(s)[2*j];
            float4 b = reinterpret_cast<const float4*>(s)[2*j + 1];
            __half2 h0 = __floats2half2_rn(a.x, a.y);
            __half2 h1 = __floats2half2_rn(a.z, a.w);
            __half2 h2 = __floats2half2_rn(b.x, b.y);
            __half2 h3 = __floats2half2_rn(b.z, b.w);
            uint4 o;
            o.x = *reinterpret_cast<uint32_t*>(&h0);
            o.y = *reinterpret_cast<uint32_t*>(&h1);
            o.z = *reinterpret_cast<uint32_t*>(&h2);
            o.w = *reinterpret_cast<uint32_t*>(&h3);
            reinterpret_cast<uint4*>(d)[j] = o;
        } else if (i < 2 * nx + nw) {
            int t = i - 2 * nx;
            const float* s; __half* d; int j, Nn;
            if (t < n1)           { s = wq;   d = g_wqt;   j = t;           Nn = INNER; }
            else if (t < n1 + n2) { s = wkv;  d = g_wkvt;  j = t - n1;      Nn = 2*INNER; }
            else                  { s = wout; d = g_woutt; j = t - n1 - n2; Nn = DIM; }
            int k = j / Nn, n = j % Nn;
            d[(size_t)n * DIM + k] = __float2half(s[j]);
        } else if (i < 2 * nx + nw + nz) {
            reinterpret_cast<float4*>(g_kv)[i - 2*nx - nw] = z4;
        } else {
            reinterpret_cast<float4*>(g_ksum)[i - 2*nx - nw - nz] = z4;
        }
    }
}

// ============================================================================
// fp16 mma GEMM core (unchanged from 217us baseline: BK=64, 3-stage ring).
// ============================================================================
#define NSTAGE 3
#define APW 36
#define BPW 36
#define ST_AW (128*APW)
#define ST_BW (128*BPW)
#define G_SMEM (NSTAGE*(ST_AW + ST_BW)*4)   // 110592

__device__ __forceinline__ void gemm_core(
    const __half* __restrict__ A, const __half* __restrict__ Bt,
    float* __restrict__ Cf, __half* __restrict__ Ch, __half* __restrict__ C2h,
    const float* __restrict__ bias, int N, int K, int epi,
    int row0, int col0)
{
    extern __shared__ uint32_t dsm[];
    uint32_t* As = dsm;
    uint32_t* Bs = dsm + NSTAGE * ST_AW;
    const uint32_t sbA = smem_u32(As);
    const uint32_t sbB = smem_u32(Bs);

    const int tid  = threadIdx.x;
    const int wid  = tid >> 5;
    const int lane = tid & 31;
    const int wm   = (wid & 1) * 64;
    const int wn   = (wid >> 1) * 32;
    const int lr = lane >> 2;
    const int lc = lane & 3;

    const int jj = lane >> 3;
    const int rr = lane & 7;
    uint32_t aoff[4];
    #pragma unroll
    for (int mt = 0; mt < 4; mt++)
        aoff[mt] = (uint32_t)(((wm + mt * 16 + (jj & 1) * 8 + rr) * APW
                               + (jj >> 1) * 4) * 4);
    uint32_t boff[2];
    #pragma unroll
    for (int p = 0; p < 2; p++)
        boff[p] = (uint32_t)(((wn + p * 16 + (jj >> 1) * 8 + rr) * BPW
                              + (jj & 1) * 4) * 4);

    float acc[4][4][4];
    #pragma unroll
    for (int i = 0; i < 4; i++)
        #pragma unroll
        for (int j = 0; j < 4; j++)
            #pragma unroll
            for (int r = 0; r < 4; r++) acc[i][j][r] = 0.f;

    auto issue = [&](int kt, int stage) {
        const int k0 = kt * 64;
        const uint32_t aB = sbA + (uint32_t)stage * ST_AW * 4;
        const uint32_t bB = sbB + (uint32_t)stage * ST_BW * 4;
        #pragma unroll
        for (int j = 0; j < 4; j++) {
            int idx = tid + 256 * j;
            int r = idx >> 3, c8 = (idx & 7) * 8;
            cp16(aB + (uint32_t)(r * APW + (idx & 7) * 4) * 4,
                 &A[(size_t)(row0 + r) * K + k0 + c8]);
        }
        #pragma unroll
        for (int j = 0; j < 4; j++) {
            int idx = tid + 256 * j;
            int r = idx >> 3, c8 = (idx & 7) * 8;
            cp16(bB + (uint32_t)(r * BPW + (idx & 7) * 4) * 4,
                 &Bt[(size_t)(col0 + r) * K + k0 + c8]);
        }
        CP_COMMIT();
    };

    const int ntiles = K / 64;
    issue(0, 0);
    issue(1, 1);

    int stage = 0;
    for (int kt = 0; kt < ntiles; kt++) {
        if (kt + 1 < ntiles) {
            asm volatile("cp.async.wait_group 1;");
        } else {
            asm volatile("cp.async.wait_group 0;");
        }
        __syncthreads();

        if (kt + 2 < ntiles) {
            int s2 = stage + 2; if (s2 >= NSTAGE) s2 -= NSTAGE;
            issue(kt + 2, s2);
        }

        const uint32_t aStage = sbA + (uint32_t)stage * ST_AW * 4;
        const uint32_t bStage = sbB + (uint32_t)stage * ST_BW * 4;

        #pragma unroll
        for (int s = 0; s < 4; s++) {
            uint32_t af[4][4];
            #pragma unroll
            for (int mt = 0; mt < 4; mt++)
                ldm_x4(af[mt], aStage + aoff[mt] + (uint32_t)s * 32);
            uint32_t bf[4][2];
            #pragma unroll
            for (int p = 0; p < 2; p++) {
                uint32_t t[4];
                ldm_x4(t, bStage + boff[p] + (uint32_t)s * 32);
                bf[2*p][0]   = t[0]; bf[2*p][1]   = t[1];
                bf[2*p+1][0] = t[2]; bf[2*p+1][1] = t[3];
            }
            #pragma unroll
            for (int mt = 0; mt < 4; mt++)
                #pragma unroll
                for (int nt = 0; nt < 4; nt++)
                    mma_f16(acc[mt][nt], af[mt][0], af[mt][1], af[mt][2],
                            af[mt][3], bf[nt][0], bf[nt][1]);
        }

        if (++stage >= NSTAGE) stage = 0;
    }

    const int half = N >> 1;
    #pragma unroll
    for (int mt = 0; mt < 4; mt++) {
        #pragma unroll
        for (int nt = 0; nt < 4; nt++) {
            const int col = col0 + wn + nt * 8 + lc * 2;
            #pragma unroll
            for (int hh = 0; hh < 2; hh++) {
                const int row = row0 + wm + mt * 16 + lr + hh * 8;
                float v0 = acc[mt][nt][hh * 2 + 0];
                float v1 = acc[mt][nt][hh * 2 + 1];
                if (epi == 0) {
                    float2 o;
                    o.x = v0 + bias[col]; o.y = v1 + bias[col + 1];
                    *reinterpret_cast<float2*>(&Cf[(size_t)row * N + col]) = o;
                } else if (epi == 1) {
                    __half2 o = __floats2half2_rn(elu1(v0), elu1(v1));
                    *reinterpret_cast<__half2*>(&Ch[(size_t)row * N + col]) = o;
                } else {
                    if (col < half) {
                        __half2 o = __floats2half2_rn(elu1(v0), elu1(v1));
                        *reinterpret_cast<__half2*>(&Ch[(size_t)row * half + col]) = o;
                    } else {
                        __half2 o = __floats2half2_rn(v0, v1);
                        *reinterpret_cast<__half2*>(&C2h[(size_t)row * half + (col - half)]) = o;
                    }
                }
            }
        }
    }
}

__global__ __launch_bounds__(256, 2)
void gemm12_kernel()
{
    const int bx = blockIdx.x;
    const int row0 = blockIdx.y * 128;
    if (bx < 3) {
        gemm_core(g_xqh, g_wqt, nullptr, g_q, nullptr, nullptr,
                  INNER, DIM, 1, row0, bx * 128);
    } else {
        gemm_core(g_xkvh, g_wkvt, nullptr, g_k, g_v, nullptr,
                  2 * INNER, DIM, 2, row0, (bx - 3) * 128);
    }
}

__global__ __launch_bounds__(256, 2)
void gemm5_kernel(const float* __restrict__ bias, float* __restrict__ out)
{
    gemm_core(g_attn, g_woutt, out, nullptr, nullptr, bias,
              INNER, DIM, 0, blockIdx.y * 128, blockIdx.x * 128);
}

// ---------------------------------------------------------------------------
// kv via fp16 mma + trans ldmatrix.
// kv[d][m] = sum_n k[n][d]*v[n][m].  M=d, N=m, K=n (k16 steps).
// k, v stored NATURALLY [n][*] as fp16 (raw uint2 copies); A = k^T and
// B = v^T gathered with ldmatrix.x4.trans. Pitch 72 halves -> conflict-free.
// Numerically identical to the tf32 path (fp16 -> fp32 exact).
// ---------------------------------------------------------------------------
#define CHUNK 256
#define KVH 72   // pitch in halves (144 B rows)
__global__ __launch_bounds__(256)
void kv_mma_kernel()
{
    __shared__ __half Kn[32 * KVH];   // k [n][d] fp16
    __shared__ __half Vs[32 * KVH];   // v [n][m] fp16
    __shared__ float red[16][64];

    const int bh = blockIdx.x;
    const int b = bh / HEADS, h = bh % HEADS;
    const int n0 = blockIdx.y * CHUNK;

    const int tid  = threadIdx.x;
    const int wid  = tid >> 5;
    const int lane = tid & 31;
    const int wm   = (wid & 1) * 32;    // d offset
    const int wn   = (wid >> 1) * 16;   // m offset
    const int lr = lane >> 2;
    const int lc = lane & 3;
    const int jj = lane >> 3;
    const int rr = lane & 7;

    const uint32_t sbK = smem_u32(Kn);
    const uint32_t sbV = smem_u32(Vs);

    // trans-ldmatrix byte offsets (per k16 step add 16 rows * KVH * 2 bytes)
    // A slot j: &Kn[(8*(j>>1)+rr)*KVH + wm + mt*16 + 8*(j&1)]
    uint32_t aoffT[2];
    #pragma unroll
    for (int mt = 0; mt < 2; mt++)
        aoffT[mt] = (uint32_t)(((8 * (jj >> 1) + rr) * KVH
                                + wm + mt * 16 + 8 * (jj & 1)) * 2);
    // B slot j: &Vs[(8*(j&1)+rr)*KVH + wn + 8*(j>>1)]
    const uint32_t boffT = (uint32_t)(((8 * (jj & 1) + rr) * KVH
                                       + wn + 8 * (jj >> 1)) * 2);
    const uint32_t stepB = (uint32_t)(16 * KVH * 2);   // +16 n rows

    const __half* kbase = g_k + ((size_t)(b * NSEQ + n0)) * INNER + h * DHEAD;
    const __half* vbase = g_v + ((size_t)(b * NSEQ + n0)) * INNER + h * DHEAD;

    float acc[2][2][4];
    #pragma unroll
    for (int i = 0; i < 2; i++)
        #pragma unroll
        for (int j = 0; j < 2; j++)
            #pragma unroll
            for (int r = 0; r < 4; r++) acc[i][j][r] = 0.f;
    float sk[4] = {0.f, 0.f, 0.f, 0.f};

    for (int sub = 0; sub < CHUNK / 32; sub++) {
        const int nn = sub * 32;
        #pragma unroll
        for (int it = 0; it < 2; it++) {
            int idx = tid + it * 256;
            int n = idx >> 4, c4 = (idx & 15) * 4;
            uint2 kraw = *reinterpret_cast<const uint2*>(
                &kbase[(size_t)(nn + n) * INNER + c4]);
            *reinterpret_cast<uint2*>(&Kn[n * KVH + c4]) = kraw;
            float2 f01 = __half22float2(*reinterpret_cast<__half2*>(&kraw.x));
            float2 f23 = __half22float2(*reinterpret_cast<__half2*>(&kraw.y));
            sk[0] += f01.x; sk[1] += f01.y; sk[2] += f23.x; sk[3] += f23.y;
            uint2 vraw = *reinterpret_cast<const uint2*>(
                &vbase[(size_t)(nn + n) * INNER + c4]);
            *reinterpret_cast<uint2*>(&Vs[n * KVH + c4]) = vraw;
        }
        __syncthreads();

        #pragma unroll
        for (int s = 0; s < 2; s++) {       // two k16 (n) steps per 32-n tile
            uint32_t af[2][4];
            #pragma unroll
            for (int mt = 0; mt < 2; mt++)
                ldm_x4_t(af[mt], sbK + aoffT[mt] + (uint32_t)s * stepB);
            uint32_t t[4];
            ldm_x4_t(t, sbV + boffT + (uint32_t)s * stepB);
            // slots: t0=(m,k0) t1=(m,k8) t2=(m+8,k0) t3=(m+8,k8)
            uint32_t bf[2][2];
            bf[0][0] = t[0]; bf[0][1] = t[1];
            bf[1][0] = t[2]; bf[1][1] = t[3];
            #pragma unroll
            for (int mt = 0; mt < 2; mt++)
                #pragma unroll
                for (int nt = 0; nt < 2; nt++)
                    mma_f16(acc[mt][nt], af[mt][0], af[mt][1], af[mt][2],
                            af[mt][3], bf[nt][0], bf[nt][1]);
        }
        __syncthreads();
    }

    // ---- ksum reduction ----
    {
        const int c4 = (tid & 15) * 4;
        const int grp = tid >> 4;
        #pragma unroll
        for (int j = 0; j < 4; j++) red[grp][c4 + j] = sk[j];
        __syncthreads();
        if (tid < 64) {
            float s = 0.f;
            #pragma unroll
            for (int r = 0; r < 16; r++) s += red[r][tid];
            atomicAdd(&g_ksum[bh * DHEAD + tid], s);
        }
    }

    // ---- kv accumulation ----
    float* kvp = g_kv + (size_t)bh * DHEAD * DHEAD;
    #pragma unroll
    for (int mt = 0; mt < 2; mt++) {
        #pragma unroll
        for (int nt = 0; nt < 2; nt++) {
            const int col = wn + nt * 8 + lc * 2;
            #pragma unroll
            for (int hh = 0; hh < 2; hh++) {
                const int row = wm + mt * 16 + lr + hh * 8;
                atomicAdd(&kvp[row * DHEAD + col],     acc[mt][nt][hh * 2 + 0]);
                atomicAdd(&kvp[row * DHEAD + col + 1], acc[mt][nt][hh * 2 + 1]);
            }
        }
    }
}

// ---------------------------------------------------------------------------
// attn via fp16 mma + ldmatrix: attn[n][m] = (q[n,:] @ kv[:,m]) * z[n].
// A = q [n][d] fp16 (non-trans). kv stored [d][m] fp16 -> B = kv^T via trans.
// kv rounded fp32->fp16: same 10-bit significand as the previous tf32 path.
// ---------------------------------------------------------------------------
#define AQH 72   // halves pitch
__global__ __launch_bounds__(256, 6)
void attn_mma_kernel()
{
    __shared__ __half qs [64 * AQH];   // q [n][d]
    __shared__ __half kvs[64 * AQH];   // kv [d][m]
    __shared__ float ks[64];
    __shared__ float zr[64];

    const int bh = blockIdx.x;
    const int b = bh / HEADS, h = bh % HEADS;
    const int n0 = blockIdx.y * 64;

    const int tid  = threadIdx.x;
    const int wid  = tid >> 5;
    const int lane = tid & 31;
    const int wm   = (wid & 1) * 32;    // n rows
    const int wn   = (wid >> 1) * 16;   // m cols
    const int lr = lane >> 2;
    const int lc = lane & 3;
    const int jj = lane >> 3;
    const int rr = lane & 7;

    const uint32_t sbQ = smem_u32(qs);
    const uint32_t sbKV = smem_u32(kvs);

    // A non-trans: slot j = (row + 8*(j&1), k + 8*(j>>1))
    uint32_t aoffN[2];
    #pragma unroll
    for (int mt = 0; mt < 2; mt++)
        aoffN[mt] = (uint32_t)(((wm + mt * 16 + (jj & 1) * 8 + rr) * AQH
                                + (jj >> 1) * 8) * 2);
    // B trans on kvs [d][m]: slot j = rows d: 8*(j&1)+rr, col m: wn+8*(j>>1)
    const uint32_t boffT = (uint32_t)(((8 * (jj & 1) + rr) * AQH
                                       + wn + 8 * (jj >> 1)) * 2);
    const uint32_t stepK = (uint32_t)(16 * 2);        // A: +16 halves in k
    const uint32_t stepD = (uint32_t)(16 * AQH * 2);  // B: +16 d rows

    // q tile 64x64 fp16 (raw copy)
    const __half* qptr = g_q + ((size_t)(b * NSEQ + n0)) * INNER + h * DHEAD;
    #pragma unroll
    for (int j = 0; j < 4; j++) {
        int idx = tid + 256 * j;
        int r = idx >> 4, c4 = (idx & 15) * 4;
        uint2 raw = *reinterpret_cast<const uint2*>(&qptr[(size_t)r * INNER + c4]);
        *reinterpret_cast<uint2*>(&qs[r * AQH + c4]) = raw;
    }
    // kv tile 64x64: fp32 -> fp16, stored [d][m]
    #pragma unroll
    for (int j = 0; j < 4; j++) {
        int idx = tid + 256 * j;
        int d = idx >> 4, m4 = (idx & 15) * 4;
        float4 v = *reinterpret_cast<const float4*>(&g_kv[(size_t)bh * 4096 + d * 64 + m4]);
        __half2 h0 = __floats2half2_rn(v.x, v.y);
        __half2 h1 = __floats2half2_rn(v.z, v.w);
        uint2 o;
        o.x = *reinterpret_cast<uint32_t*>(&h0);
        o.y = *reinterpret_cast<uint32_t*>(&h1);
        *reinterpret_cast<uint2*>(&kvs[d * AQH + m4]) = o;
    }
    if (tid < 64) ks[tid] = g_ksum[bh * 64 + tid];
    __syncthreads();

    if (tid < 64) {
        float s = 0.f;
        #pragma unroll
        for (int dd = 0; dd < 64; dd++)
            s += __half2float(qs[tid * AQH + dd]) * ks[dd];
        zr[tid] = 1.f / (s + 1e-6f);
    }
    __syncthreads();

    float acc[2][2][4];
    #pragma unroll
    for (int i = 0; i < 2; i++)
        #pragma unroll
        for (int j = 0; j < 2; j++)
            #pragma unroll
            for (int r = 0; r < 4; r++) acc[i][j][r] = 0.f;

    #pragma unroll
    for (int s = 0; s < 4; s++) {           // four k16 steps over d=64
        uint32_t af[2][4];
        #pragma unroll
        for (int mt = 0; mt < 2; mt++)
            ldm_x4(af[mt], sbQ + aoffN[mt] + (uint32_t)s * stepK);
        uint32_t t[4];
        ldm_x4_t(t, sbKV + boffT + (uint32_t)s * stepD);
        uint32_t bf[2][2];
        bf[0][0] = t[0]; bf[0][1] = t[1];
        bf[1][0] = t[2]; bf[1][1] = t[3];
        #pragma unroll
        for (int mt = 0; mt < 2; mt++)
            #pragma unroll
            for (int nt = 0; nt < 2; nt++)
                mma_f16(acc[mt][nt], af[mt][0], af[mt][1], af[mt][2],
                        af[mt][3], bf[nt][0], bf[nt][1]);
    }

    #pragma unroll
    for (int mt = 0; mt < 2; mt++) {
        #pragma unroll
        for (int nt = 0; nt < 2; nt++) {
            const int col = wn + nt * 8 + lc * 2;
            #pragma unroll
            for (int hh = 0; hh < 2; hh++) {
                const int row = wm + mt * 16 + lr + hh * 8;
                const float z = zr[row];
                __half2 o = __floats2half2_rn(acc[mt][nt][hh * 2 + 0] * z,
                                              acc[mt][nt][hh * 2 + 1] * z);
                *reinterpret_cast<__half2*>(
                    &g_attn[((size_t)(b * NSEQ + n0 + row)) * INNER + h * DHEAD + col]) = o;
            }
        }
    }
}

// ---------------------------------------------------------------------------
// Launch order: PREP, G12, KV, AT (profiled 4th slot), G5
// ---------------------------------------------------------------------------
extern "C" void kernel_launch(void* const* d_in, const int* in_sizes, int n_in,
                              void* d_out, int out_size)
{
    const float* x_q  = (const float*)d_in[0];
    const float* x_kv = (const float*)d_in[1];
    const float* Wq   = (const float*)d_in[2];
    const float* Wkv  = (const float*)d_in[3];
    const float* Wout = (const float*)d_in[4];
    const float* bout = (const float*)d_in[5];
    float* out = (float*)d_out;

    cudaFuncSetAttribute((const void*)gemm12_kernel, cudaFuncAttributeMaxDynamicSharedMemorySize, G_SMEM);
    cudaFuncSetAttribute((const void*)gemm5_kernel,  cudaFuncAttributeMaxDynamicSharedMemorySize, G_SMEM);

    dim3 blk(256);

    // 1) prep: x->fp16, weights->fp16^T, zero accumulators
    prep_kernel<<<2048, blk>>>(x_q, x_kv, Wq, Wkv, Wout);

    // 2) merged projections (fp16 mma + ldmatrix, BK=64)
    gemm12_kernel<<<dim3(9, ROWS/128), blk, G_SMEM>>>();

    // 3) kv = k^T v; ksum = sum_n k  (fp16 mma + trans ldmatrix)
    kv_mma_kernel<<<dim3(BATCH*HEADS, NSEQ/CHUNK), blk>>>();

    // 4) attn = (q @ kv) * z  (fp16 mma + ldmatrix)
    attn_mma_kernel<<<dim3(BATCH*HEADS, NSEQ/64), blk>>>();

    // 5) out = attn @ Wout + bout (fp32 out)
    gemm5_kernel<<<dim3(INNER/128, ROWS/128), blk, G_SMEM>>>(bout, out);
}